// round 14
// baseline (speedup 1.0000x reference)
#include <cuda_runtime.h>
#include <cuda_bf16.h>
#include <cstdint>
#include <math.h>

// ---------------- problem constants ----------------
#define B_    2
#define D96   96
#define H_    192
#define W_    192
#define HW_   (H_*W_)        // 36864
#define HEADS 2
#define C48   48
#define HL_   24
#define WL_   24
#define PL_   (HL_*WL_)      // 576
#define QC_   288            // 3*D
#define TPD_  48             // winograd F(4,3) tiles per spatial dim
#define NT_   4608           // 48*48*2 tiles

// weight-bank offsets (elements) in g_WBh/g_WBl
#define WB_QKV   0           // [L][288][96]  -> 2*27648
#define WB_EHY   55296       // [L][48][96]   -> 2*4608
#define WB_ELX   64512
#define WB_ELY   73728
#define WB_TOT   82944

// ---------------- scratch (static, no runtime alloc) ----------------
__device__ float g_feats  [(size_t)B_*QC_*HW_];
__device__ float g_qkvfull[(size_t)B_*QC_*HW_];
__device__ float g_weff   [D96*D96*9];
__device__ float g_beff   [D96];
__device__ float g_dw     [(size_t)B_*QC_*PL_];
__device__ float g_attn   [B_*HEADS*C48*C48];
__device__ float g_acomb  [B_*HEADS*C48*C48];
__device__ float g_low1   [(size_t)B_*D96*PL_];
__device__ float g_low2   [(size_t)B_*D96*PL_];
__device__ float g_xk     [(size_t)B_*C48*HW_];
__device__ float g_yq     [(size_t)B_*C48*HW_];
__device__ float g_yq2    [(size_t)B_*C48*HW_];
__device__ float g_bnx    [2*C48];
__device__ float g_bny    [2*C48];
__device__ float g_bny2   [2*C48];
__device__ float g_bnpartA[C48][16][2];
__device__ float g_bnpartB[C48][16][2];
__device__ float g_bnpartC[C48][16][2];
// winograd F(4x4,3x3) scratch — split bf16 operands, fp32 M
__device__ __nv_bfloat16 g_Uh [(size_t)36*D96*D96];   // MKW weights
__device__ __nv_bfloat16 g_Ul [(size_t)36*D96*D96];
__device__ __nv_bfloat16 g_UCh[(size_t)36*D96*QC_];   // CAB weights (hoisted)
__device__ __nv_bfloat16 g_UCl[(size_t)36*D96*QC_];
__device__ __nv_bfloat16 g_Vh [(size_t)36*QC_*NT_];
__device__ __nv_bfloat16 g_Vl [(size_t)36*QC_*NT_];
__device__ float         g_M  [(size_t)36*D96*NT_];
// split-bf16 activations / weights for TC 1x1 convs
__device__ __nv_bfloat16 g_Xh [(size_t)B_*D96*HW_];
__device__ __nv_bfloat16 g_Xl [(size_t)B_*D96*HW_];
__device__ __nv_bfloat16 g_HFh[(size_t)B_*D96*HW_];
__device__ __nv_bfloat16 g_HFl[(size_t)B_*D96*HW_];
__device__ __nv_bfloat16 g_LFh[(size_t)B_*D96*HW_];
__device__ __nv_bfloat16 g_LFl[(size_t)B_*D96*HW_];
__device__ __nv_bfloat16 g_WBh[WB_TOT];
__device__ __nv_bfloat16 g_WBl[WB_TOT];

__device__ __forceinline__ void split_bf16(float x, __nv_bfloat16& h, __nv_bfloat16& l){
    h = __float2bfloat16_rn(x);
    l = __float2bfloat16_rn(x - __bfloat162float(h));
}

// ---------------- streams/events: created at load time (outside capture) ----------
struct StreamInit {
    cudaStream_t s2, s3;
    cudaEvent_t eS, e1, e2, e4, eW, eC, eB;
    StreamInit(){
        cudaStreamCreateWithFlags(&s2, cudaStreamNonBlocking);
        cudaStreamCreateWithFlags(&s3, cudaStreamNonBlocking);
        cudaEventCreateWithFlags(&eS, cudaEventDisableTiming);
        cudaEventCreateWithFlags(&e1, cudaEventDisableTiming);
        cudaEventCreateWithFlags(&e2, cudaEventDisableTiming);
        cudaEventCreateWithFlags(&e4, cudaEventDisableTiming);
        cudaEventCreateWithFlags(&eW, cudaEventDisableTiming);
        cudaEventCreateWithFlags(&eC, cudaEventDisableTiming);
        cudaEventCreateWithFlags(&eB, cudaEventDisableTiming);
    }
};
static StreamInit g_si;

// ---------------- MKW effective weight (+bias folded in) ----------------
__global__ void build_weight(const float* __restrict__ w,  const float* __restrict__ wc,
                             const float* __restrict__ wh, const float* __restrict__ wv,
                             const float* __restrict__ wa, const float* __restrict__ s4,
                             float* __restrict__ weff,
                             const float* __restrict__ b,  const float* __restrict__ bc,
                             const float* __restrict__ bh, const float* __restrict__ bv,
                             const float* __restrict__ ba, float* __restrict__ beff) {
    int idx = blockIdx.x * blockDim.x + threadIdx.x;   // oc*96+ic
    const float s0=s4[0], s1=s4[1], s2=s4[2], s3=s4[3];
    if (blockIdx.x == 0 && threadIdx.x < D96){
        int c = threadIdx.x;
        beff[c] = b[c] + s0*bc[c] + s1*bh[c] + s2*bv[c] + s3*ba[c];
    }
    if (idx >= D96*D96) return;
    float wcl[9], wal[9];
    float csum = 0.f;
    #pragma unroll
    for (int t=0;t<9;t++){ wcl[t]=wc[(size_t)idx*9+t]; csum+=wcl[t]; }
    #pragma unroll
    for (int t=0;t<9;t++){ wal[t]=wa[(size_t)idx*9+t]; }
    const int perm[9] = {3,0,1,6,4,2,7,8,5};
    float wh0=wh[(size_t)idx*3+0], wh1=wh[(size_t)idx*3+1], wh2=wh[(size_t)idx*3+2];
    float wv0=wv[(size_t)idx*3+0], wv1=wv[(size_t)idx*3+1], wv2=wv[(size_t)idx*3+2];
    #pragma unroll
    for (int t=0;t<9;t++){
        float wcd = wcl[t] - (t==4 ? csum : 0.f);
        float whd = 0.f;
        if (t==0) whd =  wh0; else if (t==3) whd =  wh1; else if (t==6) whd =  wh2;
        else if (t==2) whd = -wh0; else if (t==5) whd = -wh1; else if (t==8) whd = -wh2;
        float wvd = 0.f;
        if (t<3) wvd = (t==0?wv0:(t==1?wv1:wv2));
        else if (t>=6) wvd = -(t==6?wv0:(t==7?wv1:wv2));
        float wad = wal[t] - wal[perm[t]];
        weff[(size_t)idx*9+t] = w[(size_t)idx*9+t] + s0*wcd + s1*whd + s2*wvd + s3*wad;
    }
}

// ---------------- hoisted: convert ALL 1x1 weights to split bf16 -------------------
__global__ void convert_all_w(const float* __restrict__ qkv, const float* __restrict__ ehy,
                              const float* __restrict__ elx, const float* __restrict__ ely,
                              __nv_bfloat16* __restrict__ Wh, __nv_bfloat16* __restrict__ Wl){
    int idx = blockIdx.x*blockDim.x + threadIdx.x;
    if (idx >= WB_TOT) return;
    float v;
    if (idx < WB_EHY)      v = qkv[idx];
    else if (idx < WB_ELX) v = ehy[idx - WB_EHY];
    else if (idx < WB_ELY) v = elx[idx - WB_ELX];
    else                   v = ely[idx - WB_ELY];
    __nv_bfloat16 h,l; split_bf16(v, h, l);
    Wh[idx] = h; Wl[idx] = l;
}

// ---------------- Winograd F(4x4,3x3): weight transform U = G g G^T (split bf16) ----
__global__ void wino_wtrans(const float* __restrict__ w, int OC, int IC,
                            __nv_bfloat16* __restrict__ Uh, __nv_bfloat16* __restrict__ Ul) {
    int idx = blockIdx.x*blockDim.x + threadIdx.x;   // oc*IC + ic
    if (idx >= OC*IC) return;
    float g[9];
    #pragma unroll
    for (int t=0;t<9;t++) g[t] = w[(size_t)idx*9 + t];
    const float i6 = 1.f/6.f, i12 = 1.f/12.f, i24 = 1.f/24.f;
    float Gg[6][3];
    #pragma unroll
    for (int c=0;c<3;c++){
        float g0 = g[c], g1 = g[3+c], g2 = g[6+c];
        Gg[0][c] = 0.25f*g0;
        Gg[1][c] = -i6*(g0 + g1 + g2);
        Gg[2][c] =  i6*(-g0 + g1 - g2);
        Gg[3][c] =  i24*g0 + i12*g1 + i6*g2;
        Gg[4][c] =  i24*g0 - i12*g1 + i6*g2;
        Gg[5][c] =  g2;
    }
    long OI = (long)OC*IC;
    #pragma unroll
    for (int r=0;r<6;r++){
        float a = Gg[r][0], b = Gg[r][1], c2 = Gg[r][2];
        float u[6];
        u[0] = 0.25f*a;
        u[1] = -i6*(a + b + c2);
        u[2] =  i6*(-a + b - c2);
        u[3] =  i24*a + i12*b + i6*c2;
        u[4] =  i24*a - i12*b + i6*c2;
        u[5] =  c2;
        #pragma unroll
        for (int q=0;q<6;q++){
            __nv_bfloat16 h,l; split_bf16(u[q], h, l);
            Uh[(long)(r*6+q)*OI + idx] = h;
            Ul[(long)(r*6+q)*OI + idx] = l;
        }
    }
}

// ---------------- Winograd F(4,3) input transform V = B^T d B (split bf16) ----------
__global__ void wino_itrans(const float* __restrict__ in, long inB, int IC,
                            __nv_bfloat16* __restrict__ Vh, __nv_bfloat16* __restrict__ Vl) {
    int n  = blockIdx.x*blockDim.x + threadIdx.x;   // 0..NT_-1
    int ic = blockIdx.y;
    int b   = n / (NT_/B_);
    int loc = n % (NT_/B_);
    int ty = loc / TPD_, tx = loc % TPD_;
    const float* src = in + (long)b*inB + (long)ic*HW_;
    int h0 = 4*ty - 1, w0 = 4*tx - 1;
    float d[6][6];
    #pragma unroll
    for (int r=0;r<6;r++){
        int hh = h0 + r;
        bool hok = (hh >= 0 && hh < H_);
        #pragma unroll
        for (int c=0;c<6;c++){
            int ww = w0 + c;
            d[r][c] = (hok && ww >= 0 && ww < W_) ? src[hh*W_ + ww] : 0.f;
        }
    }
    float t[6][6];
    #pragma unroll
    for (int c=0;c<6;c++){
        float d0=d[0][c], d1=d[1][c], d2=d[2][c], d3=d[3][c], d4=d[4][c], d5=d[5][c];
        t[0][c] =  4.f*d0 - 5.f*d2 + d4;
        t[1][c] = -4.f*d1 - 4.f*d2 + d3 + d4;
        t[2][c] =  4.f*d1 - 4.f*d2 - d3 + d4;
        t[3][c] = -2.f*d1 -      d2 + 2.f*d3 + d4;
        t[4][c] =  2.f*d1 -      d2 - 2.f*d3 + d4;
        t[5][c] =  4.f*d1 - 5.f*d3 + d5;
    }
    long stride = (long)IC*NT_;
    long base = (long)ic*NT_ + n;
    #pragma unroll
    for (int r=0;r<6;r++){
        float t0=t[r][0], t1=t[r][1], t2=t[r][2], t3=t[r][3], t4=t[r][4], t5=t[r][5];
        float v[6];
        v[0] =  4.f*t0 - 5.f*t2 + t4;
        v[1] = -4.f*t1 - 4.f*t2 + t3 + t4;
        v[2] =  4.f*t1 - 4.f*t2 - t3 + t4;
        v[3] = -2.f*t1 -      t2 + 2.f*t3 + t4;
        v[4] =  2.f*t1 -      t2 - 2.f*t3 + t4;
        v[5] =  4.f*t1 - 5.f*t3 + t5;
        #pragma unroll
        for (int q=0;q<6;q++){
            __nv_bfloat16 h,l; split_bf16(v[q], h, l);
            Vh[(long)(r*6+q)*stride + base] = h;
            Vl[(long)(r*6+q)*stride + base] = l;
        }
    }
}

// ---------------- split-bf16 TC GEMM, fused phases + double buffer -----------------
__global__ __launch_bounds__(256)
void wino_gemm(const __nv_bfloat16* __restrict__ Uh, const __nv_bfloat16* __restrict__ Ul,
               const __nv_bfloat16* __restrict__ Vh, const __nv_bfloat16* __restrict__ Vl,
               float* __restrict__ Mo, int IC, int NT) {
    const int p    = blockIdx.z;
    const int nBlk = blockIdx.x * 128;
    const int tid  = threadIdx.x;
    const int warp = tid >> 5, lane = tid & 31;
    const int mOff = (warp >> 2) * 48;
    const int nOff = (warp & 3) * 32;
    const int lq   = lane >> 2;
    const int lr   = lane & 3;

    __shared__ uint32_t Ah[2][96*9], Al[2][96*9];
    __shared__ uint32_t Bh[2][128*9], Bl[2][128*9];

    float acc[3][4][4];
    #pragma unroll
    for (int mt=0;mt<3;mt++)
        #pragma unroll
        for (int nt=0;nt<4;nt++)
            #pragma unroll
            for (int q=0;q<4;q++) acc[mt][nt][q]=0.f;

    const long Uplane = (long)p*96*IC;
    const long Vplane = (long)p*IC*NT;
    const int nIter = IC/16;

    #pragma unroll
    for (int s=0;s<3;s++){
        int e = tid + s*256;
        int m = e >> 3, kp = e & 7;
        long off = Uplane + (long)m*IC + kp*2;
        Ah[0][m*9+kp] = *reinterpret_cast<const uint32_t*>(Uh + off);
        Al[0][m*9+kp] = *reinterpret_cast<const uint32_t*>(Ul + off);
    }
    #pragma unroll
    for (int s=0;s<2;s++){
        int e = tid + s*256;
        int kp = e >> 6, j = e & 63;
        long off = Vplane + (long)(2*kp)*NT + nBlk + 2*j;
        uint32_t h0 = *reinterpret_cast<const uint32_t*>(Vh + off);
        uint32_t h1 = *reinterpret_cast<const uint32_t*>(Vh + off + NT);
        Bh[0][(2*j  )*9 + kp] = __byte_perm(h0, h1, 0x5410);
        Bh[0][(2*j+1)*9 + kp] = __byte_perm(h0, h1, 0x7632);
        uint32_t l0 = *reinterpret_cast<const uint32_t*>(Vl + off);
        uint32_t l1 = *reinterpret_cast<const uint32_t*>(Vl + off + NT);
        Bl[0][(2*j  )*9 + kp] = __byte_perm(l0, l1, 0x5410);
        Bl[0][(2*j+1)*9 + kp] = __byte_perm(l0, l1, 0x7632);
    }
    __syncthreads();

    for (int it=0; it<nIter; it++){
        const int cur = it & 1, nxt = cur ^ 1;
        const bool more = (it+1 < nIter);

        uint32_t sa[6], sb[8];
        if (more){
            int icb = (it+1)*16;
            #pragma unroll
            for (int s=0;s<3;s++){
                int e = tid + s*256;
                int m = e >> 3, kp = e & 7;
                long off = Uplane + (long)m*IC + icb + kp*2;
                sa[2*s  ] = *reinterpret_cast<const uint32_t*>(Uh + off);
                sa[2*s+1] = *reinterpret_cast<const uint32_t*>(Ul + off);
            }
            #pragma unroll
            for (int s=0;s<2;s++){
                int e = tid + s*256;
                int kp = e >> 6, j = e & 63;
                long off = Vplane + (long)(icb + 2*kp)*NT + nBlk + 2*j;
                sb[4*s  ] = *reinterpret_cast<const uint32_t*>(Vh + off);
                sb[4*s+1] = *reinterpret_cast<const uint32_t*>(Vh + off + NT);
                sb[4*s+2] = *reinterpret_cast<const uint32_t*>(Vl + off);
                sb[4*s+3] = *reinterpret_cast<const uint32_t*>(Vl + off + NT);
            }
        }

        #pragma unroll
        for (int ph=0; ph<3; ph++){
            const uint32_t* As = (ph < 2) ? Ah[cur] : Al[cur];
            const uint32_t* Bs = (ph == 1) ? Bl[cur] : Bh[cur];
            uint32_t a[3][4], b[4][2];
            #pragma unroll
            for (int mt=0;mt<3;mt++){
                int m0 = mOff + mt*16;
                a[mt][0] = As[(m0     + lq)*9 +     lr];
                a[mt][1] = As[(m0 + 8 + lq)*9 +     lr];
                a[mt][2] = As[(m0     + lq)*9 + 4 + lr];
                a[mt][3] = As[(m0 + 8 + lq)*9 + 4 + lr];
            }
            #pragma unroll
            for (int nt=0;nt<4;nt++){
                int n0 = nOff + nt*8;
                b[nt][0] = Bs[(n0 + lq)*9 +     lr];
                b[nt][1] = Bs[(n0 + lq)*9 + 4 + lr];
            }
            #pragma unroll
            for (int mt=0;mt<3;mt++)
                #pragma unroll
                for (int nt=0;nt<4;nt++){
                    asm volatile(
                        "mma.sync.aligned.m16n8k16.row.col.f32.bf16.bf16.f32 "
                        "{%0,%1,%2,%3}, {%4,%5,%6,%7}, {%8,%9}, {%0,%1,%2,%3};"
                        : "+f"(acc[mt][nt][0]), "+f"(acc[mt][nt][1]),
                          "+f"(acc[mt][nt][2]), "+f"(acc[mt][nt][3])
                        : "r"(a[mt][0]), "r"(a[mt][1]), "r"(a[mt][2]), "r"(a[mt][3]),
                          "r"(b[nt][0]), "r"(b[nt][1]));
                }
        }

        if (more){
            #pragma unroll
            for (int s=0;s<3;s++){
                int e = tid + s*256;
                int m = e >> 3, kp = e & 7;
                Ah[nxt][m*9+kp] = sa[2*s];
                Al[nxt][m*9+kp] = sa[2*s+1];
            }
            #pragma unroll
            for (int s=0;s<2;s++){
                int e = tid + s*256;
                int kp = e >> 6, j = e & 63;
                Bh[nxt][(2*j  )*9 + kp] = __byte_perm(sb[4*s], sb[4*s+1], 0x5410);
                Bh[nxt][(2*j+1)*9 + kp] = __byte_perm(sb[4*s], sb[4*s+1], 0x7632);
                Bl[nxt][(2*j  )*9 + kp] = __byte_perm(sb[4*s+2], sb[4*s+3], 0x5410);
                Bl[nxt][(2*j+1)*9 + kp] = __byte_perm(sb[4*s+2], sb[4*s+3], 0x7632);
            }
        }
        __syncthreads();
    }

    long Mbase = (long)p*96*NT;
    #pragma unroll
    for (int mt=0;mt<3;mt++){
        int r0 = mOff + mt*16 + lq;
        #pragma unroll
        for (int nt=0;nt<4;nt++){
            int c = nBlk + nOff + nt*8 + 2*lr;
            *reinterpret_cast<float2*>(&Mo[Mbase + (long)r0*NT + c]) =
                make_float2(acc[mt][nt][0], acc[mt][nt][1]);
            *reinterpret_cast<float2*>(&Mo[Mbase + (long)(r0+8)*NT + c]) =
                make_float2(acc[mt][nt][2], acc[mt][nt][3]);
        }
    }
}

// ---------------- split-bf16 TC GEMM for 1x1 convs (double buffered) ----------------
__global__ __launch_bounds__(256)
void gemm1x1_tc(const __nv_bfloat16* __restrict__ Wh, const __nv_bfloat16* __restrict__ Wl,
                const __nv_bfloat16* __restrict__ Xh, const __nv_bfloat16* __restrict__ Xl,
                const float* __restrict__ bias, float* __restrict__ out,
                int IC, int OC, int npix, long outBz) {
    const int z    = blockIdx.z;
    const int nBlk = blockIdx.x * 128;
    const int mBlk = blockIdx.y * 96;
    const int tid  = threadIdx.x;
    const int warp = tid >> 5, lane = tid & 31;
    const int mOff = (warp >> 2) * 48;
    const int nOff = (warp & 3) * 32;
    const int lq   = lane >> 2;
    const int lr   = lane & 3;

    __shared__ uint32_t Ah[2][96*9], Al[2][96*9];
    __shared__ uint32_t Bh[2][128*9], Bl[2][128*9];

    float acc[3][4][4];
    #pragma unroll
    for (int mt=0;mt<3;mt++)
        #pragma unroll
        for (int nt=0;nt<4;nt++)
            #pragma unroll
            for (int q=0;q<4;q++) acc[mt][nt][q]=0.f;

    const long Xplane = (long)z*IC*npix;
    const int nIter = IC/16;

    #pragma unroll
    for (int s=0;s<3;s++){
        int e = tid + s*256;
        int m = e >> 3, kp = e & 7;
        int gm = mBlk + m;
        uint32_t vh = 0, vl = 0;
        if (gm < OC){
            long off = (long)gm*IC + kp*2;
            vh = *reinterpret_cast<const uint32_t*>(Wh + off);
            vl = *reinterpret_cast<const uint32_t*>(Wl + off);
        }
        Ah[0][m*9+kp] = vh; Al[0][m*9+kp] = vl;
    }
    #pragma unroll
    for (int s=0;s<2;s++){
        int e = tid + s*256;
        int kp = e >> 6, j = e & 63;
        long off = Xplane + (long)(2*kp)*npix + nBlk + 2*j;
        uint32_t h0 = *reinterpret_cast<const uint32_t*>(Xh + off);
        uint32_t h1 = *reinterpret_cast<const uint32_t*>(Xh + off + npix);
        Bh[0][(2*j  )*9 + kp] = __byte_perm(h0, h1, 0x5410);
        Bh[0][(2*j+1)*9 + kp] = __byte_perm(h0, h1, 0x7632);
        uint32_t l0 = *reinterpret_cast<const uint32_t*>(Xl + off);
        uint32_t l1 = *reinterpret_cast<const uint32_t*>(Xl + off + npix);
        Bl[0][(2*j  )*9 + kp] = __byte_perm(l0, l1, 0x5410);
        Bl[0][(2*j+1)*9 + kp] = __byte_perm(l0, l1, 0x7632);
    }
    __syncthreads();

    for (int it=0; it<nIter; it++){
        const int cur = it & 1, nxt = cur ^ 1;
        const bool more = (it+1 < nIter);

        uint32_t sa[6], sb[8];
        if (more){
            int icb = (it+1)*16;
            #pragma unroll
            for (int s=0;s<3;s++){
                int e = tid + s*256;
                int m = e >> 3, kp = e & 7;
                int gm = mBlk + m;
                uint32_t vh = 0, vl = 0;
                if (gm < OC){
                    long off = (long)gm*IC + icb + kp*2;
                    vh = *reinterpret_cast<const uint32_t*>(Wh + off);
                    vl = *reinterpret_cast<const uint32_t*>(Wl + off);
                }
                sa[2*s] = vh; sa[2*s+1] = vl;
            }
            #pragma unroll
            for (int s=0;s<2;s++){
                int e = tid + s*256;
                int kp = e >> 6, j = e & 63;
                long off = Xplane + (long)(icb + 2*kp)*npix + nBlk + 2*j;
                sb[4*s  ] = *reinterpret_cast<const uint32_t*>(Xh + off);
                sb[4*s+1] = *reinterpret_cast<const uint32_t*>(Xh + off + npix);
                sb[4*s+2] = *reinterpret_cast<const uint32_t*>(Xl + off);
                sb[4*s+3] = *reinterpret_cast<const uint32_t*>(Xl + off + npix);
            }
        }

        #pragma unroll
        for (int ph=0; ph<3; ph++){
            const uint32_t* As = (ph < 2) ? Ah[cur] : Al[cur];
            const uint32_t* Bs = (ph == 1) ? Bl[cur] : Bh[cur];
            uint32_t a[3][4], b[4][2];
            #pragma unroll
            for (int mt=0;mt<3;mt++){
                int m0 = mOff + mt*16;
                a[mt][0] = As[(m0     + lq)*9 +     lr];
                a[mt][1] = As[(m0 + 8 + lq)*9 +     lr];
                a[mt][2] = As[(m0     + lq)*9 + 4 + lr];
                a[mt][3] = As[(m0 + 8 + lq)*9 + 4 + lr];
            }
            #pragma unroll
            for (int nt=0;nt<4;nt++){
                int n0 = nOff + nt*8;
                b[nt][0] = Bs[(n0 + lq)*9 +     lr];
                b[nt][1] = Bs[(n0 + lq)*9 + 4 + lr];
            }
            #pragma unroll
            for (int mt=0;mt<3;mt++)
                #pragma unroll
                for (int nt=0;nt<4;nt++){
                    asm volatile(
                        "mma.sync.aligned.m16n8k16.row.col.f32.bf16.bf16.f32 "
                        "{%0,%1,%2,%3}, {%4,%5,%6,%7}, {%8,%9}, {%0,%1,%2,%3};"
                        : "+f"(acc[mt][nt][0]), "+f"(acc[mt][nt][1]),
                          "+f"(acc[mt][nt][2]), "+f"(acc[mt][nt][3])
                        : "r"(a[mt][0]), "r"(a[mt][1]), "r"(a[mt][2]), "r"(a[mt][3]),
                          "r"(b[nt][0]), "r"(b[nt][1]));
                }
        }

        if (more){
            #pragma unroll
            for (int s=0;s<3;s++){
                int e = tid + s*256;
                int m = e >> 3, kp = e & 7;
                Ah[nxt][m*9+kp] = sa[2*s];
                Al[nxt][m*9+kp] = sa[2*s+1];
            }
            #pragma unroll
            for (int s=0;s<2;s++){
                int e = tid + s*256;
                int kp = e >> 6, j = e & 63;
                Bh[nxt][(2*j  )*9 + kp] = __byte_perm(sb[4*s], sb[4*s+1], 0x5410);
                Bh[nxt][(2*j+1)*9 + kp] = __byte_perm(sb[4*s], sb[4*s+1], 0x7632);
                Bl[nxt][(2*j  )*9 + kp] = __byte_perm(sb[4*s+2], sb[4*s+3], 0x5410);
                Bl[nxt][(2*j+1)*9 + kp] = __byte_perm(sb[4*s+2], sb[4*s+3], 0x7632);
            }
        }
        __syncthreads();
    }

    #pragma unroll
    for (int mt=0;mt<3;mt++){
        int r0 = mOff + mt*16 + lq;
        int g0 = mBlk + r0, g1 = g0 + 8;
        float bv0 = (bias && g0 < OC) ? bias[g0] : 0.f;
        float bv1 = (bias && g1 < OC) ? bias[g1] : 0.f;
        #pragma unroll
        for (int nt=0;nt<4;nt++){
            int c = nBlk + nOff + nt*8 + 2*lr;
            if (g0 < OC)
                *reinterpret_cast<float2*>(&out[(long)z*outBz + (long)g0*npix + c]) =
                    make_float2(acc[mt][nt][0] + bv0, acc[mt][nt][1] + bv0);
            if (g1 < OC)
                *reinterpret_cast<float2*>(&out[(long)z*outBz + (long)g1*npix + c]) =
                    make_float2(acc[mt][nt][2] + bv1, acc[mt][nt][3] + bv1);
        }
    }
}

// ---------------- Winograd F(4,3) output transform; fp32 out and split emit optional
__global__ void wino_otrans(const float* __restrict__ Mm, const float* __restrict__ bias,
                            float* __restrict__ out, long outB,
                            __nv_bfloat16* __restrict__ Xh, __nv_bfloat16* __restrict__ Xl) {
    int idx = blockIdx.x*blockDim.x + threadIdx.x;
    if (idx >= D96*NT_) return;
    int n  = idx % NT_;
    int oc = idx / NT_;
    float m[6][6];
    #pragma unroll
    for (int p=0;p<36;p++)
        m[p/6][p%6] = Mm[((long)p*D96 + oc)*NT_ + n];
    float t[4][6];
    #pragma unroll
    for (int c=0;c<6;c++){
        float m0=m[0][c], m1=m[1][c], m2=m[2][c], m3=m[3][c], m4=m[4][c], m5=m[5][c];
        t[0][c] = m0 + m1 + m2 + m3 + m4;
        t[1][c] = m1 - m2 + 2.f*m3 - 2.f*m4;
        t[2][c] = m1 + m2 + 4.f*m3 + 4.f*m4;
        t[3][c] = m1 - m2 + 8.f*m3 - 8.f*m4 + m5;
    }
    float bv = bias[oc];
    int b   = n / (NT_/B_);
    int loc = n % (NT_/B_);
    int ty = loc / TPD_, tx = loc % TPD_;
    long pixBase = (long)(b*D96 + oc)*HW_ + (long)(4*ty)*W_ + 4*tx;
    float* dst = out ? (out + (long)b*outB + (long)oc*HW_ + (long)(4*ty)*W_ + 4*tx) : nullptr;
    #pragma unroll
    for (int r=0;r<4;r++){
        float t0=t[r][0], t1=t[r][1], t2=t[r][2], t3=t[r][3], t4=t[r][4], t5=t[r][5];
        float y[4];
        y[0] = t0 + t1 + t2 + t3 + t4 + bv;
        y[1] = t1 - t2 + 2.f*t3 - 2.f*t4 + bv;
        y[2] = t1 + t2 + 4.f*t3 + 4.f*t4 + bv;
        y[3] = t1 - t2 + 8.f*t3 - 8.f*t4 + t5 + bv;
        if (dst){
            float* row = dst + (long)r*W_;
            row[0]=y[0]; row[1]=y[1]; row[2]=y[2]; row[3]=y[3];
        }
        if (Xh){
            long pb = pixBase + (long)r*W_;
            #pragma unroll
            for (int c=0;c<4;c++){
                __nv_bfloat16 h,l; split_bf16(y[c], h, l);
                Xh[pb+c] = h; Xl[pb+c] = l;
            }
        }
    }
}

// ---------------- GEMM / 1x1 conv (fp32, low-res use) ----------------
__global__ __launch_bounds__(256, 2)
void conv1x1_kernel(const float* __restrict__ in, long inB, int IC,
                    const float* __restrict__ w, const float* __restrict__ bias,
                    float* __restrict__ out, long outB, int OC, int npix, long wB) {
    const int tid  = threadIdx.x;
    const int lane = tid & 31;
    const int wy   = tid >> 5;
    const int p0   = blockIdx.x * 512;
    const int oc0  = blockIdx.y * 32;
    const int z    = blockIdx.z;

    __shared__ float xs[16][512];
    __shared__ float ws[16][32];

    float4 acc[4][4];
    #pragma unroll
    for (int j=0;j<4;j++)
        #pragma unroll
        for (int q=0;q<4;q++) acc[j][q] = make_float4(0.f,0.f,0.f,0.f);

    const float* inb = in + (long)z*inB;
    const float* wz  = w  + (long)z*wB;

    for (int c0=0; c0<IC; c0+=16) {
        #pragma unroll
        for (int s=0;s<8;s++){
            int li  = tid + s*256;
            int icl = li >> 7, pq = li & 127;
            int p = p0 + pq*4;
            float4 v = make_float4(0.f,0.f,0.f,0.f);
            if (p < npix)
                v = *reinterpret_cast<const float4*>(&inb[(long)(c0+icl)*npix + p]);
            *reinterpret_cast<float4*>(&xs[icl][pq*4]) = v;
        }
        #pragma unroll
        for (int s=0;s<2;s++){
            int li  = tid + s*256;
            int icl = li >> 5, ocl = li & 31;
            float v = 0.f;
            if (oc0+ocl < OC) v = wz[(long)(oc0+ocl)*IC + (c0+icl)];
            ws[icl][ocl] = v;
        }
        __syncthreads();
        #pragma unroll
        for (int ic=0; ic<16; ic++) {
            float4 xv[4];
            #pragma unroll
            for (int q=0;q<4;q++) xv[q] = *reinterpret_cast<const float4*>(&xs[ic][(q*32+lane)*4]);
            float4 wv = *reinterpret_cast<const float4*>(&ws[ic][wy*4]);
            #pragma unroll
            for (int q=0;q<4;q++){
                acc[0][q].x += xv[q].x*wv.x; acc[0][q].y += xv[q].y*wv.x; acc[0][q].z += xv[q].z*wv.x; acc[0][q].w += xv[q].w*wv.x;
                acc[1][q].x += xv[q].x*wv.y; acc[1][q].y += xv[q].y*wv.y; acc[1][q].z += xv[q].z*wv.y; acc[1][q].w += xv[q].w*wv.y;
                acc[2][q].x += xv[q].x*wv.z; acc[2][q].y += xv[q].y*wv.z; acc[2][q].z += xv[q].z*wv.z; acc[2][q].w += xv[q].w*wv.z;
                acc[3][q].x += xv[q].x*wv.w; acc[3][q].y += xv[q].y*wv.w; acc[3][q].z += xv[q].z*wv.w; acc[3][q].w += xv[q].w*wv.w;
            }
        }
        __syncthreads();
    }

    #pragma unroll
    for (int j=0;j<4;j++){
        int oc = oc0 + wy*4 + j;
        if (oc >= OC) continue;
        float bv = bias ? bias[oc] : 0.f;
        #pragma unroll
        for (int q=0;q<4;q++){
            int p = p0 + (q*32+lane)*4;
            if (p < npix){
                float4 r = acc[j][q];
                r.x += bv; r.y += bv; r.z += bv; r.w += bv;
                *reinterpret_cast<float4*>(&out[(long)z*outB + (long)oc*npix + p]) = r;
            }
        }
    }
}

// ---------------- fused 8x8 max pool + depthwise 3x3 (24x24) ----------------
__global__ __launch_bounds__(576)
void pool_dw(const float* __restrict__ in, const float* __restrict__ w,
             const float* __restrict__ bias, float* __restrict__ out) {
    int bc = blockIdx.x;
    int c  = bc % QC_;
    int b  = bc / QC_;
    int t  = threadIdx.x;
    int oh = t / WL_, ow = t % WL_;
    __shared__ float sp[PL_];
    const float* p = in + ((long)b*QC_ + c)*HW_ + (long)oh*8*W_ + ow*8;
    float m = -INFINITY;
    #pragma unroll
    for (int r=0;r<8;r++)
        #pragma unroll
        for (int cc=0;cc<8;cc++)
            m = fmaxf(m, p[r*W_ + cc]);
    sp[t] = m;
    __syncthreads();
    const float* wc = w + (long)c*9;
    float s = bias[c];
    #pragma unroll
    for (int dr=-1;dr<=1;dr++){
        int hh = oh+dr; if (hh<0||hh>=HL_) continue;
        #pragma unroll
        for (int dc=-1;dc<=1;dc++){
            int ww = ow+dc; if (ww<0||ww>=WL_) continue;
            s += wc[(dr+1)*3 + (dc+1)] * sp[hh*WL_ + ww];
        }
    }
    out[((long)b*QC_ + c)*PL_ + t] = s;
}

// ---------------- fused rownorm + attn: one block per (b,h) ----------------
__global__ __launch_bounds__(256)
void attn_fused(const float* __restrict__ dw, const float* __restrict__ temp,
                float* __restrict__ attn) {
    int blk = blockIdx.x;
    int b = blk / HEADS, h = blk % HEADS;
    int tid = threadIdx.x, warp = tid >> 5, lane = tid & 31;
    __shared__ float sinv[96];
    for (int row = warp; row < 96; row += 8){
        const float* p = dw + ((long)b*QC_ + (row < 48 ? h*C48 + row : D96 + h*C48 + (row-48)))*PL_;
        float s = 0.f;
        for (int n = lane; n < PL_; n += 32){ float v = p[n]; s += v*v; }
        #pragma unroll
        for (int o=16;o>0;o>>=1) s += __shfl_xor_sync(0xffffffffu, s, o);
        if (lane == 0) sinv[row] = 1.f / fmaxf(sqrtf(s), 1e-12f);
    }
    __syncthreads();
    float tmp = temp[h];
    for (int idx = tid; idx < C48*C48; idx += 256){
        int i2 = idx / C48, j = idx % C48;
        const float* q = dw + ((long)b*QC_ +        h*C48 + i2)*PL_;
        const float* k = dw + ((long)b*QC_ + D96 + h*C48 + j )*PL_;
        float s = 0.f;
        for (int n=0;n<PL_;n++) s += q[n]*k[n];
        attn[((long)(b*HEADS+h)*C48 + i2)*C48 + j] = s * sinv[i2] * sinv[48+j] * tmp;
    }
}

// ---------------- top-k threshold softmaxes, combined ----------------
__global__ void topk_combine(const float* __restrict__ attn, const float* __restrict__ aw,
                             float* __restrict__ acomb) {
    int r = threadIdx.x;
    if (r >= B_*HEADS*C48) return;
    const float* row = attn + (long)r*C48;
    float a[C48], srt[C48];
    for (int j=0;j<C48;j++){ a[j]=row[j]; srt[j]=a[j]; }
    for (int x=1;x<C48;x++){
        float key = srt[x]; int j = x-1;
        while (j>=0 && srt[j]<key){ srt[j+1]=srt[j]; j--; }
        srt[j+1]=key;
    }
    const int kks[4] = {24,32,36,38};
    float m = srt[0];
    float th[4], sm[4];
    #pragma unroll
    for (int l=0;l<4;l++){
        th[l] = srt[kks[l]-1];
        float s = 0.f;
        for (int j=0;j<C48;j++) if (a[j] >= th[l]) s += expf(a[j]-m);
        sm[l] = s;
    }
    float w0=aw[0], w1=aw[1], w2=aw[2], w3=aw[3];
    for (int j=0;j<C48;j++){
        float e = expf(a[j]-m);
        float o = 0.f;
        if (a[j] >= th[0]) o += w0*e/sm[0];
        if (a[j] >= th[1]) o += w1*e/sm[1];
        if (a[j] >= th[2]) o += w2*e/sm[2];
        if (a[j] >= th[3]) o += w3*e/sm[3];
        acomb[(long)r*C48 + j] = o;
    }
}

// ---------------- out = gelu(Acomb @ v) ----------------
__global__ void av_gelu(const float* __restrict__ acomb, const float* __restrict__ dw,
                        float* __restrict__ outlow) {
    int idx = blockIdx.x*blockDim.x + threadIdx.x;
    if (idx >= B_*HEADS*C48*PL_) return;
    int n = idx % PL_;
    int c = (idx / PL_) % C48;
    int h = (idx / (PL_*C48)) % HEADS;
    int b =  idx / (PL_*C48*HEADS);
    const float* arow = acomb + (((long)(b*HEADS+h))*C48 + c)*C48;
    const float* v = dw + ((long)b*QC_ + 2*D96 + h*C48)*PL_;
    float s = 0.f;
    #pragma unroll 4
    for (int d=0;d<C48;d++) s += arow[d] * v[(long)d*PL_ + n];
    float g = 0.5f * s * (1.f + erff(s * 0.70710678118654752440f));
    outlow[((long)b*D96 + h*C48 + c)*PL_ + n] = g;
}

// ---------------- BN partials / finals ----------------
__global__ void bn_partial1(const float* __restrict__ src, float (*part)[16][2]) {
    int c = blockIdx.x;
    int chunk = blockIdx.y;
    const float* base = src + ((long)(chunk>>3)*C48 + c)*HW_ + (long)(chunk & 7)*(HW_/8);
    float s = 0.f, s2 = 0.f;
    for (int i = threadIdx.x; i < HW_/8; i += 256){
        float v = base[i]; s += v; s2 += v*v;
    }
    __shared__ float sh[512];
    sh[threadIdx.x] = s; sh[256+threadIdx.x] = s2; __syncthreads();
    for (int st=128; st>0; st>>=1){
        if (threadIdx.x < st){ sh[threadIdx.x]+=sh[threadIdx.x+st]; sh[256+threadIdx.x]+=sh[256+threadIdx.x+st]; }
        __syncthreads();
    }
    if (threadIdx.x == 0){ part[c][chunk][0] = sh[0]; part[c][chunk][1] = sh[256]; }
}

__global__ void bn_final1(const float (*part)[16][2], float* dst) {
    int c = threadIdx.x;
    if (c >= C48) return;
    float s = 0.f, s2 = 0.f;
    #pragma unroll
    for (int k=0;k<16;k++){ s += part[c][k][0]; s2 += part[c][k][1]; }
    float N = (float)(B_*HW_);
    float m = s/N;
    float var = s2/N - m*m;
    dst[c]       = m;
    dst[C48+c]   = rsqrtf(fmaxf(var,0.f) + 1e-5f);
}

__global__ void bn_low(const float* __restrict__ src, float* __restrict__ dst) {
    int c = blockIdx.x;
    float s = 0.f, s2 = 0.f;
    for (int i = threadIdx.x; i < B_*PL_; i += 256){
        int b = i / PL_, j = i % PL_;
        float v = src[((long)b*C48 + c)*PL_ + j];
        s += v; s2 += v*v;
    }
    __shared__ float sh[512];
    sh[threadIdx.x]=s; sh[256+threadIdx.x]=s2; __syncthreads();
    for (int st=128; st>0; st>>=1){
        if (threadIdx.x < st){ sh[threadIdx.x]+=sh[threadIdx.x+st]; sh[256+threadIdx.x]+=sh[256+threadIdx.x+st]; }
        __syncthreads();
    }
    if (threadIdx.x == 0){
        float N = (float)(B_*PL_);
        float m = sh[0]/N;
        float var = sh[256]/N - m*m;
        dst[c]     = m;
        dst[C48+c] = rsqrtf(fmaxf(var,0.f) + 1e-5f);
    }
}

// ---------------- EAF blend (both full-res) ----------------
__global__ void eaf_blend(const float* __restrict__ x, long xB,
                          const float* __restrict__ y, long yB,
                          const float* __restrict__ xk, const float* __restrict__ yq,
                          const float* __restrict__ bnx, const float* __restrict__ bny,
                          float* __restrict__ out, long outB) {
    int p = blockIdx.x*blockDim.x + threadIdx.x;
    int b = blockIdx.y;
    if (p >= HW_) return;
    long base = (long)b*C48*HW_ + p;
    float s = 0.f;
    for (int c=0;c<C48;c++){
        float a  = (xk[base + (long)c*HW_] - bnx[c]) * bnx[C48+c];
        float bb = (yq[base + (long)c*HW_] - bny[c]) * bny[C48+c];
        s += a*bb;
    }
    float sim = 1.f/(1.f + expf(-s));
    for (int c=0;c<D96;c++){
        float xv = x[(long)b*xB + (long)c*HW_ + p];
        float yv = y[(long)b*yB + (long)c*HW_ + p];
        out[(long)b*outB + (long)c*HW_ + p] = sim*xv + (1.f-sim)*yv;
    }
}

// ---------------- EAF blend HF variant: x/xk low res; emits split copy -------------
__global__ void eaf_blend_hf(const float* __restrict__ xlow,
                             const float* __restrict__ y, long yB,
                             const float* __restrict__ xklow,
                             const float* __restrict__ yq,
                             const float* __restrict__ bnx, const float* __restrict__ bny,
                             float* __restrict__ out, long outB,
                             __nv_bfloat16* __restrict__ Xh, __nv_bfloat16* __restrict__ Xl) {
    int p = blockIdx.x*blockDim.x + threadIdx.x;
    int b = blockIdx.y;
    if (p >= HW_) return;
    int h = p / W_, w = p % W_;
    int lp = (h>>3)*WL_ + (w>>3);
    long basey = (long)b*C48*HW_ + p;
    float s = 0.f;
    for (int c=0;c<C48;c++){
        float a  = (xklow[((long)b*C48 + c)*PL_ + lp] - bnx[c]) * bnx[C48+c];
        float bb = (yq[basey + (long)c*HW_] - bny[c]) * bny[C48+c];
        s += a*bb;
    }
    float sim = 1.f/(1.f + expf(-s));
    for (int c=0;c<D96;c++){
        float xv = xlow[((long)b*D96 + c)*PL_ + lp];
        float yv = y[(long)b*yB + (long)c*HW_ + p];
        float o  = sim*xv + (1.f-sim)*yv;
        out[(long)b*outB + (long)c*HW_ + p] = o;
        __nv_bfloat16 hh,ll; split_bf16(o, hh, ll);
        long xi = ((long)b*D96 + c)*HW_ + p;
        Xh[xi] = hh; Xl[xi] = ll;
    }
}

// ---------------- copy input into feats slot 0 ----------------
__global__ void copy_slot0(const float* __restrict__ x, float* __restrict__ feats) {
    long idx = (long)blockIdx.x*blockDim.x + threadIdx.x;
    if (idx >= (long)B_*D96*HW_) return;
    long per = (long)D96*HW_;
    int b = idx / per;
    long r = idx % per;
    feats[(long)b*QC_*HW_ + r] = x[idx];
}

// ---------------- convert fp32 activations -> split bf16 ----------------
__global__ void convert_x(const float* __restrict__ in, long inB,
                          __nv_bfloat16* __restrict__ Xh, __nv_bfloat16* __restrict__ Xl) {
    long idx = (long)blockIdx.x*blockDim.x + threadIdx.x;
    if (idx >= (long)B_*D96*HW_) return;
    long per = (long)D96*HW_;
    int z = (int)(idx / per);
    long r = idx - (long)z*per;
    float v = in[(long)z*inB + r];
    __nv_bfloat16 h,l; split_bf16(v, h, l);
    Xh[idx] = h; Xl[idx] = l;
}

// ---------------- orchestration ----------------
extern "C" void kernel_launch(void* const* d_in, const int* in_sizes, int n_in,
                              void* d_out, int out_size) {
    const float* x_in   = (const float*)d_in[0];
    const float* hf     = (const float*)d_in[1];
    const float* lf     = (const float*)d_in[2];
    const float* mkw_w  = (const float*)d_in[3];
    const float* mkw_b  = (const float*)d_in[4];
    const float* mkw_wc = (const float*)d_in[5];
    const float* mkw_bc = (const float*)d_in[6];
    const float* mkw_wh = (const float*)d_in[7];
    const float* mkw_bh = (const float*)d_in[8];
    const float* mkw_wv = (const float*)d_in[9];
    const float* mkw_bv = (const float*)d_in[10];
    const float* mkw_wa = (const float*)d_in[11];
    const float* mkw_ba = (const float*)d_in[12];
    const float* mkw_s  = (const float*)d_in[13];
    const float* dt_temp= (const float*)d_in[14];
    const float* dt_wqkv= (const float*)d_in[15];
    const float* dt_bqkv= (const float*)d_in[16];
    const float* dt_wdw = (const float*)d_in[17];
    const float* dt_bdw = (const float*)d_in[18];
    const float* dt_wprj= (const float*)d_in[19];
    const float* dt_bprj= (const float*)d_in[20];
    const float* dt_aw  = (const float*)d_in[21];
    const float* eh_wx  = (const float*)d_in[22];
    const float* eh_wy  = (const float*)d_in[23];
    const float* el_wx  = (const float*)d_in[24];
    const float* el_wy  = (const float*)d_in[25];
    const float* cab_w  = (const float*)d_in[26];
    const float* cab_b  = (const float*)d_in[27];
    float* out = (float*)d_out;

    float *feats, *qkvfull, *weff, *beff, *dw, *attn, *acomb,
          *low1, *low2, *xk, *yq, *yq2, *bnx, *bny, *bny2, *M;
    __nv_bfloat16 *Uh, *Ul, *UCh, *UCl, *Vh, *Vl, *Xh, *Xl, *HFh, *HFl, *LFh, *LFl, *WBh, *WBl;
    float (*bnpartA)[16][2]; float (*bnpartB)[16][2]; float (*bnpartC)[16][2];
    cudaGetSymbolAddress((void**)&feats,   g_feats);
    cudaGetSymbolAddress((void**)&qkvfull, g_qkvfull);
    cudaGetSymbolAddress((void**)&weff,    g_weff);
    cudaGetSymbolAddress((void**)&beff,    g_beff);
    cudaGetSymbolAddress((void**)&dw,      g_dw);
    cudaGetSymbolAddress((void**)&attn,    g_attn);
    cudaGetSymbolAddress((void**)&acomb,   g_acomb);
    cudaGetSymbolAddress((void**)&low1,    g_low1);
    cudaGetSymbolAddress((void**)&low2,    g_low2);
    cudaGetSymbolAddress((void**)&xk,      g_xk);
    cudaGetSymbolAddress((void**)&yq,      g_yq);
    cudaGetSymbolAddress((void**)&yq2,     g_yq2);
    cudaGetSymbolAddress((void**)&bnx,     g_bnx);
    cudaGetSymbolAddress((void**)&bny,     g_bny);
    cudaGetSymbolAddress((void**)&bny2,    g_bny2);
    cudaGetSymbolAddress((void**)&bnpartA, g_bnpartA);
    cudaGetSymbolAddress((void**)&bnpartB, g_bnpartB);
    cudaGetSymbolAddress((void**)&bnpartC, g_bnpartC);
    cudaGetSymbolAddress((void**)&Uh,      g_Uh);
    cudaGetSymbolAddress((void**)&Ul,      g_Ul);
    cudaGetSymbolAddress((void**)&UCh,     g_UCh);
    cudaGetSymbolAddress((void**)&UCl,     g_UCl);
    cudaGetSymbolAddress((void**)&Vh,      g_Vh);
    cudaGetSymbolAddress((void**)&Vl,      g_Vl);
    cudaGetSymbolAddress((void**)&M,       g_M);
    cudaGetSymbolAddress((void**)&Xh,      g_Xh);
    cudaGetSymbolAddress((void**)&Xl,      g_Xl);
    cudaGetSymbolAddress((void**)&HFh,     g_HFh);
    cudaGetSymbolAddress((void**)&HFl,     g_HFl);
    cudaGetSymbolAddress((void**)&LFh,     g_LFh);
    cudaGetSymbolAddress((void**)&LFl,     g_LFl);
    cudaGetSymbolAddress((void**)&WBh,     g_WBh);
    cudaGetSymbolAddress((void**)&WBl,     g_WBl);

    const long fB   = (long)QC_*HW_;
    const long dB   = (long)D96*HW_;
    const long cB   = (long)C48*HW_;
    const long lowB = (long)D96*PL_;
    const long lowC = (long)C48*PL_;
    const long nConv = (long)B_*D96*HW_;
    const unsigned convGrid = (unsigned)((nConv+255)/256);
    cudaStream_t S0 = (cudaStream_t)0;
    cudaStream_t S2 = g_si.s2, S3 = g_si.s3;

    // ---- prologue with forks ----
    cudaEventRecord(g_si.eS, S0);
    cudaStreamWaitEvent(S2, g_si.eS, 0);
    cudaStreamWaitEvent(S3, g_si.eS, 0);
    copy_slot0<<<convGrid, 256, 0, S0>>>(x_in, feats);
    convert_x<<<convGrid, 256, 0, S2>>>(hf, dB, HFh, HFl);
    convert_all_w<<<(WB_TOT+255)/256, 256, 0, S2>>>(dt_wqkv, eh_wy, el_wx, el_wy, WBh, WBl);
    cudaEventRecord(g_si.eW, S2);
    convert_x<<<convGrid, 256, 0, S3>>>(lf, dB, LFh, LFl);
    wino_wtrans<<<(D96*QC_+255)/256, 256, 0, S3>>>(cab_w, D96, QC_, UCh, UCl);
    cudaEventRecord(g_si.eC, S3);

    for (int i=0;i<2;i++){
        const float* s4 = mkw_s + i*4;

        // ---- fork s3: ely GEMM + BN (LF branch; independent of layer body) ----
        if (i == 0) cudaStreamWaitEvent(S3, g_si.eW, 0);   // weight bank ready
        else        cudaStreamWaitEvent(S3, g_si.eB, 0);   // prev layer's eaf_blend done
        gemm1x1_tc<<<dim3(HW_/128, 1, B_), 256, 0, S3>>>(WBh + WB_ELY + (size_t)i*C48*D96,
            WBl + WB_ELY + (size_t)i*C48*D96, LFh, LFl,
            nullptr, yq2, D96, C48, HW_, cB);
        bn_partial1<<<dim3(C48,16), 256, 0, S3>>>(yq2, bnpartC);
        bn_final1<<<1, C48, 0, S3>>>(bnpartC, bny2);
        cudaEventRecord(g_si.e4, S3);

        // ---- stream0: MKW wino (split emit only; fp32 output is dead) ----
        build_weight<<<(D96*D96+255)/256, 256, 0, S0>>>(mkw_w + (size_t)i*D96*D96*9,
                                                 mkw_wc + (size_t)i*D96*D96*9,
                                                 mkw_wh + (size_t)i*D96*D96*3,
                                                 mkw_wv + (size_t)i*D96*D96*3,
                                                 mkw_wa + (size_t)i*D96*D96*9,
                                                 s4, weff,
                                                 mkw_b + i*D96, mkw_bc + i*D96,
                                                 mkw_bh + i*D96, mkw_bv + i*D96,
                                                 mkw_ba + i*D96, beff);
        const float* xcur = feats + (size_t)i*D96*HW_;
        wino_wtrans<<<(D96*D96+255)/256, 256, 0, S0>>>(weff, D96, D96, Uh, Ul);
        wino_itrans<<<dim3(NT_/256, D96), 256, 0, S0>>>(xcur, fB, D96, Vh, Vl);
        wino_gemm<<<dim3(NT_/128, 1, 36), 256, 0, S0>>>(Uh, Ul, Vh, Vl, M, D96, NT_);
        wino_otrans<<<(D96*NT_+255)/256, 256, 0, S0>>>(M, beff, nullptr, 0L, Xh, Xl);

        if (i == 0) cudaStreamWaitEvent(S0, g_si.eW, 0);
        gemm1x1_tc<<<dim3(HW_/128, 3, B_), 256, 0, S0>>>(WBh + WB_QKV + (size_t)i*QC_*D96,
            WBl + WB_QKV + (size_t)i*QC_*D96, Xh, Xl,
            dt_bqkv + i*QC_, qkvfull, D96, QC_, HW_, fB);
        cudaEventRecord(g_si.e1, S0);

        // ---- fork s2: hf-side yq GEMM + BN, concurrent with attention chain ----
        cudaStreamWaitEvent(S2, g_si.e1, 0);
        gemm1x1_tc<<<dim3(HW_/128, 1, B_), 256, 0, S2>>>(WBh + WB_EHY + (size_t)i*C48*D96,
            WBl + WB_EHY + (size_t)i*C48*D96, HFh, HFl,
            nullptr, yq, D96, C48, HW_, cB);
        bn_partial1<<<dim3(C48,16), 256, 0, S2>>>(yq, bnpartB);
        bn_final1<<<1, C48, 0, S2>>>(bnpartB, bny);
        cudaEventRecord(g_si.e2, S2);

        // ---- stream0: attention chain ----
        pool_dw<<<B_*QC_, 576, 0, S0>>>(qkvfull, dt_wdw + (size_t)i*QC_*9, dt_bdw + i*QC_, dw);
        attn_fused<<<B_*HEADS, 256, 0, S0>>>(dw, dt_temp + i*HEADS, attn);
        topk_combine<<<1, 192, 0, S0>>>(attn, dt_aw + i*4, acomb);
        av_gelu<<<(B_*HEADS*C48*PL_+255)/256, 256, 0, S0>>>(acomb, dw, low1);
        conv1x1_kernel<<<dim3((PL_+511)/512, D96/32, B_), 256, 0, S0>>>(
            low1, lowB, D96, dt_wprj + (size_t)i*D96*D96, dt_bprj + i*D96,
            low2, lowB, D96, PL_, 0L);
        conv1x1_kernel<<<dim3((PL_+511)/512, (C48+31)/32, B_), 256, 0, S0>>>(
            low2, lowB, D96, eh_wx + (size_t)i*C48*D96, nullptr, xk, lowC, C48, PL_, 0L);
        bn_low<<<C48, 256, 0, S0>>>(xk, bnx);

        float* slot_out = feats + (size_t)(i+1)*D96*HW_;
        cudaStreamWaitEvent(S0, g_si.e2, 0);
        eaf_blend_hf<<<dim3(HW_/256, B_), 256, 0, S0>>>(low2, hf, dB, xk, yq, bnx, bny,
                                                        slot_out, fB, Xh, Xl);

        // ---- EAF_LF: elx on stream0, ely already done on s3 ----
        gemm1x1_tc<<<dim3(HW_/128, 1, B_), 256, 0, S0>>>(WBh + WB_ELX + (size_t)i*C48*D96,
            WBl + WB_ELX + (size_t)i*C48*D96, Xh, Xl,
            nullptr, xk, D96, C48, HW_, cB);
        bn_partial1<<<dim3(C48,16), 256, 0, S0>>>(xk, bnpartA);
        bn_final1<<<1, C48, 0, S0>>>(bnpartA, bnx);
        cudaStreamWaitEvent(S0, g_si.e4, 0);
        eaf_blend<<<dim3(HW_/256, B_), 256, 0, S0>>>(slot_out, fB, lf, dB, xk, yq2, bnx, bny2,
                                                     slot_out, fB);
        cudaEventRecord(g_si.eB, S0);
    }

    // ---- CAB conv3x3 (IC=288) via Winograd + TC GEMM (U hoisted on s3) ----
    cudaStreamWaitEvent(S0, g_si.eC, 0);
    wino_itrans<<<dim3(NT_/256, QC_), 256, 0, S0>>>(feats, fB, QC_, Vh, Vl);
    wino_gemm<<<dim3(NT_/128, 1, 36), 256, 0, S0>>>(UCh, UCl, Vh, Vl, M, QC_, NT_);
    wino_otrans<<<(D96*NT_+255)/256, 256, 0, S0>>>(M, cab_b, out, dB, nullptr, nullptr);
}

// round 15
// speedup vs baseline: 1.2523x; 1.2523x over previous
#include <cuda_runtime.h>
#include <cuda_bf16.h>
#include <cstdint>
#include <math.h>

// ---------------- problem constants ----------------
#define B_    2
#define D96   96
#define H_    192
#define W_    192
#define HW_   (H_*W_)        // 36864
#define HEADS 2
#define C48   48
#define HL_   24
#define WL_   24
#define PL_   (HL_*WL_)      // 576
#define QC_   288            // 3*D
#define TPD_  48             // winograd F(4,3) tiles per spatial dim
#define NT_   4608           // 48*48*2 tiles

// weight-bank offsets (elements) in g_WBh/g_WBl
#define WB_QKV   0           // [L][288][96]  -> 2*27648
#define WB_EHY   55296       // [L][48][96]   -> 2*4608
#define WB_ELX   64512
#define WB_ELY   73728
#define WB_TOT   82944

// ---------------- scratch (static, no runtime alloc) ----------------
__device__ float g_feats  [(size_t)B_*QC_*HW_];
__device__ float g_qkvfull[(size_t)B_*QC_*HW_];
__device__ float g_weff   [D96*D96*9];
__device__ float g_beff   [D96];
__device__ float g_dw     [(size_t)B_*QC_*PL_];
__device__ float g_attn   [B_*HEADS*C48*C48];
__device__ float g_acomb  [B_*HEADS*C48*C48];
__device__ float g_low1   [(size_t)B_*D96*PL_];
__device__ float g_low2   [(size_t)B_*D96*PL_];
__device__ float g_xk     [(size_t)B_*C48*HW_];
__device__ float g_yq     [(size_t)B_*C48*HW_];
__device__ float g_bnx    [2*C48];
__device__ float g_bny    [2*C48];
__device__ float g_bnpart2[96][16][2];
// winograd F(4x4,3x3) scratch — split bf16 operands, fp32 M
__device__ __nv_bfloat16 g_Uh [(size_t)36*D96*D96];   // MKW weights
__device__ __nv_bfloat16 g_Ul [(size_t)36*D96*D96];
__device__ __nv_bfloat16 g_UCh[(size_t)36*D96*QC_];   // CAB weights (hoisted)
__device__ __nv_bfloat16 g_UCl[(size_t)36*D96*QC_];
__device__ __nv_bfloat16 g_Vh [(size_t)36*QC_*NT_];
__device__ __nv_bfloat16 g_Vl [(size_t)36*QC_*NT_];
__device__ float         g_M  [(size_t)36*D96*NT_];
// split-bf16 activations / weights for TC 1x1 convs
__device__ __nv_bfloat16 g_Xh [(size_t)B_*D96*HW_];
__device__ __nv_bfloat16 g_Xl [(size_t)B_*D96*HW_];
__device__ __nv_bfloat16 g_HFh[(size_t)B_*D96*HW_];
__device__ __nv_bfloat16 g_HFl[(size_t)B_*D96*HW_];
__device__ __nv_bfloat16 g_LFh[(size_t)B_*D96*HW_];
__device__ __nv_bfloat16 g_LFl[(size_t)B_*D96*HW_];
__device__ __nv_bfloat16 g_WBh[WB_TOT];
__device__ __nv_bfloat16 g_WBl[WB_TOT];

__device__ __forceinline__ void split_bf16(float x, __nv_bfloat16& h, __nv_bfloat16& l){
    h = __float2bfloat16_rn(x);
    l = __float2bfloat16_rn(x - __bfloat162float(h));
}

// ---------------- MKW effective weight (+bias folded in) ----------------
__global__ void build_weight(const float* __restrict__ w,  const float* __restrict__ wc,
                             const float* __restrict__ wh, const float* __restrict__ wv,
                             const float* __restrict__ wa, const float* __restrict__ s4,
                             float* __restrict__ weff,
                             const float* __restrict__ b,  const float* __restrict__ bc,
                             const float* __restrict__ bh, const float* __restrict__ bv,
                             const float* __restrict__ ba, float* __restrict__ beff) {
    int idx = blockIdx.x * blockDim.x + threadIdx.x;   // oc*96+ic
    const float s0=s4[0], s1=s4[1], s2=s4[2], s3=s4[3];
    if (blockIdx.x == 0 && threadIdx.x < D96){
        int c = threadIdx.x;
        beff[c] = b[c] + s0*bc[c] + s1*bh[c] + s2*bv[c] + s3*ba[c];
    }
    if (idx >= D96*D96) return;
    float wcl[9], wal[9];
    float csum = 0.f;
    #pragma unroll
    for (int t=0;t<9;t++){ wcl[t]=wc[(size_t)idx*9+t]; csum+=wcl[t]; }
    #pragma unroll
    for (int t=0;t<9;t++){ wal[t]=wa[(size_t)idx*9+t]; }
    const int perm[9] = {3,0,1,6,4,2,7,8,5};
    float wh0=wh[(size_t)idx*3+0], wh1=wh[(size_t)idx*3+1], wh2=wh[(size_t)idx*3+2];
    float wv0=wv[(size_t)idx*3+0], wv1=wv[(size_t)idx*3+1], wv2=wv[(size_t)idx*3+2];
    #pragma unroll
    for (int t=0;t<9;t++){
        float wcd = wcl[t] - (t==4 ? csum : 0.f);
        float whd = 0.f;
        if (t==0) whd =  wh0; else if (t==3) whd =  wh1; else if (t==6) whd =  wh2;
        else if (t==2) whd = -wh0; else if (t==5) whd = -wh1; else if (t==8) whd = -wh2;
        float wvd = 0.f;
        if (t<3) wvd = (t==0?wv0:(t==1?wv1:wv2));
        else if (t>=6) wvd = -(t==6?wv0:(t==7?wv1:wv2));
        float wad = wal[t] - wal[perm[t]];
        weff[(size_t)idx*9+t] = w[(size_t)idx*9+t] + s0*wcd + s1*whd + s2*wvd + s3*wad;
    }
}

// ---------------- hoisted: convert ALL 1x1 weights to split bf16 -------------------
__global__ void convert_all_w(const float* __restrict__ qkv, const float* __restrict__ ehy,
                              const float* __restrict__ elx, const float* __restrict__ ely,
                              __nv_bfloat16* __restrict__ Wh, __nv_bfloat16* __restrict__ Wl){
    int idx = blockIdx.x*blockDim.x + threadIdx.x;
    if (idx >= WB_TOT) return;
    float v;
    if (idx < WB_EHY)      v = qkv[idx];
    else if (idx < WB_ELX) v = ehy[idx - WB_EHY];
    else if (idx < WB_ELY) v = elx[idx - WB_ELX];
    else                   v = ely[idx - WB_ELY];
    __nv_bfloat16 h,l; split_bf16(v, h, l);
    Wh[idx] = h; Wl[idx] = l;
}

// ---------------- Winograd F(4x4,3x3): weight transform U = G g G^T (split bf16) ----
__global__ void wino_wtrans(const float* __restrict__ w, int OC, int IC,
                            __nv_bfloat16* __restrict__ Uh, __nv_bfloat16* __restrict__ Ul) {
    int idx = blockIdx.x*blockDim.x + threadIdx.x;   // oc*IC + ic
    if (idx >= OC*IC) return;
    float g[9];
    #pragma unroll
    for (int t=0;t<9;t++) g[t] = w[(size_t)idx*9 + t];
    const float i6 = 1.f/6.f, i12 = 1.f/12.f, i24 = 1.f/24.f;
    float Gg[6][3];
    #pragma unroll
    for (int c=0;c<3;c++){
        float g0 = g[c], g1 = g[3+c], g2 = g[6+c];
        Gg[0][c] = 0.25f*g0;
        Gg[1][c] = -i6*(g0 + g1 + g2);
        Gg[2][c] =  i6*(-g0 + g1 - g2);
        Gg[3][c] =  i24*g0 + i12*g1 + i6*g2;
        Gg[4][c] =  i24*g0 - i12*g1 + i6*g2;
        Gg[5][c] =  g2;
    }
    long OI = (long)OC*IC;
    #pragma unroll
    for (int r=0;r<6;r++){
        float a = Gg[r][0], b = Gg[r][1], c2 = Gg[r][2];
        float u[6];
        u[0] = 0.25f*a;
        u[1] = -i6*(a + b + c2);
        u[2] =  i6*(-a + b - c2);
        u[3] =  i24*a + i12*b + i6*c2;
        u[4] =  i24*a - i12*b + i6*c2;
        u[5] =  c2;
        #pragma unroll
        for (int q=0;q<6;q++){
            __nv_bfloat16 h,l; split_bf16(u[q], h, l);
            Uh[(long)(r*6+q)*OI + idx] = h;
            Ul[(long)(r*6+q)*OI + idx] = l;
        }
    }
}

// ---------------- Winograd F(4,3) input transform V = B^T d B (split bf16) ----------
__global__ void wino_itrans(const float* __restrict__ in, long inB, int IC,
                            __nv_bfloat16* __restrict__ Vh, __nv_bfloat16* __restrict__ Vl) {
    int n  = blockIdx.x*blockDim.x + threadIdx.x;   // 0..NT_-1
    int ic = blockIdx.y;
    int b   = n / (NT_/B_);
    int loc = n % (NT_/B_);
    int ty = loc / TPD_, tx = loc % TPD_;
    const float* src = in + (long)b*inB + (long)ic*HW_;
    int h0 = 4*ty - 1, w0 = 4*tx - 1;
    float d[6][6];
    #pragma unroll
    for (int r=0;r<6;r++){
        int hh = h0 + r;
        bool hok = (hh >= 0 && hh < H_);
        #pragma unroll
        for (int c=0;c<6;c++){
            int ww = w0 + c;
            d[r][c] = (hok && ww >= 0 && ww < W_) ? src[hh*W_ + ww] : 0.f;
        }
    }
    float t[6][6];
    #pragma unroll
    for (int c=0;c<6;c++){
        float d0=d[0][c], d1=d[1][c], d2=d[2][c], d3=d[3][c], d4=d[4][c], d5=d[5][c];
        t[0][c] =  4.f*d0 - 5.f*d2 + d4;
        t[1][c] = -4.f*d1 - 4.f*d2 + d3 + d4;
        t[2][c] =  4.f*d1 - 4.f*d2 - d3 + d4;
        t[3][c] = -2.f*d1 -      d2 + 2.f*d3 + d4;
        t[4][c] =  2.f*d1 -      d2 - 2.f*d3 + d4;
        t[5][c] =  4.f*d1 - 5.f*d3 + d5;
    }
    long stride = (long)IC*NT_;
    long base = (long)ic*NT_ + n;
    #pragma unroll
    for (int r=0;r<6;r++){
        float t0=t[r][0], t1=t[r][1], t2=t[r][2], t3=t[r][3], t4=t[r][4], t5=t[r][5];
        float v[6];
        v[0] =  4.f*t0 - 5.f*t2 + t4;
        v[1] = -4.f*t1 - 4.f*t2 + t3 + t4;
        v[2] =  4.f*t1 - 4.f*t2 - t3 + t4;
        v[3] = -2.f*t1 -      t2 + 2.f*t3 + t4;
        v[4] =  2.f*t1 -      t2 - 2.f*t3 + t4;
        v[5] =  4.f*t1 - 5.f*t3 + t5;
        #pragma unroll
        for (int q=0;q<6;q++){
            __nv_bfloat16 h,l; split_bf16(v[q], h, l);
            Vh[(long)(r*6+q)*stride + base] = h;
            Vl[(long)(r*6+q)*stride + base] = l;
        }
    }
}

// ---------------- split-bf16 TC GEMM, fused phases + double buffer -----------------
__global__ __launch_bounds__(256)
void wino_gemm(const __nv_bfloat16* __restrict__ Uh, const __nv_bfloat16* __restrict__ Ul,
               const __nv_bfloat16* __restrict__ Vh, const __nv_bfloat16* __restrict__ Vl,
               float* __restrict__ Mo, int IC, int NT) {
    const int p    = blockIdx.z;
    const int nBlk = blockIdx.x * 128;
    const int tid  = threadIdx.x;
    const int warp = tid >> 5, lane = tid & 31;
    const int mOff = (warp >> 2) * 48;
    const int nOff = (warp & 3) * 32;
    const int lq   = lane >> 2;
    const int lr   = lane & 3;

    __shared__ uint32_t Ah[2][96*9], Al[2][96*9];
    __shared__ uint32_t Bh[2][128*9], Bl[2][128*9];

    float acc[3][4][4];
    #pragma unroll
    for (int mt=0;mt<3;mt++)
        #pragma unroll
        for (int nt=0;nt<4;nt++)
            #pragma unroll
            for (int q=0;q<4;q++) acc[mt][nt][q]=0.f;

    const long Uplane = (long)p*96*IC;
    const long Vplane = (long)p*IC*NT;
    const int nIter = IC/16;

    #pragma unroll
    for (int s=0;s<3;s++){
        int e = tid + s*256;
        int m = e >> 3, kp = e & 7;
        long off = Uplane + (long)m*IC + kp*2;
        Ah[0][m*9+kp] = *reinterpret_cast<const uint32_t*>(Uh + off);
        Al[0][m*9+kp] = *reinterpret_cast<const uint32_t*>(Ul + off);
    }
    #pragma unroll
    for (int s=0;s<2;s++){
        int e = tid + s*256;
        int kp = e >> 6, j = e & 63;
        long off = Vplane + (long)(2*kp)*NT + nBlk + 2*j;
        uint32_t h0 = *reinterpret_cast<const uint32_t*>(Vh + off);
        uint32_t h1 = *reinterpret_cast<const uint32_t*>(Vh + off + NT);
        Bh[0][(2*j  )*9 + kp] = __byte_perm(h0, h1, 0x5410);
        Bh[0][(2*j+1)*9 + kp] = __byte_perm(h0, h1, 0x7632);
        uint32_t l0 = *reinterpret_cast<const uint32_t*>(Vl + off);
        uint32_t l1 = *reinterpret_cast<const uint32_t*>(Vl + off + NT);
        Bl[0][(2*j  )*9 + kp] = __byte_perm(l0, l1, 0x5410);
        Bl[0][(2*j+1)*9 + kp] = __byte_perm(l0, l1, 0x7632);
    }
    __syncthreads();

    for (int it=0; it<nIter; it++){
        const int cur = it & 1, nxt = cur ^ 1;
        const bool more = (it+1 < nIter);

        uint32_t sa[6], sb[8];
        if (more){
            int icb = (it+1)*16;
            #pragma unroll
            for (int s=0;s<3;s++){
                int e = tid + s*256;
                int m = e >> 3, kp = e & 7;
                long off = Uplane + (long)m*IC + icb + kp*2;
                sa[2*s  ] = *reinterpret_cast<const uint32_t*>(Uh + off);
                sa[2*s+1] = *reinterpret_cast<const uint32_t*>(Ul + off);
            }
            #pragma unroll
            for (int s=0;s<2;s++){
                int e = tid + s*256;
                int kp = e >> 6, j = e & 63;
                long off = Vplane + (long)(icb + 2*kp)*NT + nBlk + 2*j;
                sb[4*s  ] = *reinterpret_cast<const uint32_t*>(Vh + off);
                sb[4*s+1] = *reinterpret_cast<const uint32_t*>(Vh + off + NT);
                sb[4*s+2] = *reinterpret_cast<const uint32_t*>(Vl + off);
                sb[4*s+3] = *reinterpret_cast<const uint32_t*>(Vl + off + NT);
            }
        }

        #pragma unroll
        for (int ph=0; ph<3; ph++){
            const uint32_t* As = (ph < 2) ? Ah[cur] : Al[cur];
            const uint32_t* Bs = (ph == 1) ? Bl[cur] : Bh[cur];
            uint32_t a[3][4], b[4][2];
            #pragma unroll
            for (int mt=0;mt<3;mt++){
                int m0 = mOff + mt*16;
                a[mt][0] = As[(m0     + lq)*9 +     lr];
                a[mt][1] = As[(m0 + 8 + lq)*9 +     lr];
                a[mt][2] = As[(m0     + lq)*9 + 4 + lr];
                a[mt][3] = As[(m0 + 8 + lq)*9 + 4 + lr];
            }
            #pragma unroll
            for (int nt=0;nt<4;nt++){
                int n0 = nOff + nt*8;
                b[nt][0] = Bs[(n0 + lq)*9 +     lr];
                b[nt][1] = Bs[(n0 + lq)*9 + 4 + lr];
            }
            #pragma unroll
            for (int mt=0;mt<3;mt++)
                #pragma unroll
                for (int nt=0;nt<4;nt++){
                    asm volatile(
                        "mma.sync.aligned.m16n8k16.row.col.f32.bf16.bf16.f32 "
                        "{%0,%1,%2,%3}, {%4,%5,%6,%7}, {%8,%9}, {%0,%1,%2,%3};"
                        : "+f"(acc[mt][nt][0]), "+f"(acc[mt][nt][1]),
                          "+f"(acc[mt][nt][2]), "+f"(acc[mt][nt][3])
                        : "r"(a[mt][0]), "r"(a[mt][1]), "r"(a[mt][2]), "r"(a[mt][3]),
                          "r"(b[nt][0]), "r"(b[nt][1]));
                }
        }

        if (more){
            #pragma unroll
            for (int s=0;s<3;s++){
                int e = tid + s*256;
                int m = e >> 3, kp = e & 7;
                Ah[nxt][m*9+kp] = sa[2*s];
                Al[nxt][m*9+kp] = sa[2*s+1];
            }
            #pragma unroll
            for (int s=0;s<2;s++){
                int e = tid + s*256;
                int kp = e >> 6, j = e & 63;
                Bh[nxt][(2*j  )*9 + kp] = __byte_perm(sb[4*s], sb[4*s+1], 0x5410);
                Bh[nxt][(2*j+1)*9 + kp] = __byte_perm(sb[4*s], sb[4*s+1], 0x7632);
                Bl[nxt][(2*j  )*9 + kp] = __byte_perm(sb[4*s+2], sb[4*s+3], 0x5410);
                Bl[nxt][(2*j+1)*9 + kp] = __byte_perm(sb[4*s+2], sb[4*s+3], 0x7632);
            }
        }
        __syncthreads();
    }

    long Mbase = (long)p*96*NT;
    #pragma unroll
    for (int mt=0;mt<3;mt++){
        int r0 = mOff + mt*16 + lq;
        #pragma unroll
        for (int nt=0;nt<4;nt++){
            int c = nBlk + nOff + nt*8 + 2*lr;
            *reinterpret_cast<float2*>(&Mo[Mbase + (long)r0*NT + c]) =
                make_float2(acc[mt][nt][0], acc[mt][nt][1]);
            *reinterpret_cast<float2*>(&Mo[Mbase + (long)(r0+8)*NT + c]) =
                make_float2(acc[mt][nt][2], acc[mt][nt][3]);
        }
    }
}

// ---------------- split-bf16 TC GEMM for 1x1 convs (double buffered) ----------------
__global__ __launch_bounds__(256)
void gemm1x1_tc(const __nv_bfloat16* __restrict__ Wh, const __nv_bfloat16* __restrict__ Wl,
                const __nv_bfloat16* __restrict__ Xh, const __nv_bfloat16* __restrict__ Xl,
                const float* __restrict__ bias, float* __restrict__ out,
                int IC, int OC, int npix, long outBz) {
    const int z    = blockIdx.z;
    const int nBlk = blockIdx.x * 128;
    const int mBlk = blockIdx.y * 96;
    const int tid  = threadIdx.x;
    const int warp = tid >> 5, lane = tid & 31;
    const int mOff = (warp >> 2) * 48;
    const int nOff = (warp & 3) * 32;
    const int lq   = lane >> 2;
    const int lr   = lane & 3;

    __shared__ uint32_t Ah[2][96*9], Al[2][96*9];
    __shared__ uint32_t Bh[2][128*9], Bl[2][128*9];

    float acc[3][4][4];
    #pragma unroll
    for (int mt=0;mt<3;mt++)
        #pragma unroll
        for (int nt=0;nt<4;nt++)
            #pragma unroll
            for (int q=0;q<4;q++) acc[mt][nt][q]=0.f;

    const long Xplane = (long)z*IC*npix;
    const int nIter = IC/16;

    #pragma unroll
    for (int s=0;s<3;s++){
        int e = tid + s*256;
        int m = e >> 3, kp = e & 7;
        int gm = mBlk + m;
        uint32_t vh = 0, vl = 0;
        if (gm < OC){
            long off = (long)gm*IC + kp*2;
            vh = *reinterpret_cast<const uint32_t*>(Wh + off);
            vl = *reinterpret_cast<const uint32_t*>(Wl + off);
        }
        Ah[0][m*9+kp] = vh; Al[0][m*9+kp] = vl;
    }
    #pragma unroll
    for (int s=0;s<2;s++){
        int e = tid + s*256;
        int kp = e >> 6, j = e & 63;
        long off = Xplane + (long)(2*kp)*npix + nBlk + 2*j;
        uint32_t h0 = *reinterpret_cast<const uint32_t*>(Xh + off);
        uint32_t h1 = *reinterpret_cast<const uint32_t*>(Xh + off + npix);
        Bh[0][(2*j  )*9 + kp] = __byte_perm(h0, h1, 0x5410);
        Bh[0][(2*j+1)*9 + kp] = __byte_perm(h0, h1, 0x7632);
        uint32_t l0 = *reinterpret_cast<const uint32_t*>(Xl + off);
        uint32_t l1 = *reinterpret_cast<const uint32_t*>(Xl + off + npix);
        Bl[0][(2*j  )*9 + kp] = __byte_perm(l0, l1, 0x5410);
        Bl[0][(2*j+1)*9 + kp] = __byte_perm(l0, l1, 0x7632);
    }
    __syncthreads();

    for (int it=0; it<nIter; it++){
        const int cur = it & 1, nxt = cur ^ 1;
        const bool more = (it+1 < nIter);

        uint32_t sa[6], sb[8];
        if (more){
            int icb = (it+1)*16;
            #pragma unroll
            for (int s=0;s<3;s++){
                int e = tid + s*256;
                int m = e >> 3, kp = e & 7;
                int gm = mBlk + m;
                uint32_t vh = 0, vl = 0;
                if (gm < OC){
                    long off = (long)gm*IC + icb + kp*2;
                    vh = *reinterpret_cast<const uint32_t*>(Wh + off);
                    vl = *reinterpret_cast<const uint32_t*>(Wl + off);
                }
                sa[2*s] = vh; sa[2*s+1] = vl;
            }
            #pragma unroll
            for (int s=0;s<2;s++){
                int e = tid + s*256;
                int kp = e >> 6, j = e & 63;
                long off = Xplane + (long)(icb + 2*kp)*npix + nBlk + 2*j;
                sb[4*s  ] = *reinterpret_cast<const uint32_t*>(Xh + off);
                sb[4*s+1] = *reinterpret_cast<const uint32_t*>(Xh + off + npix);
                sb[4*s+2] = *reinterpret_cast<const uint32_t*>(Xl + off);
                sb[4*s+3] = *reinterpret_cast<const uint32_t*>(Xl + off + npix);
            }
        }

        #pragma unroll
        for (int ph=0; ph<3; ph++){
            const uint32_t* As = (ph < 2) ? Ah[cur] : Al[cur];
            const uint32_t* Bs = (ph == 1) ? Bl[cur] : Bh[cur];
            uint32_t a[3][4], b[4][2];
            #pragma unroll
            for (int mt=0;mt<3;mt++){
                int m0 = mOff + mt*16;
                a[mt][0] = As[(m0     + lq)*9 +     lr];
                a[mt][1] = As[(m0 + 8 + lq)*9 +     lr];
                a[mt][2] = As[(m0     + lq)*9 + 4 + lr];
                a[mt][3] = As[(m0 + 8 + lq)*9 + 4 + lr];
            }
            #pragma unroll
            for (int nt=0;nt<4;nt++){
                int n0 = nOff + nt*8;
                b[nt][0] = Bs[(n0 + lq)*9 +     lr];
                b[nt][1] = Bs[(n0 + lq)*9 + 4 + lr];
            }
            #pragma unroll
            for (int mt=0;mt<3;mt++)
                #pragma unroll
                for (int nt=0;nt<4;nt++){
                    asm volatile(
                        "mma.sync.aligned.m16n8k16.row.col.f32.bf16.bf16.f32 "
                        "{%0,%1,%2,%3}, {%4,%5,%6,%7}, {%8,%9}, {%0,%1,%2,%3};"
                        : "+f"(acc[mt][nt][0]), "+f"(acc[mt][nt][1]),
                          "+f"(acc[mt][nt][2]), "+f"(acc[mt][nt][3])
                        : "r"(a[mt][0]), "r"(a[mt][1]), "r"(a[mt][2]), "r"(a[mt][3]),
                          "r"(b[nt][0]), "r"(b[nt][1]));
                }
        }

        if (more){
            #pragma unroll
            for (int s=0;s<3;s++){
                int e = tid + s*256;
                int m = e >> 3, kp = e & 7;
                Ah[nxt][m*9+kp] = sa[2*s];
                Al[nxt][m*9+kp] = sa[2*s+1];
            }
            #pragma unroll
            for (int s=0;s<2;s++){
                int e = tid + s*256;
                int kp = e >> 6, j = e & 63;
                Bh[nxt][(2*j  )*9 + kp] = __byte_perm(sb[4*s], sb[4*s+1], 0x5410);
                Bh[nxt][(2*j+1)*9 + kp] = __byte_perm(sb[4*s], sb[4*s+1], 0x7632);
                Bl[nxt][(2*j  )*9 + kp] = __byte_perm(sb[4*s+2], sb[4*s+3], 0x5410);
                Bl[nxt][(2*j+1)*9 + kp] = __byte_perm(sb[4*s+2], sb[4*s+3], 0x7632);
            }
        }
        __syncthreads();
    }

    #pragma unroll
    for (int mt=0;mt<3;mt++){
        int r0 = mOff + mt*16 + lq;
        int g0 = mBlk + r0, g1 = g0 + 8;
        float bv0 = (bias && g0 < OC) ? bias[g0] : 0.f;
        float bv1 = (bias && g1 < OC) ? bias[g1] : 0.f;
        #pragma unroll
        for (int nt=0;nt<4;nt++){
            int c = nBlk + nOff + nt*8 + 2*lr;
            if (g0 < OC)
                *reinterpret_cast<float2*>(&out[(long)z*outBz + (long)g0*npix + c]) =
                    make_float2(acc[mt][nt][0] + bv0, acc[mt][nt][1] + bv0);
            if (g1 < OC)
                *reinterpret_cast<float2*>(&out[(long)z*outBz + (long)g1*npix + c]) =
                    make_float2(acc[mt][nt][2] + bv1, acc[mt][nt][3] + bv1);
        }
    }
}

// ---------------- Winograd F(4,3) output transform; fp32 out and split emit optional
__global__ void wino_otrans(const float* __restrict__ Mm, const float* __restrict__ bias,
                            float* __restrict__ out, long outB,
                            __nv_bfloat16* __restrict__ Xh, __nv_bfloat16* __restrict__ Xl) {
    int idx = blockIdx.x*blockDim.x + threadIdx.x;
    if (idx >= D96*NT_) return;
    int n  = idx % NT_;
    int oc = idx / NT_;
    float m[6][6];
    #pragma unroll
    for (int p=0;p<36;p++)
        m[p/6][p%6] = Mm[((long)p*D96 + oc)*NT_ + n];
    float t[4][6];
    #pragma unroll
    for (int c=0;c<6;c++){
        float m0=m[0][c], m1=m[1][c], m2=m[2][c], m3=m[3][c], m4=m[4][c], m5=m[5][c];
        t[0][c] = m0 + m1 + m2 + m3 + m4;
        t[1][c] = m1 - m2 + 2.f*m3 - 2.f*m4;
        t[2][c] = m1 + m2 + 4.f*m3 + 4.f*m4;
        t[3][c] = m1 - m2 + 8.f*m3 - 8.f*m4 + m5;
    }
    float bv = bias[oc];
    int b   = n / (NT_/B_);
    int loc = n % (NT_/B_);
    int ty = loc / TPD_, tx = loc % TPD_;
    long pixBase = (long)(b*D96 + oc)*HW_ + (long)(4*ty)*W_ + 4*tx;
    float* dst = out ? (out + (long)b*outB + (long)oc*HW_ + (long)(4*ty)*W_ + 4*tx) : nullptr;
    #pragma unroll
    for (int r=0;r<4;r++){
        float t0=t[r][0], t1=t[r][1], t2=t[r][2], t3=t[r][3], t4=t[r][4], t5=t[r][5];
        float y[4];
        y[0] = t0 + t1 + t2 + t3 + t4 + bv;
        y[1] = t1 - t2 + 2.f*t3 - 2.f*t4 + bv;
        y[2] = t1 + t2 + 4.f*t3 + 4.f*t4 + bv;
        y[3] = t1 - t2 + 8.f*t3 - 8.f*t4 + t5 + bv;
        if (dst){
            float* row = dst + (long)r*W_;
            row[0]=y[0]; row[1]=y[1]; row[2]=y[2]; row[3]=y[3];
        }
        if (Xh){
            long pb = pixBase + (long)r*W_;
            #pragma unroll
            for (int c=0;c<4;c++){
                __nv_bfloat16 h,l; split_bf16(y[c], h, l);
                Xh[pb+c] = h; Xl[pb+c] = l;
            }
        }
    }
}

// ---------------- GEMM / 1x1 conv (fp32, low-res use) ----------------
__global__ __launch_bounds__(256, 2)
void conv1x1_kernel(const float* __restrict__ in, long inB, int IC,
                    const float* __restrict__ w, const float* __restrict__ bias,
                    float* __restrict__ out, long outB, int OC, int npix, long wB) {
    const int tid  = threadIdx.x;
    const int lane = tid & 31;
    const int wy   = tid >> 5;
    const int p0   = blockIdx.x * 512;
    const int oc0  = blockIdx.y * 32;
    const int z    = blockIdx.z;

    __shared__ float xs[16][512];
    __shared__ float ws[16][32];

    float4 acc[4][4];
    #pragma unroll
    for (int j=0;j<4;j++)
        #pragma unroll
        for (int q=0;q<4;q++) acc[j][q] = make_float4(0.f,0.f,0.f,0.f);

    const float* inb = in + (long)z*inB;
    const float* wz  = w  + (long)z*wB;

    for (int c0=0; c0<IC; c0+=16) {
        #pragma unroll
        for (int s=0;s<8;s++){
            int li  = tid + s*256;
            int icl = li >> 7, pq = li & 127;
            int p = p0 + pq*4;
            float4 v = make_float4(0.f,0.f,0.f,0.f);
            if (p < npix)
                v = *reinterpret_cast<const float4*>(&inb[(long)(c0+icl)*npix + p]);
            *reinterpret_cast<float4*>(&xs[icl][pq*4]) = v;
        }
        #pragma unroll
        for (int s=0;s<2;s++){
            int li  = tid + s*256;
            int icl = li >> 5, ocl = li & 31;
            float v = 0.f;
            if (oc0+ocl < OC) v = wz[(long)(oc0+ocl)*IC + (c0+icl)];
            ws[icl][ocl] = v;
        }
        __syncthreads();
        #pragma unroll
        for (int ic=0; ic<16; ic++) {
            float4 xv[4];
            #pragma unroll
            for (int q=0;q<4;q++) xv[q] = *reinterpret_cast<const float4*>(&xs[ic][(q*32+lane)*4]);
            float4 wv = *reinterpret_cast<const float4*>(&ws[ic][wy*4]);
            #pragma unroll
            for (int q=0;q<4;q++){
                acc[0][q].x += xv[q].x*wv.x; acc[0][q].y += xv[q].y*wv.x; acc[0][q].z += xv[q].z*wv.x; acc[0][q].w += xv[q].w*wv.x;
                acc[1][q].x += xv[q].x*wv.y; acc[1][q].y += xv[q].y*wv.y; acc[1][q].z += xv[q].z*wv.y; acc[1][q].w += xv[q].w*wv.y;
                acc[2][q].x += xv[q].x*wv.z; acc[2][q].y += xv[q].y*wv.z; acc[2][q].z += xv[q].z*wv.z; acc[2][q].w += xv[q].w*wv.z;
                acc[3][q].x += xv[q].x*wv.w; acc[3][q].y += xv[q].y*wv.w; acc[3][q].z += xv[q].z*wv.w; acc[3][q].w += xv[q].w*wv.w;
            }
        }
        __syncthreads();
    }

    #pragma unroll
    for (int j=0;j<4;j++){
        int oc = oc0 + wy*4 + j;
        if (oc >= OC) continue;
        float bv = bias ? bias[oc] : 0.f;
        #pragma unroll
        for (int q=0;q<4;q++){
            int p = p0 + (q*32+lane)*4;
            if (p < npix){
                float4 r = acc[j][q];
                r.x += bv; r.y += bv; r.z += bv; r.w += bv;
                *reinterpret_cast<float4*>(&out[(long)z*outB + (long)oc*npix + p]) = r;
            }
        }
    }
}

// ---------------- fused 8x8 max pool + depthwise 3x3 (24x24) ----------------
__global__ __launch_bounds__(576)
void pool_dw(const float* __restrict__ in, const float* __restrict__ w,
             const float* __restrict__ bias, float* __restrict__ out) {
    int bc = blockIdx.x;
    int c  = bc % QC_;
    int b  = bc / QC_;
    int t  = threadIdx.x;
    int oh = t / WL_, ow = t % WL_;
    __shared__ float sp[PL_];
    const float* p = in + ((long)b*QC_ + c)*HW_ + (long)oh*8*W_ + ow*8;
    float m = -INFINITY;
    #pragma unroll
    for (int r=0;r<8;r++)
        #pragma unroll
        for (int cc=0;cc<8;cc++)
            m = fmaxf(m, p[r*W_ + cc]);
    sp[t] = m;
    __syncthreads();
    const float* wc = w + (long)c*9;
    float s = bias[c];
    #pragma unroll
    for (int dr=-1;dr<=1;dr++){
        int hh = oh+dr; if (hh<0||hh>=HL_) continue;
        #pragma unroll
        for (int dc=-1;dc<=1;dc++){
            int ww = ow+dc; if (ww<0||ww>=WL_) continue;
            s += wc[(dr+1)*3 + (dc+1)] * sp[hh*WL_ + ww];
        }
    }
    out[((long)b*QC_ + c)*PL_ + t] = s;
}

// ---------------- fused rownorm + attn: one block per (b,h) ----------------
__global__ __launch_bounds__(256)
void attn_fused(const float* __restrict__ dw, const float* __restrict__ temp,
                float* __restrict__ attn) {
    int blk = blockIdx.x;
    int b = blk / HEADS, h = blk % HEADS;
    int tid = threadIdx.x, warp = tid >> 5, lane = tid & 31;
    __shared__ float sinv[96];
    for (int row = warp; row < 96; row += 8){
        const float* p = dw + ((long)b*QC_ + (row < 48 ? h*C48 + row : D96 + h*C48 + (row-48)))*PL_;
        float s = 0.f;
        for (int n = lane; n < PL_; n += 32){ float v = p[n]; s += v*v; }
        #pragma unroll
        for (int o=16;o>0;o>>=1) s += __shfl_xor_sync(0xffffffffu, s, o);
        if (lane == 0) sinv[row] = 1.f / fmaxf(sqrtf(s), 1e-12f);
    }
    __syncthreads();
    float tmp = temp[h];
    for (int idx = tid; idx < C48*C48; idx += 256){
        int i2 = idx / C48, j = idx % C48;
        const float* q = dw + ((long)b*QC_ +        h*C48 + i2)*PL_;
        const float* k = dw + ((long)b*QC_ + D96 + h*C48 + j )*PL_;
        float s = 0.f;
        for (int n=0;n<PL_;n++) s += q[n]*k[n];
        attn[((long)(b*HEADS+h)*C48 + i2)*C48 + j] = s * sinv[i2] * sinv[48+j] * tmp;
    }
}

// ---------------- top-k threshold softmaxes, combined ----------------
__global__ void topk_combine(const float* __restrict__ attn, const float* __restrict__ aw,
                             float* __restrict__ acomb) {
    int r = threadIdx.x;
    if (r >= B_*HEADS*C48) return;
    const float* row = attn + (long)r*C48;
    float a[C48], srt[C48];
    for (int j=0;j<C48;j++){ a[j]=row[j]; srt[j]=a[j]; }
    for (int x=1;x<C48;x++){
        float key = srt[x]; int j = x-1;
        while (j>=0 && srt[j]<key){ srt[j+1]=srt[j]; j--; }
        srt[j+1]=key;
    }
    const int kks[4] = {24,32,36,38};
    float m = srt[0];
    float th[4], sm[4];
    #pragma unroll
    for (int l=0;l<4;l++){
        th[l] = srt[kks[l]-1];
        float s = 0.f;
        for (int j=0;j<C48;j++) if (a[j] >= th[l]) s += expf(a[j]-m);
        sm[l] = s;
    }
    float w0=aw[0], w1=aw[1], w2=aw[2], w3=aw[3];
    for (int j=0;j<C48;j++){
        float e = expf(a[j]-m);
        float o = 0.f;
        if (a[j] >= th[0]) o += w0*e/sm[0];
        if (a[j] >= th[1]) o += w1*e/sm[1];
        if (a[j] >= th[2]) o += w2*e/sm[2];
        if (a[j] >= th[3]) o += w3*e/sm[3];
        acomb[(long)r*C48 + j] = o;
    }
}

// ---------------- out = gelu(Acomb @ v) ----------------
__global__ void av_gelu(const float* __restrict__ acomb, const float* __restrict__ dw,
                        float* __restrict__ outlow) {
    int idx = blockIdx.x*blockDim.x + threadIdx.x;
    if (idx >= B_*HEADS*C48*PL_) return;
    int n = idx % PL_;
    int c = (idx / PL_) % C48;
    int h = (idx / (PL_*C48)) % HEADS;
    int b =  idx / (PL_*C48*HEADS);
    const float* arow = acomb + (((long)(b*HEADS+h))*C48 + c)*C48;
    const float* v = dw + ((long)b*QC_ + 2*D96 + h*C48)*PL_;
    float s = 0.f;
    #pragma unroll 4
    for (int d=0;d<C48;d++) s += arow[d] * v[(long)d*PL_ + n];
    float g = 0.5f * s * (1.f + erff(s * 0.70710678118654752440f));
    outlow[((long)b*D96 + h*C48 + c)*PL_ + n] = g;
}

// ---------------- BN partials / finals ----------------
__global__ void bn_partial1(const float* __restrict__ src, float (*part)[16][2]) {
    int c = blockIdx.x;
    int chunk = blockIdx.y;
    const float* base = src + ((long)(chunk>>3)*C48 + c)*HW_ + (long)(chunk & 7)*(HW_/8);
    float s = 0.f, s2 = 0.f;
    for (int i = threadIdx.x; i < HW_/8; i += 256){
        float v = base[i]; s += v; s2 += v*v;
    }
    __shared__ float sh[512];
    sh[threadIdx.x] = s; sh[256+threadIdx.x] = s2; __syncthreads();
    for (int st=128; st>0; st>>=1){
        if (threadIdx.x < st){ sh[threadIdx.x]+=sh[threadIdx.x+st]; sh[256+threadIdx.x]+=sh[256+threadIdx.x+st]; }
        __syncthreads();
    }
    if (threadIdx.x == 0){ part[c][chunk][0] = sh[0]; part[c][chunk][1] = sh[256]; }
}

__global__ void bn_final1(const float (*part)[16][2], float* dst) {
    int c = threadIdx.x;
    if (c >= C48) return;
    float s = 0.f, s2 = 0.f;
    #pragma unroll
    for (int k=0;k<16;k++){ s += part[c][k][0]; s2 += part[c][k][1]; }
    float N = (float)(B_*HW_);
    float m = s/N;
    float var = s2/N - m*m;
    dst[c]       = m;
    dst[C48+c]   = rsqrtf(fmaxf(var,0.f) + 1e-5f);
}

__global__ void bn_partial2(const float* __restrict__ xk, const float* __restrict__ yq,
                            float (*part)[16][2]) {
    int c = blockIdx.x;           // 0..95 : <48 -> xk, >=48 -> yq
    int chunk = blockIdx.y;
    const float* src = (c < C48) ? xk : yq;
    int cc = c % C48;
    const float* base = src + ((long)(chunk>>3)*C48 + cc)*HW_ + (long)(chunk & 7)*(HW_/8);
    float s = 0.f, s2 = 0.f;
    for (int i = threadIdx.x; i < HW_/8; i += 256){
        float v = base[i]; s += v; s2 += v*v;
    }
    __shared__ float sh[512];
    sh[threadIdx.x] = s; sh[256+threadIdx.x] = s2; __syncthreads();
    for (int st=128; st>0; st>>=1){
        if (threadIdx.x < st){ sh[threadIdx.x]+=sh[threadIdx.x+st]; sh[256+threadIdx.x]+=sh[256+threadIdx.x+st]; }
        __syncthreads();
    }
    if (threadIdx.x == 0){ part[c][chunk][0] = sh[0]; part[c][chunk][1] = sh[256]; }
}

__global__ void bn_final2(const float (*part)[16][2], float* bnx, float* bny) {
    int c = threadIdx.x;
    if (c >= 96) return;
    float s = 0.f, s2 = 0.f;
    #pragma unroll
    for (int k=0;k<16;k++){ s += part[c][k][0]; s2 += part[c][k][1]; }
    float N = (float)(B_*HW_);
    float m = s/N;
    float var = s2/N - m*m;
    float* dst = (c < C48) ? bnx : bny;
    int cc = c % C48;
    dst[cc]     = m;
    dst[C48+cc] = rsqrtf(fmaxf(var,0.f) + 1e-5f);
}

__global__ void bn_low(const float* __restrict__ src, float* __restrict__ dst) {
    int c = blockIdx.x;
    float s = 0.f, s2 = 0.f;
    for (int i = threadIdx.x; i < B_*PL_; i += 256){
        int b = i / PL_, j = i % PL_;
        float v = src[((long)b*C48 + c)*PL_ + j];
        s += v; s2 += v*v;
    }
    __shared__ float sh[512];
    sh[threadIdx.x]=s; sh[256+threadIdx.x]=s2; __syncthreads();
    for (int st=128; st>0; st>>=1){
        if (threadIdx.x < st){ sh[threadIdx.x]+=sh[threadIdx.x+st]; sh[256+threadIdx.x]+=sh[256+threadIdx.x+st]; }
        __syncthreads();
    }
    if (threadIdx.x == 0){
        float N = (float)(B_*PL_);
        float m = sh[0]/N;
        float var = sh[256]/N - m*m;
        dst[c]     = m;
        dst[C48+c] = rsqrtf(fmaxf(var,0.f) + 1e-5f);
    }
}

// ---------------- EAF blend (both full-res) ----------------
__global__ void eaf_blend(const float* __restrict__ x, long xB,
                          const float* __restrict__ y, long yB,
                          const float* __restrict__ xk, const float* __restrict__ yq,
                          const float* __restrict__ bnx, const float* __restrict__ bny,
                          float* __restrict__ out, long outB) {
    int p = blockIdx.x*blockDim.x + threadIdx.x;
    int b = blockIdx.y;
    if (p >= HW_) return;
    long base = (long)b*C48*HW_ + p;
    float s = 0.f;
    for (int c=0;c<C48;c++){
        float a  = (xk[base + (long)c*HW_] - bnx[c]) * bnx[C48+c];
        float bb = (yq[base + (long)c*HW_] - bny[c]) * bny[C48+c];
        s += a*bb;
    }
    float sim = 1.f/(1.f + expf(-s));
    for (int c=0;c<D96;c++){
        float xv = x[(long)b*xB + (long)c*HW_ + p];
        float yv = y[(long)b*yB + (long)c*HW_ + p];
        out[(long)b*outB + (long)c*HW_ + p] = sim*xv + (1.f-sim)*yv;
    }
}

// ---------------- EAF blend HF variant: x/xk low res; emits split copy -------------
__global__ void eaf_blend_hf(const float* __restrict__ xlow,
                             const float* __restrict__ y, long yB,
                             const float* __restrict__ xklow,
                             const float* __restrict__ yq,
                             const float* __restrict__ bnx, const float* __restrict__ bny,
                             float* __restrict__ out, long outB,
                             __nv_bfloat16* __restrict__ Xh, __nv_bfloat16* __restrict__ Xl) {
    int p = blockIdx.x*blockDim.x + threadIdx.x;
    int b = blockIdx.y;
    if (p >= HW_) return;
    int h = p / W_, w = p % W_;
    int lp = (h>>3)*WL_ + (w>>3);
    long basey = (long)b*C48*HW_ + p;
    float s = 0.f;
    for (int c=0;c<C48;c++){
        float a  = (xklow[((long)b*C48 + c)*PL_ + lp] - bnx[c]) * bnx[C48+c];
        float bb = (yq[basey + (long)c*HW_] - bny[c]) * bny[C48+c];
        s += a*bb;
    }
    float sim = 1.f/(1.f + expf(-s));
    for (int c=0;c<D96;c++){
        float xv = xlow[((long)b*D96 + c)*PL_ + lp];
        float yv = y[(long)b*yB + (long)c*HW_ + p];
        float o  = sim*xv + (1.f-sim)*yv;
        out[(long)b*outB + (long)c*HW_ + p] = o;
        __nv_bfloat16 hh,ll; split_bf16(o, hh, ll);
        long xi = ((long)b*D96 + c)*HW_ + p;
        Xh[xi] = hh; Xl[xi] = ll;
    }
}

// ---------------- copy input into feats slot 0 ----------------
__global__ void copy_slot0(const float* __restrict__ x, float* __restrict__ feats) {
    long idx = (long)blockIdx.x*blockDim.x + threadIdx.x;
    if (idx >= (long)B_*D96*HW_) return;
    long per = (long)D96*HW_;
    int b = idx / per;
    long r = idx % per;
    feats[(long)b*QC_*HW_ + r] = x[idx];
}

// ---------------- convert fp32 activations -> split bf16 ----------------
__global__ void convert_x(const float* __restrict__ in, long inB,
                          __nv_bfloat16* __restrict__ Xh, __nv_bfloat16* __restrict__ Xl) {
    long idx = (long)blockIdx.x*blockDim.x + threadIdx.x;
    if (idx >= (long)B_*D96*HW_) return;
    long per = (long)D96*HW_;
    int z = (int)(idx / per);
    long r = idx - (long)z*per;
    float v = in[(long)z*inB + r];
    __nv_bfloat16 h,l; split_bf16(v, h, l);
    Xh[idx] = h; Xl[idx] = l;
}

// ---------------- orchestration (single stream) ----------------
extern "C" void kernel_launch(void* const* d_in, const int* in_sizes, int n_in,
                              void* d_out, int out_size) {
    const float* x_in   = (const float*)d_in[0];
    const float* hf     = (const float*)d_in[1];
    const float* lf     = (const float*)d_in[2];
    const float* mkw_w  = (const float*)d_in[3];
    const float* mkw_b  = (const float*)d_in[4];
    const float* mkw_wc = (const float*)d_in[5];
    const float* mkw_bc = (const float*)d_in[6];
    const float* mkw_wh = (const float*)d_in[7];
    const float* mkw_bh = (const float*)d_in[8];
    const float* mkw_wv = (const float*)d_in[9];
    const float* mkw_bv = (const float*)d_in[10];
    const float* mkw_wa = (const float*)d_in[11];
    const float* mkw_ba = (const float*)d_in[12];
    const float* mkw_s  = (const float*)d_in[13];
    const float* dt_temp= (const float*)d_in[14];
    const float* dt_wqkv= (const float*)d_in[15];
    const float* dt_bqkv= (const float*)d_in[16];
    const float* dt_wdw = (const float*)d_in[17];
    const float* dt_bdw = (const float*)d_in[18];
    const float* dt_wprj= (const float*)d_in[19];
    const float* dt_bprj= (const float*)d_in[20];
    const float* dt_aw  = (const float*)d_in[21];
    const float* eh_wx  = (const float*)d_in[22];
    const float* eh_wy  = (const float*)d_in[23];
    const float* el_wx  = (const float*)d_in[24];
    const float* el_wy  = (const float*)d_in[25];
    const float* cab_w  = (const float*)d_in[26];
    const float* cab_b  = (const float*)d_in[27];
    float* out = (float*)d_out;

    float *feats, *qkvfull, *weff, *beff, *dw, *attn, *acomb,
          *low1, *low2, *xk, *yq, *bnx, *bny, *M;
    __nv_bfloat16 *Uh, *Ul, *UCh, *UCl, *Vh, *Vl, *Xh, *Xl, *HFh, *HFl, *LFh, *LFl, *WBh, *WBl;
    float (*bnpart2)[16][2];
    cudaGetSymbolAddress((void**)&feats,   g_feats);
    cudaGetSymbolAddress((void**)&qkvfull, g_qkvfull);
    cudaGetSymbolAddress((void**)&weff,    g_weff);
    cudaGetSymbolAddress((void**)&beff,    g_beff);
    cudaGetSymbolAddress((void**)&dw,      g_dw);
    cudaGetSymbolAddress((void**)&attn,    g_attn);
    cudaGetSymbolAddress((void**)&acomb,   g_acomb);
    cudaGetSymbolAddress((void**)&low1,    g_low1);
    cudaGetSymbolAddress((void**)&low2,    g_low2);
    cudaGetSymbolAddress((void**)&xk,      g_xk);
    cudaGetSymbolAddress((void**)&yq,      g_yq);
    cudaGetSymbolAddress((void**)&bnx,     g_bnx);
    cudaGetSymbolAddress((void**)&bny,     g_bny);
    cudaGetSymbolAddress((void**)&bnpart2, g_bnpart2);
    cudaGetSymbolAddress((void**)&Uh,      g_Uh);
    cudaGetSymbolAddress((void**)&Ul,      g_Ul);
    cudaGetSymbolAddress((void**)&UCh,     g_UCh);
    cudaGetSymbolAddress((void**)&UCl,     g_UCl);
    cudaGetSymbolAddress((void**)&Vh,      g_Vh);
    cudaGetSymbolAddress((void**)&Vl,      g_Vl);
    cudaGetSymbolAddress((void**)&M,       g_M);
    cudaGetSymbolAddress((void**)&Xh,      g_Xh);
    cudaGetSymbolAddress((void**)&Xl,      g_Xl);
    cudaGetSymbolAddress((void**)&HFh,     g_HFh);
    cudaGetSymbolAddress((void**)&HFl,     g_HFl);
    cudaGetSymbolAddress((void**)&LFh,     g_LFh);
    cudaGetSymbolAddress((void**)&LFl,     g_LFl);
    cudaGetSymbolAddress((void**)&WBh,     g_WBh);
    cudaGetSymbolAddress((void**)&WBl,     g_WBl);

    const long fB   = (long)QC_*HW_;
    const long dB   = (long)D96*HW_;
    const long cB   = (long)C48*HW_;
    const long lowB = (long)D96*PL_;
    const long lowC = (long)C48*PL_;
    const long nConv = (long)B_*D96*HW_;
    const unsigned convGrid = (unsigned)((nConv+255)/256);

    // prologue: hoisted conversions / transforms
    copy_slot0<<<convGrid, 256>>>(x_in, feats);
    convert_x<<<convGrid, 256>>>(hf, dB, HFh, HFl);
    convert_x<<<convGrid, 256>>>(lf, dB, LFh, LFl);
    convert_all_w<<<(WB_TOT+255)/256, 256>>>(dt_wqkv, eh_wy, el_wx, el_wy, WBh, WBl);
    wino_wtrans<<<(D96*QC_+255)/256, 256>>>(cab_w, D96, QC_, UCh, UCl);

    for (int i=0;i<2;i++){
        const float* s4 = mkw_s + i*4;
        build_weight<<<(D96*D96+255)/256, 256>>>(mkw_w + (size_t)i*D96*D96*9,
                                                 mkw_wc + (size_t)i*D96*D96*9,
                                                 mkw_wh + (size_t)i*D96*D96*3,
                                                 mkw_wv + (size_t)i*D96*D96*3,
                                                 mkw_wa + (size_t)i*D96*D96*9,
                                                 s4, weff,
                                                 mkw_b + i*D96, mkw_bc + i*D96,
                                                 mkw_bh + i*D96, mkw_bv + i*D96,
                                                 mkw_ba + i*D96, beff);

        // ---- MKW conv3x3: Winograd F(4,3) + TC GEMM; split emit only (fp32 dead) ----
        const float* xcur = feats + (size_t)i*D96*HW_;
        wino_wtrans<<<(D96*D96+255)/256, 256>>>(weff, D96, D96, Uh, Ul);
        wino_itrans<<<dim3(NT_/256, D96), 256>>>(xcur, fB, D96, Vh, Vl);
        wino_gemm<<<dim3(NT_/128, 1, 36), 256>>>(Uh, Ul, Vh, Vl, M, D96, NT_);
        wino_otrans<<<(D96*NT_+255)/256, 256>>>(M, beff, nullptr, 0L, Xh, Xl);

        // ---- qkv 1x1 (full res) via TC GEMM (X split from otrans) ----
        gemm1x1_tc<<<dim3(HW_/128, 3, B_), 256>>>(WBh + WB_QKV + (size_t)i*QC_*D96,
            WBl + WB_QKV + (size_t)i*QC_*D96, Xh, Xl,
            dt_bqkv + i*QC_, qkvfull, D96, QC_, HW_, fB);

        pool_dw<<<B_*QC_, 576>>>(qkvfull, dt_wdw + (size_t)i*QC_*9, dt_bdw + i*QC_, dw);
        attn_fused<<<B_*HEADS, 256>>>(dw, dt_temp + i*HEADS, attn);
        topk_combine<<<1, 192>>>(attn, dt_aw + i*4, acomb);
        av_gelu<<<(B_*HEADS*C48*PL_+255)/256, 256>>>(acomb, dw, low1);

        // proj 1x1 at low res (fp32)
        conv1x1_kernel<<<dim3((PL_+511)/512, D96/32, B_), 256>>>(
            low1, lowB, D96, dt_wprj + (size_t)i*D96*D96, dt_bprj + i*D96,
            low2, lowB, D96, PL_, 0L);

        float* slot_out = feats + (size_t)(i+1)*D96*HW_;

        // ---- EAF_HF (xk at low res fp32; yq full res TC); blend emits split ----
        conv1x1_kernel<<<dim3((PL_+511)/512, (C48+31)/32, B_), 256>>>(
            low2, lowB, D96, eh_wx + (size_t)i*C48*D96, nullptr, xk, lowC, C48, PL_, 0L);
        gemm1x1_tc<<<dim3(HW_/128, 1, B_), 256>>>(WBh + WB_EHY + (size_t)i*C48*D96,
            WBl + WB_EHY + (size_t)i*C48*D96, HFh, HFl,
            nullptr, yq, D96, C48, HW_, cB);
        bn_low<<<C48, 256>>>(xk, bnx);
        bn_partial1<<<dim3(C48,16), 256>>>(yq, bnpart2);
        bn_final1<<<1, C48>>>(bnpart2, bny);
        eaf_blend_hf<<<dim3(HW_/256, B_), 256>>>(low2, hf, dB, xk, yq, bnx, bny,
                                                 slot_out, fB, Xh, Xl);

        // ---- EAF_LF (both full res, TC; X split from blend_hf) ----
        gemm1x1_tc<<<dim3(HW_/128, 1, B_), 256>>>(WBh + WB_ELX + (size_t)i*C48*D96,
            WBl + WB_ELX + (size_t)i*C48*D96, Xh, Xl,
            nullptr, xk, D96, C48, HW_, cB);
        gemm1x1_tc<<<dim3(HW_/128, 1, B_), 256>>>(WBh + WB_ELY + (size_t)i*C48*D96,
            WBl + WB_ELY + (size_t)i*C48*D96, LFh, LFl,
            nullptr, yq, D96, C48, HW_, cB);
        bn_partial2<<<dim3(96,16), 256>>>(xk, yq, bnpart2);
        bn_final2<<<1, 96>>>(bnpart2, bnx, bny);
        eaf_blend<<<dim3(HW_/256, B_), 256>>>(slot_out, fB, lf, dB, xk, yq, bnx, bny,
                                              slot_out, fB);
    }

    // ---- CAB conv3x3 (IC=288) via Winograd + TC GEMM (U hoisted) ----
    wino_itrans<<<dim3(NT_/256, QC_), 256>>>(feats, fB, QC_, Vh, Vl);
    wino_gemm<<<dim3(NT_/128, 1, 36), 256>>>(UCh, UCl, Vh, Vl, M, QC_, NT_);
    wino_otrans<<<(D96*NT_+255)/256, 256>>>(M, cab_b, out, dB, nullptr, nullptr);
}

// round 16
// speedup vs baseline: 2.4283x; 1.9391x over previous
#include <cuda_runtime.h>
#include <cuda_bf16.h>
#include <cstdint>
#include <math.h>

// ---------------- problem constants ----------------
#define B_    2
#define D96   96
#define H_    192
#define W_    192
#define HW_   (H_*W_)        // 36864
#define HEADS 2
#define C48   48
#define HL_   24
#define WL_   24
#define PL_   (HL_*WL_)      // 576
#define QC_   288            // 3*D
#define TPD_  48             // winograd F(4,3) tiles per spatial dim
#define NT_   4608           // 48*48*2 tiles

// weight-bank offsets (elements) in g_WBh/g_WBl
#define WB_QKV   0           // [L][288][96]  -> 2*27648
#define WB_EHY   55296       // [L][48][96]   -> 2*4608
#define WB_ELX   64512
#define WB_ELY   73728
#define WB_TOT   82944

// ---------------- scratch (static, no runtime alloc) ----------------
__device__ float g_feats  [(size_t)B_*QC_*HW_];
__device__ float g_qkvfull[(size_t)B_*QC_*HW_];
__device__ float g_weff   [D96*D96*9];
__device__ float g_beff   [D96];
__device__ float g_dw     [(size_t)B_*QC_*PL_];
__device__ float g_attn   [B_*HEADS*C48*C48];
__device__ float g_acomb  [B_*HEADS*C48*C48];
__device__ float g_low1   [(size_t)B_*D96*PL_];
__device__ float g_low2   [(size_t)B_*D96*PL_];
__device__ float g_xk     [(size_t)B_*C48*HW_];
__device__ float g_yq     [(size_t)B_*C48*HW_];
__device__ float g_bnx    [2*C48];
__device__ float g_bny    [2*C48];
__device__ float g_bnpart2[96][16][2];
// winograd F(4x4,3x3) scratch — split bf16 operands, fp32 M
__device__ __nv_bfloat16 g_Uh [(size_t)36*D96*D96];   // MKW weights
__device__ __nv_bfloat16 g_Ul [(size_t)36*D96*D96];
__device__ __nv_bfloat16 g_UCh[(size_t)36*D96*QC_];   // CAB weights (hoisted)
__device__ __nv_bfloat16 g_UCl[(size_t)36*D96*QC_];
__device__ __nv_bfloat16 g_Vh [(size_t)36*QC_*NT_];
__device__ __nv_bfloat16 g_Vl [(size_t)36*QC_*NT_];
__device__ float         g_M  [(size_t)36*D96*NT_];
// split-bf16 activations / weights for TC 1x1 convs
__device__ __nv_bfloat16 g_Xh [(size_t)B_*D96*HW_];
__device__ __nv_bfloat16 g_Xl [(size_t)B_*D96*HW_];
__device__ __nv_bfloat16 g_HFh[(size_t)B_*D96*HW_];
__device__ __nv_bfloat16 g_HFl[(size_t)B_*D96*HW_];
__device__ __nv_bfloat16 g_LFh[(size_t)B_*D96*HW_];
__device__ __nv_bfloat16 g_LFl[(size_t)B_*D96*HW_];
__device__ __nv_bfloat16 g_WBh[WB_TOT];
__device__ __nv_bfloat16 g_WBl[WB_TOT];

__device__ __forceinline__ void split_bf16(float x, __nv_bfloat16& h, __nv_bfloat16& l){
    h = __float2bfloat16_rn(x);
    l = __float2bfloat16_rn(x - __bfloat162float(h));
}

// ---------------- MKW effective weight (+bias folded in) ----------------
__global__ void build_weight(const float* __restrict__ w,  const float* __restrict__ wc,
                             const float* __restrict__ wh, const float* __restrict__ wv,
                             const float* __restrict__ wa, const float* __restrict__ s4,
                             float* __restrict__ weff,
                             const float* __restrict__ b,  const float* __restrict__ bc,
                             const float* __restrict__ bh, const float* __restrict__ bv,
                             const float* __restrict__ ba, float* __restrict__ beff) {
    int idx = blockIdx.x * blockDim.x + threadIdx.x;   // oc*96+ic
    const float s0=s4[0], s1=s4[1], s2=s4[2], s3=s4[3];
    if (blockIdx.x == 0 && threadIdx.x < D96){
        int c = threadIdx.x;
        beff[c] = b[c] + s0*bc[c] + s1*bh[c] + s2*bv[c] + s3*ba[c];
    }
    if (idx >= D96*D96) return;
    float wcl[9], wal[9];
    float csum = 0.f;
    #pragma unroll
    for (int t=0;t<9;t++){ wcl[t]=wc[(size_t)idx*9+t]; csum+=wcl[t]; }
    #pragma unroll
    for (int t=0;t<9;t++){ wal[t]=wa[(size_t)idx*9+t]; }
    const int perm[9] = {3,0,1,6,4,2,7,8,5};
    float wh0=wh[(size_t)idx*3+0], wh1=wh[(size_t)idx*3+1], wh2=wh[(size_t)idx*3+2];
    float wv0=wv[(size_t)idx*3+0], wv1=wv[(size_t)idx*3+1], wv2=wv[(size_t)idx*3+2];
    #pragma unroll
    for (int t=0;t<9;t++){
        float wcd = wcl[t] - (t==4 ? csum : 0.f);
        float whd = 0.f;
        if (t==0) whd =  wh0; else if (t==3) whd =  wh1; else if (t==6) whd =  wh2;
        else if (t==2) whd = -wh0; else if (t==5) whd = -wh1; else if (t==8) whd = -wh2;
        float wvd = 0.f;
        if (t<3) wvd = (t==0?wv0:(t==1?wv1:wv2));
        else if (t>=6) wvd = -(t==6?wv0:(t==7?wv1:wv2));
        float wad = wal[t] - wal[perm[t]];
        weff[(size_t)idx*9+t] = w[(size_t)idx*9+t] + s0*wcd + s1*whd + s2*wvd + s3*wad;
    }
}

// ---------------- hoisted: convert ALL 1x1 weights to split bf16 -------------------
__global__ void convert_all_w(const float* __restrict__ qkv, const float* __restrict__ ehy,
                              const float* __restrict__ elx, const float* __restrict__ ely,
                              __nv_bfloat16* __restrict__ Wh, __nv_bfloat16* __restrict__ Wl){
    int idx = blockIdx.x*blockDim.x + threadIdx.x;
    if (idx >= WB_TOT) return;
    float v;
    if (idx < WB_EHY)      v = qkv[idx];
    else if (idx < WB_ELX) v = ehy[idx - WB_EHY];
    else if (idx < WB_ELY) v = elx[idx - WB_ELX];
    else                   v = ely[idx - WB_ELY];
    __nv_bfloat16 h,l; split_bf16(v, h, l);
    Wh[idx] = h; Wl[idx] = l;
}

// ---------------- Winograd F(4x4,3x3): weight transform U = G g G^T (split bf16) ----
__global__ void wino_wtrans(const float* __restrict__ w, int OC, int IC,
                            __nv_bfloat16* __restrict__ Uh, __nv_bfloat16* __restrict__ Ul) {
    int idx = blockIdx.x*blockDim.x + threadIdx.x;   // oc*IC + ic
    if (idx >= OC*IC) return;
    float g[9];
    #pragma unroll
    for (int t=0;t<9;t++) g[t] = w[(size_t)idx*9 + t];
    const float i6 = 1.f/6.f, i12 = 1.f/12.f, i24 = 1.f/24.f;
    float Gg[6][3];
    #pragma unroll
    for (int c=0;c<3;c++){
        float g0 = g[c], g1 = g[3+c], g2 = g[6+c];
        Gg[0][c] = 0.25f*g0;
        Gg[1][c] = -i6*(g0 + g1 + g2);
        Gg[2][c] =  i6*(-g0 + g1 - g2);
        Gg[3][c] =  i24*g0 + i12*g1 + i6*g2;
        Gg[4][c] =  i24*g0 - i12*g1 + i6*g2;
        Gg[5][c] =  g2;
    }
    long OI = (long)OC*IC;
    #pragma unroll
    for (int r=0;r<6;r++){
        float a = Gg[r][0], b = Gg[r][1], c2 = Gg[r][2];
        float u[6];
        u[0] = 0.25f*a;
        u[1] = -i6*(a + b + c2);
        u[2] =  i6*(-a + b - c2);
        u[3] =  i24*a + i12*b + i6*c2;
        u[4] =  i24*a - i12*b + i6*c2;
        u[5] =  c2;
        #pragma unroll
        for (int q=0;q<6;q++){
            __nv_bfloat16 h,l; split_bf16(u[q], h, l);
            Uh[(long)(r*6+q)*OI + idx] = h;
            Ul[(long)(r*6+q)*OI + idx] = l;
        }
    }
}

// ---------------- Winograd F(4,3) input transform V = B^T d B (split bf16) ----------
__global__ void wino_itrans(const float* __restrict__ in, long inB, int IC,
                            __nv_bfloat16* __restrict__ Vh, __nv_bfloat16* __restrict__ Vl) {
    int n  = blockIdx.x*blockDim.x + threadIdx.x;   // 0..NT_-1
    int ic = blockIdx.y;
    int b   = n / (NT_/B_);
    int loc = n % (NT_/B_);
    int ty = loc / TPD_, tx = loc % TPD_;
    const float* src = in + (long)b*inB + (long)ic*HW_;
    int h0 = 4*ty - 1, w0 = 4*tx - 1;
    float d[6][6];
    #pragma unroll
    for (int r=0;r<6;r++){
        int hh = h0 + r;
        bool hok = (hh >= 0 && hh < H_);
        #pragma unroll
        for (int c=0;c<6;c++){
            int ww = w0 + c;
            d[r][c] = (hok && ww >= 0 && ww < W_) ? src[hh*W_ + ww] : 0.f;
        }
    }
    float t[6][6];
    #pragma unroll
    for (int c=0;c<6;c++){
        float d0=d[0][c], d1=d[1][c], d2=d[2][c], d3=d[3][c], d4=d[4][c], d5=d[5][c];
        t[0][c] =  4.f*d0 - 5.f*d2 + d4;
        t[1][c] = -4.f*d1 - 4.f*d2 + d3 + d4;
        t[2][c] =  4.f*d1 - 4.f*d2 - d3 + d4;
        t[3][c] = -2.f*d1 -      d2 + 2.f*d3 + d4;
        t[4][c] =  2.f*d1 -      d2 - 2.f*d3 + d4;
        t[5][c] =  4.f*d1 - 5.f*d3 + d5;
    }
    long stride = (long)IC*NT_;
    long base = (long)ic*NT_ + n;
    #pragma unroll
    for (int r=0;r<6;r++){
        float t0=t[r][0], t1=t[r][1], t2=t[r][2], t3=t[r][3], t4=t[r][4], t5=t[r][5];
        float v[6];
        v[0] =  4.f*t0 - 5.f*t2 + t4;
        v[1] = -4.f*t1 - 4.f*t2 + t3 + t4;
        v[2] =  4.f*t1 - 4.f*t2 - t3 + t4;
        v[3] = -2.f*t1 -      t2 + 2.f*t3 + t4;
        v[4] =  2.f*t1 -      t2 - 2.f*t3 + t4;
        v[5] =  4.f*t1 - 5.f*t3 + t5;
        #pragma unroll
        for (int q=0;q<6;q++){
            __nv_bfloat16 h,l; split_bf16(v[q], h, l);
            Vh[(long)(r*6+q)*stride + base] = h;
            Vl[(long)(r*6+q)*stride + base] = l;
        }
    }
}

// ---------------- split-bf16 TC GEMM, fused phases + double buffer -----------------
__global__ __launch_bounds__(256)
void wino_gemm(const __nv_bfloat16* __restrict__ Uh, const __nv_bfloat16* __restrict__ Ul,
               const __nv_bfloat16* __restrict__ Vh, const __nv_bfloat16* __restrict__ Vl,
               float* __restrict__ Mo, int IC, int NT) {
    const int p    = blockIdx.z;
    const int nBlk = blockIdx.x * 128;
    const int tid  = threadIdx.x;
    const int warp = tid >> 5, lane = tid & 31;
    const int mOff = (warp >> 2) * 48;
    const int nOff = (warp & 3) * 32;
    const int lq   = lane >> 2;
    const int lr   = lane & 3;

    __shared__ uint32_t Ah[2][96*9], Al[2][96*9];
    __shared__ uint32_t Bh[2][128*9], Bl[2][128*9];

    float acc[3][4][4];
    #pragma unroll
    for (int mt=0;mt<3;mt++)
        #pragma unroll
        for (int nt=0;nt<4;nt++)
            #pragma unroll
            for (int q=0;q<4;q++) acc[mt][nt][q]=0.f;

    const long Uplane = (long)p*96*IC;
    const long Vplane = (long)p*IC*NT;
    const int nIter = IC/16;

    #pragma unroll
    for (int s=0;s<3;s++){
        int e = tid + s*256;
        int m = e >> 3, kp = e & 7;
        long off = Uplane + (long)m*IC + kp*2;
        Ah[0][m*9+kp] = *reinterpret_cast<const uint32_t*>(Uh + off);
        Al[0][m*9+kp] = *reinterpret_cast<const uint32_t*>(Ul + off);
    }
    #pragma unroll
    for (int s=0;s<2;s++){
        int e = tid + s*256;
        int kp = e >> 6, j = e & 63;
        long off = Vplane + (long)(2*kp)*NT + nBlk + 2*j;
        uint32_t h0 = *reinterpret_cast<const uint32_t*>(Vh + off);
        uint32_t h1 = *reinterpret_cast<const uint32_t*>(Vh + off + NT);
        Bh[0][(2*j  )*9 + kp] = __byte_perm(h0, h1, 0x5410);
        Bh[0][(2*j+1)*9 + kp] = __byte_perm(h0, h1, 0x7632);
        uint32_t l0 = *reinterpret_cast<const uint32_t*>(Vl + off);
        uint32_t l1 = *reinterpret_cast<const uint32_t*>(Vl + off + NT);
        Bl[0][(2*j  )*9 + kp] = __byte_perm(l0, l1, 0x5410);
        Bl[0][(2*j+1)*9 + kp] = __byte_perm(l0, l1, 0x7632);
    }
    __syncthreads();

    for (int it=0; it<nIter; it++){
        const int cur = it & 1, nxt = cur ^ 1;
        const bool more = (it+1 < nIter);

        uint32_t sa[6], sb[8];
        if (more){
            int icb = (it+1)*16;
            #pragma unroll
            for (int s=0;s<3;s++){
                int e = tid + s*256;
                int m = e >> 3, kp = e & 7;
                long off = Uplane + (long)m*IC + icb + kp*2;
                sa[2*s  ] = *reinterpret_cast<const uint32_t*>(Uh + off);
                sa[2*s+1] = *reinterpret_cast<const uint32_t*>(Ul + off);
            }
            #pragma unroll
            for (int s=0;s<2;s++){
                int e = tid + s*256;
                int kp = e >> 6, j = e & 63;
                long off = Vplane + (long)(icb + 2*kp)*NT + nBlk + 2*j;
                sb[4*s  ] = *reinterpret_cast<const uint32_t*>(Vh + off);
                sb[4*s+1] = *reinterpret_cast<const uint32_t*>(Vh + off + NT);
                sb[4*s+2] = *reinterpret_cast<const uint32_t*>(Vl + off);
                sb[4*s+3] = *reinterpret_cast<const uint32_t*>(Vl + off + NT);
            }
        }

        #pragma unroll
        for (int ph=0; ph<3; ph++){
            const uint32_t* As = (ph < 2) ? Ah[cur] : Al[cur];
            const uint32_t* Bs = (ph == 1) ? Bl[cur] : Bh[cur];
            uint32_t a[3][4], b[4][2];
            #pragma unroll
            for (int mt=0;mt<3;mt++){
                int m0 = mOff + mt*16;
                a[mt][0] = As[(m0     + lq)*9 +     lr];
                a[mt][1] = As[(m0 + 8 + lq)*9 +     lr];
                a[mt][2] = As[(m0     + lq)*9 + 4 + lr];
                a[mt][3] = As[(m0 + 8 + lq)*9 + 4 + lr];
            }
            #pragma unroll
            for (int nt=0;nt<4;nt++){
                int n0 = nOff + nt*8;
                b[nt][0] = Bs[(n0 + lq)*9 +     lr];
                b[nt][1] = Bs[(n0 + lq)*9 + 4 + lr];
            }
            #pragma unroll
            for (int mt=0;mt<3;mt++)
                #pragma unroll
                for (int nt=0;nt<4;nt++){
                    asm volatile(
                        "mma.sync.aligned.m16n8k16.row.col.f32.bf16.bf16.f32 "
                        "{%0,%1,%2,%3}, {%4,%5,%6,%7}, {%8,%9}, {%0,%1,%2,%3};"
                        : "+f"(acc[mt][nt][0]), "+f"(acc[mt][nt][1]),
                          "+f"(acc[mt][nt][2]), "+f"(acc[mt][nt][3])
                        : "r"(a[mt][0]), "r"(a[mt][1]), "r"(a[mt][2]), "r"(a[mt][3]),
                          "r"(b[nt][0]), "r"(b[nt][1]));
                }
        }

        if (more){
            #pragma unroll
            for (int s=0;s<3;s++){
                int e = tid + s*256;
                int m = e >> 3, kp = e & 7;
                Ah[nxt][m*9+kp] = sa[2*s];
                Al[nxt][m*9+kp] = sa[2*s+1];
            }
            #pragma unroll
            for (int s=0;s<2;s++){
                int e = tid + s*256;
                int kp = e >> 6, j = e & 63;
                Bh[nxt][(2*j  )*9 + kp] = __byte_perm(sb[4*s], sb[4*s+1], 0x5410);
                Bh[nxt][(2*j+1)*9 + kp] = __byte_perm(sb[4*s], sb[4*s+1], 0x7632);
                Bl[nxt][(2*j  )*9 + kp] = __byte_perm(sb[4*s+2], sb[4*s+3], 0x5410);
                Bl[nxt][(2*j+1)*9 + kp] = __byte_perm(sb[4*s+2], sb[4*s+3], 0x7632);
            }
        }
        __syncthreads();
    }

    long Mbase = (long)p*96*NT;
    #pragma unroll
    for (int mt=0;mt<3;mt++){
        int r0 = mOff + mt*16 + lq;
        #pragma unroll
        for (int nt=0;nt<4;nt++){
            int c = nBlk + nOff + nt*8 + 2*lr;
            *reinterpret_cast<float2*>(&Mo[Mbase + (long)r0*NT + c]) =
                make_float2(acc[mt][nt][0], acc[mt][nt][1]);
            *reinterpret_cast<float2*>(&Mo[Mbase + (long)(r0+8)*NT + c]) =
                make_float2(acc[mt][nt][2], acc[mt][nt][3]);
        }
    }
}

// ---------------- split-bf16 TC GEMM for 1x1 convs (double buffered) ----------------
__global__ __launch_bounds__(256)
void gemm1x1_tc(const __nv_bfloat16* __restrict__ Wh, const __nv_bfloat16* __restrict__ Wl,
                const __nv_bfloat16* __restrict__ Xh, const __nv_bfloat16* __restrict__ Xl,
                const float* __restrict__ bias, float* __restrict__ out,
                int IC, int OC, int npix, long outBz) {
    const int z    = blockIdx.z;
    const int nBlk = blockIdx.x * 128;
    const int mBlk = blockIdx.y * 96;
    const int tid  = threadIdx.x;
    const int warp = tid >> 5, lane = tid & 31;
    const int mOff = (warp >> 2) * 48;
    const int nOff = (warp & 3) * 32;
    const int lq   = lane >> 2;
    const int lr   = lane & 3;

    __shared__ uint32_t Ah[2][96*9], Al[2][96*9];
    __shared__ uint32_t Bh[2][128*9], Bl[2][128*9];

    float acc[3][4][4];
    #pragma unroll
    for (int mt=0;mt<3;mt++)
        #pragma unroll
        for (int nt=0;nt<4;nt++)
            #pragma unroll
            for (int q=0;q<4;q++) acc[mt][nt][q]=0.f;

    const long Xplane = (long)z*IC*npix;
    const int nIter = IC/16;

    #pragma unroll
    for (int s=0;s<3;s++){
        int e = tid + s*256;
        int m = e >> 3, kp = e & 7;
        int gm = mBlk + m;
        uint32_t vh = 0, vl = 0;
        if (gm < OC){
            long off = (long)gm*IC + kp*2;
            vh = *reinterpret_cast<const uint32_t*>(Wh + off);
            vl = *reinterpret_cast<const uint32_t*>(Wl + off);
        }
        Ah[0][m*9+kp] = vh; Al[0][m*9+kp] = vl;
    }
    #pragma unroll
    for (int s=0;s<2;s++){
        int e = tid + s*256;
        int kp = e >> 6, j = e & 63;
        long off = Xplane + (long)(2*kp)*npix + nBlk + 2*j;
        uint32_t h0 = *reinterpret_cast<const uint32_t*>(Xh + off);
        uint32_t h1 = *reinterpret_cast<const uint32_t*>(Xh + off + npix);
        Bh[0][(2*j  )*9 + kp] = __byte_perm(h0, h1, 0x5410);
        Bh[0][(2*j+1)*9 + kp] = __byte_perm(h0, h1, 0x7632);
        uint32_t l0 = *reinterpret_cast<const uint32_t*>(Xl + off);
        uint32_t l1 = *reinterpret_cast<const uint32_t*>(Xl + off + npix);
        Bl[0][(2*j  )*9 + kp] = __byte_perm(l0, l1, 0x5410);
        Bl[0][(2*j+1)*9 + kp] = __byte_perm(l0, l1, 0x7632);
    }
    __syncthreads();

    for (int it=0; it<nIter; it++){
        const int cur = it & 1, nxt = cur ^ 1;
        const bool more = (it+1 < nIter);

        uint32_t sa[6], sb[8];
        if (more){
            int icb = (it+1)*16;
            #pragma unroll
            for (int s=0;s<3;s++){
                int e = tid + s*256;
                int m = e >> 3, kp = e & 7;
                int gm = mBlk + m;
                uint32_t vh = 0, vl = 0;
                if (gm < OC){
                    long off = (long)gm*IC + icb + kp*2;
                    vh = *reinterpret_cast<const uint32_t*>(Wh + off);
                    vl = *reinterpret_cast<const uint32_t*>(Wl + off);
                }
                sa[2*s] = vh; sa[2*s+1] = vl;
            }
            #pragma unroll
            for (int s=0;s<2;s++){
                int e = tid + s*256;
                int kp = e >> 6, j = e & 63;
                long off = Xplane + (long)(icb + 2*kp)*npix + nBlk + 2*j;
                sb[4*s  ] = *reinterpret_cast<const uint32_t*>(Xh + off);
                sb[4*s+1] = *reinterpret_cast<const uint32_t*>(Xh + off + npix);
                sb[4*s+2] = *reinterpret_cast<const uint32_t*>(Xl + off);
                sb[4*s+3] = *reinterpret_cast<const uint32_t*>(Xl + off + npix);
            }
        }

        #pragma unroll
        for (int ph=0; ph<3; ph++){
            const uint32_t* As = (ph < 2) ? Ah[cur] : Al[cur];
            const uint32_t* Bs = (ph == 1) ? Bl[cur] : Bh[cur];
            uint32_t a[3][4], b[4][2];
            #pragma unroll
            for (int mt=0;mt<3;mt++){
                int m0 = mOff + mt*16;
                a[mt][0] = As[(m0     + lq)*9 +     lr];
                a[mt][1] = As[(m0 + 8 + lq)*9 +     lr];
                a[mt][2] = As[(m0     + lq)*9 + 4 + lr];
                a[mt][3] = As[(m0 + 8 + lq)*9 + 4 + lr];
            }
            #pragma unroll
            for (int nt=0;nt<4;nt++){
                int n0 = nOff + nt*8;
                b[nt][0] = Bs[(n0 + lq)*9 +     lr];
                b[nt][1] = Bs[(n0 + lq)*9 + 4 + lr];
            }
            #pragma unroll
            for (int mt=0;mt<3;mt++)
                #pragma unroll
                for (int nt=0;nt<4;nt++){
                    asm volatile(
                        "mma.sync.aligned.m16n8k16.row.col.f32.bf16.bf16.f32 "
                        "{%0,%1,%2,%3}, {%4,%5,%6,%7}, {%8,%9}, {%0,%1,%2,%3};"
                        : "+f"(acc[mt][nt][0]), "+f"(acc[mt][nt][1]),
                          "+f"(acc[mt][nt][2]), "+f"(acc[mt][nt][3])
                        : "r"(a[mt][0]), "r"(a[mt][1]), "r"(a[mt][2]), "r"(a[mt][3]),
                          "r"(b[nt][0]), "r"(b[nt][1]));
                }
        }

        if (more){
            #pragma unroll
            for (int s=0;s<3;s++){
                int e = tid + s*256;
                int m = e >> 3, kp = e & 7;
                Ah[nxt][m*9+kp] = sa[2*s];
                Al[nxt][m*9+kp] = sa[2*s+1];
            }
            #pragma unroll
            for (int s=0;s<2;s++){
                int e = tid + s*256;
                int kp = e >> 6, j = e & 63;
                Bh[nxt][(2*j  )*9 + kp] = __byte_perm(sb[4*s], sb[4*s+1], 0x5410);
                Bh[nxt][(2*j+1)*9 + kp] = __byte_perm(sb[4*s], sb[4*s+1], 0x7632);
                Bl[nxt][(2*j  )*9 + kp] = __byte_perm(sb[4*s+2], sb[4*s+3], 0x5410);
                Bl[nxt][(2*j+1)*9 + kp] = __byte_perm(sb[4*s+2], sb[4*s+3], 0x7632);
            }
        }
        __syncthreads();
    }

    #pragma unroll
    for (int mt=0;mt<3;mt++){
        int r0 = mOff + mt*16 + lq;
        int g0 = mBlk + r0, g1 = g0 + 8;
        float bv0 = (bias && g0 < OC) ? bias[g0] : 0.f;
        float bv1 = (bias && g1 < OC) ? bias[g1] : 0.f;
        #pragma unroll
        for (int nt=0;nt<4;nt++){
            int c = nBlk + nOff + nt*8 + 2*lr;
            if (g0 < OC)
                *reinterpret_cast<float2*>(&out[(long)z*outBz + (long)g0*npix + c]) =
                    make_float2(acc[mt][nt][0] + bv0, acc[mt][nt][1] + bv0);
            if (g1 < OC)
                *reinterpret_cast<float2*>(&out[(long)z*outBz + (long)g1*npix + c]) =
                    make_float2(acc[mt][nt][2] + bv1, acc[mt][nt][3] + bv1);
        }
    }
}

// ---------------- Winograd F(4,3) output transform; fp32 out and split emit optional
__global__ void wino_otrans(const float* __restrict__ Mm, const float* __restrict__ bias,
                            float* __restrict__ out, long outB,
                            __nv_bfloat16* __restrict__ Xh, __nv_bfloat16* __restrict__ Xl) {
    int idx = blockIdx.x*blockDim.x + threadIdx.x;
    if (idx >= D96*NT_) return;
    int n  = idx % NT_;
    int oc = idx / NT_;
    float m[6][6];
    #pragma unroll
    for (int p=0;p<36;p++)
        m[p/6][p%6] = Mm[((long)p*D96 + oc)*NT_ + n];
    float t[4][6];
    #pragma unroll
    for (int c=0;c<6;c++){
        float m0=m[0][c], m1=m[1][c], m2=m[2][c], m3=m[3][c], m4=m[4][c], m5=m[5][c];
        t[0][c] = m0 + m1 + m2 + m3 + m4;
        t[1][c] = m1 - m2 + 2.f*m3 - 2.f*m4;
        t[2][c] = m1 + m2 + 4.f*m3 + 4.f*m4;
        t[3][c] = m1 - m2 + 8.f*m3 - 8.f*m4 + m5;
    }
    float bv = bias[oc];
    int b   = n / (NT_/B_);
    int loc = n % (NT_/B_);
    int ty = loc / TPD_, tx = loc % TPD_;
    long pixBase = (long)(b*D96 + oc)*HW_ + (long)(4*ty)*W_ + 4*tx;
    float* dst = out ? (out + (long)b*outB + (long)oc*HW_ + (long)(4*ty)*W_ + 4*tx) : nullptr;
    #pragma unroll
    for (int r=0;r<4;r++){
        float t0=t[r][0], t1=t[r][1], t2=t[r][2], t3=t[r][3], t4=t[r][4], t5=t[r][5];
        float y[4];
        y[0] = t0 + t1 + t2 + t3 + t4 + bv;
        y[1] = t1 - t2 + 2.f*t3 - 2.f*t4 + bv;
        y[2] = t1 + t2 + 4.f*t3 + 4.f*t4 + bv;
        y[3] = t1 - t2 + 8.f*t3 - 8.f*t4 + t5 + bv;
        if (dst){
            float* row = dst + (long)r*W_;
            row[0]=y[0]; row[1]=y[1]; row[2]=y[2]; row[3]=y[3];
        }
        if (Xh){
            long pb = pixBase + (long)r*W_;
            #pragma unroll
            for (int c=0;c<4;c++){
                __nv_bfloat16 h,l; split_bf16(y[c], h, l);
                Xh[pb+c] = h; Xl[pb+c] = l;
            }
        }
    }
}

// ---------------- GEMM / 1x1 conv (fp32, low-res use) ----------------
__global__ __launch_bounds__(256, 2)
void conv1x1_kernel(const float* __restrict__ in, long inB, int IC,
                    const float* __restrict__ w, const float* __restrict__ bias,
                    float* __restrict__ out, long outB, int OC, int npix, long wB) {
    const int tid  = threadIdx.x;
    const int lane = tid & 31;
    const int wy   = tid >> 5;
    const int p0   = blockIdx.x * 512;
    const int oc0  = blockIdx.y * 32;
    const int z    = blockIdx.z;

    __shared__ float xs[16][512];
    __shared__ float ws[16][32];

    float4 acc[4][4];
    #pragma unroll
    for (int j=0;j<4;j++)
        #pragma unroll
        for (int q=0;q<4;q++) acc[j][q] = make_float4(0.f,0.f,0.f,0.f);

    const float* inb = in + (long)z*inB;
    const float* wz  = w  + (long)z*wB;

    for (int c0=0; c0<IC; c0+=16) {
        #pragma unroll
        for (int s=0;s<8;s++){
            int li  = tid + s*256;
            int icl = li >> 7, pq = li & 127;
            int p = p0 + pq*4;
            float4 v = make_float4(0.f,0.f,0.f,0.f);
            if (p < npix)
                v = *reinterpret_cast<const float4*>(&inb[(long)(c0+icl)*npix + p]);
            *reinterpret_cast<float4*>(&xs[icl][pq*4]) = v;
        }
        #pragma unroll
        for (int s=0;s<2;s++){
            int li  = tid + s*256;
            int icl = li >> 5, ocl = li & 31;
            float v = 0.f;
            if (oc0+ocl < OC) v = wz[(long)(oc0+ocl)*IC + (c0+icl)];
            ws[icl][ocl] = v;
        }
        __syncthreads();
        #pragma unroll
        for (int ic=0; ic<16; ic++) {
            float4 xv[4];
            #pragma unroll
            for (int q=0;q<4;q++) xv[q] = *reinterpret_cast<const float4*>(&xs[ic][(q*32+lane)*4]);
            float4 wv = *reinterpret_cast<const float4*>(&ws[ic][wy*4]);
            #pragma unroll
            for (int q=0;q<4;q++){
                acc[0][q].x += xv[q].x*wv.x; acc[0][q].y += xv[q].y*wv.x; acc[0][q].z += xv[q].z*wv.x; acc[0][q].w += xv[q].w*wv.x;
                acc[1][q].x += xv[q].x*wv.y; acc[1][q].y += xv[q].y*wv.y; acc[1][q].z += xv[q].z*wv.y; acc[1][q].w += xv[q].w*wv.y;
                acc[2][q].x += xv[q].x*wv.z; acc[2][q].y += xv[q].y*wv.z; acc[2][q].z += xv[q].z*wv.z; acc[2][q].w += xv[q].w*wv.z;
                acc[3][q].x += xv[q].x*wv.w; acc[3][q].y += xv[q].y*wv.w; acc[3][q].z += xv[q].z*wv.w; acc[3][q].w += xv[q].w*wv.w;
            }
        }
        __syncthreads();
    }

    #pragma unroll
    for (int j=0;j<4;j++){
        int oc = oc0 + wy*4 + j;
        if (oc >= OC) continue;
        float bv = bias ? bias[oc] : 0.f;
        #pragma unroll
        for (int q=0;q<4;q++){
            int p = p0 + (q*32+lane)*4;
            if (p < npix){
                float4 r = acc[j][q];
                r.x += bv; r.y += bv; r.z += bv; r.w += bv;
                *reinterpret_cast<float4*>(&out[(long)z*outB + (long)oc*npix + p]) = r;
            }
        }
    }
}

// ---------------- fused 8x8 max pool + depthwise 3x3 (24x24) ----------------
__global__ __launch_bounds__(576)
void pool_dw(const float* __restrict__ in, const float* __restrict__ w,
             const float* __restrict__ bias, float* __restrict__ out) {
    int bc = blockIdx.x;
    int c  = bc % QC_;
    int b  = bc / QC_;
    int t  = threadIdx.x;
    int oh = t / WL_, ow = t % WL_;
    __shared__ float sp[PL_];
    const float* p = in + ((long)b*QC_ + c)*HW_ + (long)oh*8*W_ + ow*8;
    float m = -INFINITY;
    #pragma unroll
    for (int r=0;r<8;r++)
        #pragma unroll
        for (int cc=0;cc<8;cc++)
            m = fmaxf(m, p[r*W_ + cc]);
    sp[t] = m;
    __syncthreads();
    const float* wc = w + (long)c*9;
    float s = bias[c];
    #pragma unroll
    for (int dr=-1;dr<=1;dr++){
        int hh = oh+dr; if (hh<0||hh>=HL_) continue;
        #pragma unroll
        for (int dc=-1;dc<=1;dc++){
            int ww = ow+dc; if (ww<0||ww>=WL_) continue;
            s += wc[(dr+1)*3 + (dc+1)] * sp[hh*WL_ + ww];
        }
    }
    out[((long)b*QC_ + c)*PL_ + t] = s;
}

// ---------------- normalize q / k rows in place (R13-proven) ----------------
__global__ void rownorm(float* dw) {
    int rid = blockIdx.x;
    int sel = rid / (B_*HEADS*C48);
    int rem = rid % (B_*HEADS*C48);
    int b   = rem / (HEADS*C48);
    int ch  = rem % (HEADS*C48);
    float* row = dw + ((long)b*QC_ + sel*D96 + ch)*PL_;
    __shared__ float sh[256];
    float s = 0.f;
    for (int i=threadIdx.x;i<PL_;i+=256){ float v=row[i]; s += v*v; }
    sh[threadIdx.x]=s; __syncthreads();
    for (int st=128;st>0;st>>=1){ if (threadIdx.x<st) sh[threadIdx.x]+=sh[threadIdx.x+st]; __syncthreads(); }
    float scale = 1.f / fmaxf(sqrtf(sh[0]), 1e-12f);
    for (int i=threadIdx.x;i<PL_;i+=256) row[i]*=scale;
}

// ---------------- attn = qn @ kn^T * temp (R13-proven, 36 blocks) ----------------
__global__ void attn_kernel(const float* __restrict__ dw, const float* __restrict__ temp,
                            float* __restrict__ attn) {
    int idx = blockIdx.x*blockDim.x + threadIdx.x;
    if (idx >= B_*HEADS*C48*C48) return;
    int j = idx % C48;
    int i = (idx / C48) % C48;
    int h = (idx / (C48*C48)) % HEADS;
    int b =  idx / (C48*C48*HEADS);
    const float* q = dw + ((long)b*QC_ +      h*C48 + i)*PL_;
    const float* k = dw + ((long)b*QC_ + D96 + h*C48 + j)*PL_;
    float s = 0.f;
    for (int n=0;n<PL_;n++) s += q[n]*k[n];
    attn[idx] = s * temp[h];
}

// ---------------- top-k threshold softmaxes, combined ----------------
__global__ void topk_combine(const float* __restrict__ attn, const float* __restrict__ aw,
                             float* __restrict__ acomb) {
    int r = threadIdx.x;
    if (r >= B_*HEADS*C48) return;
    const float* row = attn + (long)r*C48;
    float a[C48], srt[C48];
    for (int j=0;j<C48;j++){ a[j]=row[j]; srt[j]=a[j]; }
    for (int x=1;x<C48;x++){
        float key = srt[x]; int j = x-1;
        while (j>=0 && srt[j]<key){ srt[j+1]=srt[j]; j--; }
        srt[j+1]=key;
    }
    const int kks[4] = {24,32,36,38};
    float m = srt[0];
    float th[4], sm[4];
    #pragma unroll
    for (int l=0;l<4;l++){
        th[l] = srt[kks[l]-1];
        float s = 0.f;
        for (int j=0;j<C48;j++) if (a[j] >= th[l]) s += expf(a[j]-m);
        sm[l] = s;
    }
    float w0=aw[0], w1=aw[1], w2=aw[2], w3=aw[3];
    for (int j=0;j<C48;j++){
        float e = expf(a[j]-m);
        float o = 0.f;
        if (a[j] >= th[0]) o += w0*e/sm[0];
        if (a[j] >= th[1]) o += w1*e/sm[1];
        if (a[j] >= th[2]) o += w2*e/sm[2];
        if (a[j] >= th[3]) o += w3*e/sm[3];
        acomb[(long)r*C48 + j] = o;
    }
}

// ---------------- out = gelu(Acomb @ v) ----------------
__global__ void av_gelu(const float* __restrict__ acomb, const float* __restrict__ dw,
                        float* __restrict__ outlow) {
    int idx = blockIdx.x*blockDim.x + threadIdx.x;
    if (idx >= B_*HEADS*C48*PL_) return;
    int n = idx % PL_;
    int c = (idx / PL_) % C48;
    int h = (idx / (PL_*C48)) % HEADS;
    int b =  idx / (PL_*C48*HEADS);
    const float* arow = acomb + (((long)(b*HEADS+h))*C48 + c)*C48;
    const float* v = dw + ((long)b*QC_ + 2*D96 + h*C48)*PL_;
    float s = 0.f;
    #pragma unroll 4
    for (int d=0;d<C48;d++) s += arow[d] * v[(long)d*PL_ + n];
    float g = 0.5f * s * (1.f + erff(s * 0.70710678118654752440f));
    outlow[((long)b*D96 + h*C48 + c)*PL_ + n] = g;
}

// ---------------- BN partials / finals ----------------
__global__ void bn_partial1(const float* __restrict__ src, float (*part)[16][2]) {
    int c = blockIdx.x;
    int chunk = blockIdx.y;
    const float* base = src + ((long)(chunk>>3)*C48 + c)*HW_ + (long)(chunk & 7)*(HW_/8);
    float s = 0.f, s2 = 0.f;
    for (int i = threadIdx.x; i < HW_/8; i += 256){
        float v = base[i]; s += v; s2 += v*v;
    }
    __shared__ float sh[512];
    sh[threadIdx.x] = s; sh[256+threadIdx.x] = s2; __syncthreads();
    for (int st=128; st>0; st>>=1){
        if (threadIdx.x < st){ sh[threadIdx.x]+=sh[threadIdx.x+st]; sh[256+threadIdx.x]+=sh[256+threadIdx.x+st]; }
        __syncthreads();
    }
    if (threadIdx.x == 0){ part[c][chunk][0] = sh[0]; part[c][chunk][1] = sh[256]; }
}

__global__ void bn_final1(const float (*part)[16][2], float* dst) {
    int c = threadIdx.x;
    if (c >= C48) return;
    float s = 0.f, s2 = 0.f;
    #pragma unroll
    for (int k=0;k<16;k++){ s += part[c][k][0]; s2 += part[c][k][1]; }
    float N = (float)(B_*HW_);
    float m = s/N;
    float var = s2/N - m*m;
    dst[c]       = m;
    dst[C48+c]   = rsqrtf(fmaxf(var,0.f) + 1e-5f);
}

__global__ void bn_partial2(const float* __restrict__ xk, const float* __restrict__ yq,
                            float (*part)[16][2]) {
    int c = blockIdx.x;           // 0..95 : <48 -> xk, >=48 -> yq
    int chunk = blockIdx.y;
    const float* src = (c < C48) ? xk : yq;
    int cc = c % C48;
    const float* base = src + ((long)(chunk>>3)*C48 + cc)*HW_ + (long)(chunk & 7)*(HW_/8);
    float s = 0.f, s2 = 0.f;
    for (int i = threadIdx.x; i < HW_/8; i += 256){
        float v = base[i]; s += v; s2 += v*v;
    }
    __shared__ float sh[512];
    sh[threadIdx.x] = s; sh[256+threadIdx.x] = s2; __syncthreads();
    for (int st=128; st>0; st>>=1){
        if (threadIdx.x < st){ sh[threadIdx.x]+=sh[threadIdx.x+st]; sh[256+threadIdx.x]+=sh[256+threadIdx.x+st]; }
        __syncthreads();
    }
    if (threadIdx.x == 0){ part[c][chunk][0] = sh[0]; part[c][chunk][1] = sh[256]; }
}

__global__ void bn_final2(const float (*part)[16][2], float* bnx, float* bny) {
    int c = threadIdx.x;
    if (c >= 96) return;
    float s = 0.f, s2 = 0.f;
    #pragma unroll
    for (int k=0;k<16;k++){ s += part[c][k][0]; s2 += part[c][k][1]; }
    float N = (float)(B_*HW_);
    float m = s/N;
    float var = s2/N - m*m;
    float* dst = (c < C48) ? bnx : bny;
    int cc = c % C48;
    dst[cc]     = m;
    dst[C48+cc] = rsqrtf(fmaxf(var,0.f) + 1e-5f);
}

__global__ void bn_low(const float* __restrict__ src, float* __restrict__ dst) {
    int c = blockIdx.x;
    float s = 0.f, s2 = 0.f;
    for (int i = threadIdx.x; i < B_*PL_; i += 256){
        int b = i / PL_, j = i % PL_;
        float v = src[((long)b*C48 + c)*PL_ + j];
        s += v; s2 += v*v;
    }
    __shared__ float sh[512];
    sh[threadIdx.x]=s; sh[256+threadIdx.x]=s2; __syncthreads();
    for (int st=128; st>0; st>>=1){
        if (threadIdx.x < st){ sh[threadIdx.x]+=sh[threadIdx.x+st]; sh[256+threadIdx.x]+=sh[256+threadIdx.x+st]; }
        __syncthreads();
    }
    if (threadIdx.x == 0){
        float N = (float)(B_*PL_);
        float m = sh[0]/N;
        float var = sh[256]/N - m*m;
        dst[c]     = m;
        dst[C48+c] = rsqrtf(fmaxf(var,0.f) + 1e-5f);
    }
}

// ---------------- EAF blend (both full-res) ----------------
__global__ void eaf_blend(const float* __restrict__ x, long xB,
                          const float* __restrict__ y, long yB,
                          const float* __restrict__ xk, const float* __restrict__ yq,
                          const float* __restrict__ bnx, const float* __restrict__ bny,
                          float* __restrict__ out, long outB) {
    int p = blockIdx.x*blockDim.x + threadIdx.x;
    int b = blockIdx.y;
    if (p >= HW_) return;
    long base = (long)b*C48*HW_ + p;
    float s = 0.f;
    for (int c=0;c<C48;c++){
        float a  = (xk[base + (long)c*HW_] - bnx[c]) * bnx[C48+c];
        float bb = (yq[base + (long)c*HW_] - bny[c]) * bny[C48+c];
        s += a*bb;
    }
    float sim = 1.f/(1.f + expf(-s));
    for (int c=0;c<D96;c++){
        float xv = x[(long)b*xB + (long)c*HW_ + p];
        float yv = y[(long)b*yB + (long)c*HW_ + p];
        out[(long)b*outB + (long)c*HW_ + p] = sim*xv + (1.f-sim)*yv;
    }
}

// ---------------- EAF blend HF variant: x/xk low res; emits split copy -------------
__global__ void eaf_blend_hf(const float* __restrict__ xlow,
                             const float* __restrict__ y, long yB,
                             const float* __restrict__ xklow,
                             const float* __restrict__ yq,
                             const float* __restrict__ bnx, const float* __restrict__ bny,
                             float* __restrict__ out, long outB,
                             __nv_bfloat16* __restrict__ Xh, __nv_bfloat16* __restrict__ Xl) {
    int p = blockIdx.x*blockDim.x + threadIdx.x;
    int b = blockIdx.y;
    if (p >= HW_) return;
    int h = p / W_, w = p % W_;
    int lp = (h>>3)*WL_ + (w>>3);
    long basey = (long)b*C48*HW_ + p;
    float s = 0.f;
    for (int c=0;c<C48;c++){
        float a  = (xklow[((long)b*C48 + c)*PL_ + lp] - bnx[c]) * bnx[C48+c];
        float bb = (yq[basey + (long)c*HW_] - bny[c]) * bny[C48+c];
        s += a*bb;
    }
    float sim = 1.f/(1.f + expf(-s));
    for (int c=0;c<D96;c++){
        float xv = xlow[((long)b*D96 + c)*PL_ + lp];
        float yv = y[(long)b*yB + (long)c*HW_ + p];
        float o  = sim*xv + (1.f-sim)*yv;
        out[(long)b*outB + (long)c*HW_ + p] = o;
        __nv_bfloat16 hh,ll; split_bf16(o, hh, ll);
        long xi = ((long)b*D96 + c)*HW_ + p;
        Xh[xi] = hh; Xl[xi] = ll;
    }
}

// ---------------- copy input into feats slot 0 ----------------
__global__ void copy_slot0(const float* __restrict__ x, float* __restrict__ feats) {
    long idx = (long)blockIdx.x*blockDim.x + threadIdx.x;
    if (idx >= (long)B_*D96*HW_) return;
    long per = (long)D96*HW_;
    int b = idx / per;
    long r = idx % per;
    feats[(long)b*QC_*HW_ + r] = x[idx];
}

// ---------------- convert fp32 activations -> split bf16 ----------------
__global__ void convert_x(const float* __restrict__ in, long inB,
                          __nv_bfloat16* __restrict__ Xh, __nv_bfloat16* __restrict__ Xl) {
    long idx = (long)blockIdx.x*blockDim.x + threadIdx.x;
    if (idx >= (long)B_*D96*HW_) return;
    long per = (long)D96*HW_;
    int z = (int)(idx / per);
    long r = idx - (long)z*per;
    float v = in[(long)z*inB + r];
    __nv_bfloat16 h,l; split_bf16(v, h, l);
    Xh[idx] = h; Xl[idx] = l;
}

// ---------------- orchestration (single stream) ----------------
extern "C" void kernel_launch(void* const* d_in, const int* in_sizes, int n_in,
                              void* d_out, int out_size) {
    const float* x_in   = (const float*)d_in[0];
    const float* hf     = (const float*)d_in[1];
    const float* lf     = (const float*)d_in[2];
    const float* mkw_w  = (const float*)d_in[3];
    const float* mkw_b  = (const float*)d_in[4];
    const float* mkw_wc = (const float*)d_in[5];
    const float* mkw_bc = (const float*)d_in[6];
    const float* mkw_wh = (const float*)d_in[7];
    const float* mkw_bh = (const float*)d_in[8];
    const float* mkw_wv = (const float*)d_in[9];
    const float* mkw_bv = (const float*)d_in[10];
    const float* mkw_wa = (const float*)d_in[11];
    const float* mkw_ba = (const float*)d_in[12];
    const float* mkw_s  = (const float*)d_in[13];
    const float* dt_temp= (const float*)d_in[14];
    const float* dt_wqkv= (const float*)d_in[15];
    const float* dt_bqkv= (const float*)d_in[16];
    const float* dt_wdw = (const float*)d_in[17];
    const float* dt_bdw = (const float*)d_in[18];
    const float* dt_wprj= (const float*)d_in[19];
    const float* dt_bprj= (const float*)d_in[20];
    const float* dt_aw  = (const float*)d_in[21];
    const float* eh_wx  = (const float*)d_in[22];
    const float* eh_wy  = (const float*)d_in[23];
    const float* el_wx  = (const float*)d_in[24];
    const float* el_wy  = (const float*)d_in[25];
    const float* cab_w  = (const float*)d_in[26];
    const float* cab_b  = (const float*)d_in[27];
    float* out = (float*)d_out;

    float *feats, *qkvfull, *weff, *beff, *dw, *attn, *acomb,
          *low1, *low2, *xk, *yq, *bnx, *bny, *M;
    __nv_bfloat16 *Uh, *Ul, *UCh, *UCl, *Vh, *Vl, *Xh, *Xl, *HFh, *HFl, *LFh, *LFl, *WBh, *WBl;
    float (*bnpart2)[16][2];
    cudaGetSymbolAddress((void**)&feats,   g_feats);
    cudaGetSymbolAddress((void**)&qkvfull, g_qkvfull);
    cudaGetSymbolAddress((void**)&weff,    g_weff);
    cudaGetSymbolAddress((void**)&beff,    g_beff);
    cudaGetSymbolAddress((void**)&dw,      g_dw);
    cudaGetSymbolAddress((void**)&attn,    g_attn);
    cudaGetSymbolAddress((void**)&acomb,   g_acomb);
    cudaGetSymbolAddress((void**)&low1,    g_low1);
    cudaGetSymbolAddress((void**)&low2,    g_low2);
    cudaGetSymbolAddress((void**)&xk,      g_xk);
    cudaGetSymbolAddress((void**)&yq,      g_yq);
    cudaGetSymbolAddress((void**)&bnx,     g_bnx);
    cudaGetSymbolAddress((void**)&bny,     g_bny);
    cudaGetSymbolAddress((void**)&bnpart2, g_bnpart2);
    cudaGetSymbolAddress((void**)&Uh,      g_Uh);
    cudaGetSymbolAddress((void**)&Ul,      g_Ul);
    cudaGetSymbolAddress((void**)&UCh,     g_UCh);
    cudaGetSymbolAddress((void**)&UCl,     g_UCl);
    cudaGetSymbolAddress((void**)&Vh,      g_Vh);
    cudaGetSymbolAddress((void**)&Vl,      g_Vl);
    cudaGetSymbolAddress((void**)&M,       g_M);
    cudaGetSymbolAddress((void**)&Xh,      g_Xh);
    cudaGetSymbolAddress((void**)&Xl,      g_Xl);
    cudaGetSymbolAddress((void**)&HFh,     g_HFh);
    cudaGetSymbolAddress((void**)&HFl,     g_HFl);
    cudaGetSymbolAddress((void**)&LFh,     g_LFh);
    cudaGetSymbolAddress((void**)&LFl,     g_LFl);
    cudaGetSymbolAddress((void**)&WBh,     g_WBh);
    cudaGetSymbolAddress((void**)&WBl,     g_WBl);

    const long fB   = (long)QC_*HW_;
    const long dB   = (long)D96*HW_;
    const long cB   = (long)C48*HW_;
    const long lowB = (long)D96*PL_;
    const long lowC = (long)C48*PL_;
    const long nConv = (long)B_*D96*HW_;
    const unsigned convGrid = (unsigned)((nConv+255)/256);

    // prologue: hoisted conversions / transforms
    copy_slot0<<<convGrid, 256>>>(x_in, feats);
    convert_x<<<convGrid, 256>>>(hf, dB, HFh, HFl);
    convert_x<<<convGrid, 256>>>(lf, dB, LFh, LFl);
    convert_all_w<<<(WB_TOT+255)/256, 256>>>(dt_wqkv, eh_wy, el_wx, el_wy, WBh, WBl);
    wino_wtrans<<<(D96*QC_+255)/256, 256>>>(cab_w, D96, QC_, UCh, UCl);

    for (int i=0;i<2;i++){
        const float* s4 = mkw_s + i*4;
        build_weight<<<(D96*D96+255)/256, 256>>>(mkw_w + (size_t)i*D96*D96*9,
                                                 mkw_wc + (size_t)i*D96*D96*9,
                                                 mkw_wh + (size_t)i*D96*D96*3,
                                                 mkw_wv + (size_t)i*D96*D96*3,
                                                 mkw_wa + (size_t)i*D96*D96*9,
                                                 s4, weff,
                                                 mkw_b + i*D96, mkw_bc + i*D96,
                                                 mkw_bh + i*D96, mkw_bv + i*D96,
                                                 mkw_ba + i*D96, beff);

        // ---- MKW conv3x3: Winograd F(4,3) + TC GEMM; split emit only (fp32 dead) ----
        const float* xcur = feats + (size_t)i*D96*HW_;
        wino_wtrans<<<(D96*D96+255)/256, 256>>>(weff, D96, D96, Uh, Ul);
        wino_itrans<<<dim3(NT_/256, D96), 256>>>(xcur, fB, D96, Vh, Vl);
        wino_gemm<<<dim3(NT_/128, 1, 36), 256>>>(Uh, Ul, Vh, Vl, M, D96, NT_);
        wino_otrans<<<(D96*NT_+255)/256, 256>>>(M, beff, nullptr, 0L, Xh, Xl);

        // ---- qkv 1x1 (full res) via TC GEMM (X split from otrans) ----
        gemm1x1_tc<<<dim3(HW_/128, 3, B_), 256>>>(WBh + WB_QKV + (size_t)i*QC_*D96,
            WBl + WB_QKV + (size_t)i*QC_*D96, Xh, Xl,
            dt_bqkv + i*QC_, qkvfull, D96, QC_, HW_, fB);

        pool_dw<<<B_*QC_, 576>>>(qkvfull, dt_wdw + (size_t)i*QC_*9, dt_bdw + i*QC_, dw);
        rownorm<<<2*B_*HEADS*C48, 256>>>(dw);
        attn_kernel<<<(B_*HEADS*C48*C48+255)/256, 256>>>(dw, dt_temp + i*HEADS, attn);
        topk_combine<<<1, 192>>>(attn, dt_aw + i*4, acomb);
        av_gelu<<<(B_*HEADS*C48*PL_+255)/256, 256>>>(acomb, dw, low1);

        // proj 1x1 at low res (fp32)
        conv1x1_kernel<<<dim3((PL_+511)/512, D96/32, B_), 256>>>(
            low1, lowB, D96, dt_wprj + (size_t)i*D96*D96, dt_bprj + i*D96,
            low2, lowB, D96, PL_, 0L);

        float* slot_out = feats + (size_t)(i+1)*D96*HW_;

        // ---- EAF_HF (xk at low res fp32; yq full res TC); blend emits split ----
        conv1x1_kernel<<<dim3((PL_+511)/512, (C48+31)/32, B_), 256>>>(
            low2, lowB, D96, eh_wx + (size_t)i*C48*D96, nullptr, xk, lowC, C48, PL_, 0L);
        gemm1x1_tc<<<dim3(HW_/128, 1, B_), 256>>>(WBh + WB_EHY + (size_t)i*C48*D96,
            WBl + WB_EHY + (size_t)i*C48*D96, HFh, HFl,
            nullptr, yq, D96, C48, HW_, cB);
        bn_low<<<C48, 256>>>(xk, bnx);
        bn_partial1<<<dim3(C48,16), 256>>>(yq, bnpart2);
        bn_final1<<<1, C48>>>(bnpart2, bny);
        eaf_blend_hf<<<dim3(HW_/256, B_), 256>>>(low2, hf, dB, xk, yq, bnx, bny,
                                                 slot_out, fB, Xh, Xl);

        // ---- EAF_LF (both full res, TC; X split from blend_hf) ----
        gemm1x1_tc<<<dim3(HW_/128, 1, B_), 256>>>(WBh + WB_ELX + (size_t)i*C48*D96,
            WBl + WB_ELX + (size_t)i*C48*D96, Xh, Xl,
            nullptr, xk, D96, C48, HW_, cB);
        gemm1x1_tc<<<dim3(HW_/128, 1, B_), 256>>>(WBh + WB_ELY + (size_t)i*C48*D96,
            WBl + WB_ELY + (size_t)i*C48*D96, LFh, LFl,
            nullptr, yq, D96, C48, HW_, cB);
        bn_partial2<<<dim3(96,16), 256>>>(xk, yq, bnpart2);
        bn_final2<<<1, 96>>>(bnpart2, bnx, bny);
        eaf_blend<<<dim3(HW_/256, B_), 256>>>(slot_out, fB, lf, dB, xk, yq, bnx, bny,
                                              slot_out, fB);
    }

    // ---- CAB conv3x3 (IC=288) via Winograd + TC GEMM (U hoisted) ----
    wino_itrans<<<dim3(NT_/256, QC_), 256>>>(feats, fB, QC_, Vh, Vl);
    wino_gemm<<<dim3(NT_/128, 1, 36), 256>>>(UCh, UCl, Vh, Vl, M, QC_, NT_);
    wino_otrans<<<(D96*NT_+255)/256, 256>>>(M, cab_b, out, dB, nullptr, nullptr);
}

// round 17
// speedup vs baseline: 2.5168x; 1.0365x over previous
#include <cuda_runtime.h>
#include <cuda_bf16.h>
#include <cstdint>
#include <math.h>

// ---------------- problem constants ----------------
#define B_    2
#define D96   96
#define H_    192
#define W_    192
#define HW_   (H_*W_)        // 36864
#define HEADS 2
#define C48   48
#define HL_   24
#define WL_   24
#define PL_   (HL_*WL_)      // 576
#define QC_   288            // 3*D
#define TPD_  48             // winograd F(4,3) tiles per spatial dim
#define NT_   4608           // 48*48*2 tiles

// weight-bank offsets (elements) in g_WBh/g_WBl
#define WB_QKV   0           // [L][288][96]  -> 2*27648
#define WB_EHY   55296       // [L][48][96]   -> 2*4608
#define WB_ELX   64512
#define WB_ELY   73728
#define WB_TOT   82944

// ---------------- scratch (static, no runtime alloc) ----------------
__device__ float g_feats  [(size_t)B_*QC_*HW_];
__device__ float g_qkvfull[(size_t)B_*QC_*HW_];
__device__ float g_weff   [D96*D96*9];
__device__ float g_beff   [D96];
__device__ float g_dw     [(size_t)B_*QC_*PL_];
__device__ float g_attn   [B_*HEADS*C48*C48];
__device__ float g_acomb  [B_*HEADS*C48*C48];
__device__ float g_low1   [(size_t)B_*D96*PL_];
__device__ float g_low2   [(size_t)B_*D96*PL_];
__device__ float g_xk     [(size_t)B_*C48*HW_];
__device__ float g_yq     [(size_t)B_*C48*HW_];
__device__ float g_bnx    [2*C48];
__device__ float g_bny    [2*C48];
__device__ float g_bnpart2[96][16][2];
// winograd F(4x4,3x3) scratch — split bf16 operands, fp32 M
// V is laid out [36][288][NT]: ch 0-95 = x (layer0 itrans), 96-191 = slot1
// (layer1 itrans), 192-287 = slot2 (CAB itrans). MKW GEMMs read 96-ch windows.
__device__ __nv_bfloat16 g_Uh [(size_t)36*D96*D96];   // MKW weights
__device__ __nv_bfloat16 g_Ul [(size_t)36*D96*D96];
__device__ __nv_bfloat16 g_UCh[(size_t)36*D96*QC_];   // CAB weights (hoisted)
__device__ __nv_bfloat16 g_UCl[(size_t)36*D96*QC_];
__device__ __nv_bfloat16 g_Vh [(size_t)36*QC_*NT_];
__device__ __nv_bfloat16 g_Vl [(size_t)36*QC_*NT_];
__device__ float         g_M  [(size_t)36*D96*NT_];
// split-bf16 activations / weights for TC 1x1 convs
__device__ __nv_bfloat16 g_Xh [(size_t)B_*D96*HW_];
__device__ __nv_bfloat16 g_Xl [(size_t)B_*D96*HW_];
__device__ __nv_bfloat16 g_HFh[(size_t)B_*D96*HW_];
__device__ __nv_bfloat16 g_HFl[(size_t)B_*D96*HW_];
__device__ __nv_bfloat16 g_LFh[(size_t)B_*D96*HW_];
__device__ __nv_bfloat16 g_LFl[(size_t)B_*D96*HW_];
__device__ __nv_bfloat16 g_WBh[WB_TOT];
__device__ __nv_bfloat16 g_WBl[WB_TOT];

__device__ __forceinline__ void split_bf16(float x, __nv_bfloat16& h, __nv_bfloat16& l){
    h = __float2bfloat16_rn(x);
    l = __float2bfloat16_rn(x - __bfloat162float(h));
}

// ---------------- MKW effective weight (+bias folded in) ----------------
__global__ void build_weight(const float* __restrict__ w,  const float* __restrict__ wc,
                             const float* __restrict__ wh, const float* __restrict__ wv,
                             const float* __restrict__ wa, const float* __restrict__ s4,
                             float* __restrict__ weff,
                             const float* __restrict__ b,  const float* __restrict__ bc,
                             const float* __restrict__ bh, const float* __restrict__ bv,
                             const float* __restrict__ ba, float* __restrict__ beff) {
    int idx = blockIdx.x * blockDim.x + threadIdx.x;   // oc*96+ic
    const float s0=s4[0], s1=s4[1], s2=s4[2], s3=s4[3];
    if (blockIdx.x == 0 && threadIdx.x < D96){
        int c = threadIdx.x;
        beff[c] = b[c] + s0*bc[c] + s1*bh[c] + s2*bv[c] + s3*ba[c];
    }
    if (idx >= D96*D96) return;
    float wcl[9], wal[9];
    float csum = 0.f;
    #pragma unroll
    for (int t=0;t<9;t++){ wcl[t]=wc[(size_t)idx*9+t]; csum+=wcl[t]; }
    #pragma unroll
    for (int t=0;t<9;t++){ wal[t]=wa[(size_t)idx*9+t]; }
    const int perm[9] = {3,0,1,6,4,2,7,8,5};
    float wh0=wh[(size_t)idx*3+0], wh1=wh[(size_t)idx*3+1], wh2=wh[(size_t)idx*3+2];
    float wv0=wv[(size_t)idx*3+0], wv1=wv[(size_t)idx*3+1], wv2=wv[(size_t)idx*3+2];
    #pragma unroll
    for (int t=0;t<9;t++){
        float wcd = wcl[t] - (t==4 ? csum : 0.f);
        float whd = 0.f;
        if (t==0) whd =  wh0; else if (t==3) whd =  wh1; else if (t==6) whd =  wh2;
        else if (t==2) whd = -wh0; else if (t==5) whd = -wh1; else if (t==8) whd = -wh2;
        float wvd = 0.f;
        if (t<3) wvd = (t==0?wv0:(t==1?wv1:wv2));
        else if (t>=6) wvd = -(t==6?wv0:(t==7?wv1:wv2));
        float wad = wal[t] - wal[perm[t]];
        weff[(size_t)idx*9+t] = w[(size_t)idx*9+t] + s0*wcd + s1*whd + s2*wvd + s3*wad;
    }
}

// ---------------- hoisted: convert ALL 1x1 weights to split bf16 -------------------
__global__ void convert_all_w(const float* __restrict__ qkv, const float* __restrict__ ehy,
                              const float* __restrict__ elx, const float* __restrict__ ely,
                              __nv_bfloat16* __restrict__ Wh, __nv_bfloat16* __restrict__ Wl){
    int idx = blockIdx.x*blockDim.x + threadIdx.x;
    if (idx >= WB_TOT) return;
    float v;
    if (idx < WB_EHY)      v = qkv[idx];
    else if (idx < WB_ELX) v = ehy[idx - WB_EHY];
    else if (idx < WB_ELY) v = elx[idx - WB_ELX];
    else                   v = ely[idx - WB_ELY];
    __nv_bfloat16 h,l; split_bf16(v, h, l);
    Wh[idx] = h; Wl[idx] = l;
}

// ---------------- Winograd F(4x4,3x3): weight transform U = G g G^T (split bf16) ----
__global__ void wino_wtrans(const float* __restrict__ w, int OC, int IC,
                            __nv_bfloat16* __restrict__ Uh, __nv_bfloat16* __restrict__ Ul) {
    int idx = blockIdx.x*blockDim.x + threadIdx.x;   // oc*IC + ic
    if (idx >= OC*IC) return;
    float g[9];
    #pragma unroll
    for (int t=0;t<9;t++) g[t] = w[(size_t)idx*9 + t];
    const float i6 = 1.f/6.f, i12 = 1.f/12.f, i24 = 1.f/24.f;
    float Gg[6][3];
    #pragma unroll
    for (int c=0;c<3;c++){
        float g0 = g[c], g1 = g[3+c], g2 = g[6+c];
        Gg[0][c] = 0.25f*g0;
        Gg[1][c] = -i6*(g0 + g1 + g2);
        Gg[2][c] =  i6*(-g0 + g1 - g2);
        Gg[3][c] =  i24*g0 + i12*g1 + i6*g2;
        Gg[4][c] =  i24*g0 - i12*g1 + i6*g2;
        Gg[5][c] =  g2;
    }
    long OI = (long)OC*IC;
    #pragma unroll
    for (int r=0;r<6;r++){
        float a = Gg[r][0], b = Gg[r][1], c2 = Gg[r][2];
        float u[6];
        u[0] = 0.25f*a;
        u[1] = -i6*(a + b + c2);
        u[2] =  i6*(-a + b - c2);
        u[3] =  i24*a + i12*b + i6*c2;
        u[4] =  i24*a - i12*b + i6*c2;
        u[5] =  c2;
        #pragma unroll
        for (int q=0;q<6;q++){
            __nv_bfloat16 h,l; split_bf16(u[q], h, l);
            Uh[(long)(r*6+q)*OI + idx] = h;
            Ul[(long)(r*6+q)*OI + idx] = l;
        }
    }
}

// ---------------- Winograd F(4,3) input transform V = B^T d B (split bf16) ----------
// Processes 96 channels; writes into [36][ICtot][NT] layout at channel chanOff+ic.
__global__ void wino_itrans(const float* __restrict__ in, long inB,
                            int ICtot, int chanOff,
                            __nv_bfloat16* __restrict__ Vh, __nv_bfloat16* __restrict__ Vl) {
    int n  = blockIdx.x*blockDim.x + threadIdx.x;   // 0..NT_-1
    int ic = blockIdx.y;                            // 0..95
    int b   = n / (NT_/B_);
    int loc = n % (NT_/B_);
    int ty = loc / TPD_, tx = loc % TPD_;
    const float* src = in + (long)b*inB + (long)ic*HW_;
    int h0 = 4*ty - 1, w0 = 4*tx - 1;
    float d[6][6];
    #pragma unroll
    for (int r=0;r<6;r++){
        int hh = h0 + r;
        bool hok = (hh >= 0 && hh < H_);
        #pragma unroll
        for (int c=0;c<6;c++){
            int ww = w0 + c;
            d[r][c] = (hok && ww >= 0 && ww < W_) ? src[hh*W_ + ww] : 0.f;
        }
    }
    float t[6][6];
    #pragma unroll
    for (int c=0;c<6;c++){
        float d0=d[0][c], d1=d[1][c], d2=d[2][c], d3=d[3][c], d4=d[4][c], d5=d[5][c];
        t[0][c] =  4.f*d0 - 5.f*d2 + d4;
        t[1][c] = -4.f*d1 - 4.f*d2 + d3 + d4;
        t[2][c] =  4.f*d1 - 4.f*d2 - d3 + d4;
        t[3][c] = -2.f*d1 -      d2 + 2.f*d3 + d4;
        t[4][c] =  2.f*d1 -      d2 - 2.f*d3 + d4;
        t[5][c] =  4.f*d1 - 5.f*d3 + d5;
    }
    long stride = (long)ICtot*NT_;
    long base = (long)(chanOff + ic)*NT_ + n;
    #pragma unroll
    for (int r=0;r<6;r++){
        float t0=t[r][0], t1=t[r][1], t2=t[r][2], t3=t[r][3], t4=t[r][4], t5=t[r][5];
        float v[6];
        v[0] =  4.f*t0 - 5.f*t2 + t4;
        v[1] = -4.f*t1 - 4.f*t2 + t3 + t4;
        v[2] =  4.f*t1 - 4.f*t2 - t3 + t4;
        v[3] = -2.f*t1 -      t2 + 2.f*t3 + t4;
        v[4] =  2.f*t1 -      t2 - 2.f*t3 + t4;
        v[5] =  4.f*t1 - 5.f*t3 + t5;
        #pragma unroll
        for (int q=0;q<6;q++){
            __nv_bfloat16 h,l; split_bf16(v[q], h, l);
            Vh[(long)(r*6+q)*stride + base] = h;
            Vl[(long)(r*6+q)*stride + base] = l;
        }
    }
}

// ---------------- split-bf16 TC GEMM, fused phases + double buffer -----------------
// K = IC logical channels starting at the given V base pointer; V plane stride ICv*NT.
__global__ __launch_bounds__(256)
void wino_gemm(const __nv_bfloat16* __restrict__ Uh, const __nv_bfloat16* __restrict__ Ul,
               const __nv_bfloat16* __restrict__ Vh, const __nv_bfloat16* __restrict__ Vl,
               float* __restrict__ Mo, int IC, int ICv, int NT) {
    const int p    = blockIdx.z;
    const int nBlk = blockIdx.x * 128;
    const int tid  = threadIdx.x;
    const int warp = tid >> 5, lane = tid & 31;
    const int mOff = (warp >> 2) * 48;
    const int nOff = (warp & 3) * 32;
    const int lq   = lane >> 2;
    const int lr   = lane & 3;

    __shared__ uint32_t Ah[2][96*9], Al[2][96*9];
    __shared__ uint32_t Bh[2][128*9], Bl[2][128*9];

    float acc[3][4][4];
    #pragma unroll
    for (int mt=0;mt<3;mt++)
        #pragma unroll
        for (int nt=0;nt<4;nt++)
            #pragma unroll
            for (int q=0;q<4;q++) acc[mt][nt][q]=0.f;

    const long Uplane = (long)p*96*IC;
    const long Vplane = (long)p*ICv*NT;
    const int nIter = IC/16;

    #pragma unroll
    for (int s=0;s<3;s++){
        int e = tid + s*256;
        int m = e >> 3, kp = e & 7;
        long off = Uplane + (long)m*IC + kp*2;
        Ah[0][m*9+kp] = *reinterpret_cast<const uint32_t*>(Uh + off);
        Al[0][m*9+kp] = *reinterpret_cast<const uint32_t*>(Ul + off);
    }
    #pragma unroll
    for (int s=0;s<2;s++){
        int e = tid + s*256;
        int kp = e >> 6, j = e & 63;
        long off = Vplane + (long)(2*kp)*NT + nBlk + 2*j;
        uint32_t h0 = *reinterpret_cast<const uint32_t*>(Vh + off);
        uint32_t h1 = *reinterpret_cast<const uint32_t*>(Vh + off + NT);
        Bh[0][(2*j  )*9 + kp] = __byte_perm(h0, h1, 0x5410);
        Bh[0][(2*j+1)*9 + kp] = __byte_perm(h0, h1, 0x7632);
        uint32_t l0 = *reinterpret_cast<const uint32_t*>(Vl + off);
        uint32_t l1 = *reinterpret_cast<const uint32_t*>(Vl + off + NT);
        Bl[0][(2*j  )*9 + kp] = __byte_perm(l0, l1, 0x5410);
        Bl[0][(2*j+1)*9 + kp] = __byte_perm(l0, l1, 0x7632);
    }
    __syncthreads();

    for (int it=0; it<nIter; it++){
        const int cur = it & 1, nxt = cur ^ 1;
        const bool more = (it+1 < nIter);

        uint32_t sa[6], sb[8];
        if (more){
            int icb = (it+1)*16;
            #pragma unroll
            for (int s=0;s<3;s++){
                int e = tid + s*256;
                int m = e >> 3, kp = e & 7;
                long off = Uplane + (long)m*IC + icb + kp*2;
                sa[2*s  ] = *reinterpret_cast<const uint32_t*>(Uh + off);
                sa[2*s+1] = *reinterpret_cast<const uint32_t*>(Ul + off);
            }
            #pragma unroll
            for (int s=0;s<2;s++){
                int e = tid + s*256;
                int kp = e >> 6, j = e & 63;
                long off = Vplane + (long)(icb + 2*kp)*NT + nBlk + 2*j;
                sb[4*s  ] = *reinterpret_cast<const uint32_t*>(Vh + off);
                sb[4*s+1] = *reinterpret_cast<const uint32_t*>(Vh + off + NT);
                sb[4*s+2] = *reinterpret_cast<const uint32_t*>(Vl + off);
                sb[4*s+3] = *reinterpret_cast<const uint32_t*>(Vl + off + NT);
            }
        }

        #pragma unroll
        for (int ph=0; ph<3; ph++){
            const uint32_t* As = (ph < 2) ? Ah[cur] : Al[cur];
            const uint32_t* Bs = (ph == 1) ? Bl[cur] : Bh[cur];
            uint32_t a[3][4], b[4][2];
            #pragma unroll
            for (int mt=0;mt<3;mt++){
                int m0 = mOff + mt*16;
                a[mt][0] = As[(m0     + lq)*9 +     lr];
                a[mt][1] = As[(m0 + 8 + lq)*9 +     lr];
                a[mt][2] = As[(m0     + lq)*9 + 4 + lr];
                a[mt][3] = As[(m0 + 8 + lq)*9 + 4 + lr];
            }
            #pragma unroll
            for (int nt=0;nt<4;nt++){
                int n0 = nOff + nt*8;
                b[nt][0] = Bs[(n0 + lq)*9 +     lr];
                b[nt][1] = Bs[(n0 + lq)*9 + 4 + lr];
            }
            #pragma unroll
            for (int mt=0;mt<3;mt++)
                #pragma unroll
                for (int nt=0;nt<4;nt++){
                    asm volatile(
                        "mma.sync.aligned.m16n8k16.row.col.f32.bf16.bf16.f32 "
                        "{%0,%1,%2,%3}, {%4,%5,%6,%7}, {%8,%9}, {%0,%1,%2,%3};"
                        : "+f"(acc[mt][nt][0]), "+f"(acc[mt][nt][1]),
                          "+f"(acc[mt][nt][2]), "+f"(acc[mt][nt][3])
                        : "r"(a[mt][0]), "r"(a[mt][1]), "r"(a[mt][2]), "r"(a[mt][3]),
                          "r"(b[nt][0]), "r"(b[nt][1]));
                }
        }

        if (more){
            #pragma unroll
            for (int s=0;s<3;s++){
                int e = tid + s*256;
                int m = e >> 3, kp = e & 7;
                Ah[nxt][m*9+kp] = sa[2*s];
                Al[nxt][m*9+kp] = sa[2*s+1];
            }
            #pragma unroll
            for (int s=0;s<2;s++){
                int e = tid + s*256;
                int kp = e >> 6, j = e & 63;
                Bh[nxt][(2*j  )*9 + kp] = __byte_perm(sb[4*s], sb[4*s+1], 0x5410);
                Bh[nxt][(2*j+1)*9 + kp] = __byte_perm(sb[4*s], sb[4*s+1], 0x7632);
                Bl[nxt][(2*j  )*9 + kp] = __byte_perm(sb[4*s+2], sb[4*s+3], 0x5410);
                Bl[nxt][(2*j+1)*9 + kp] = __byte_perm(sb[4*s+2], sb[4*s+3], 0x7632);
            }
        }
        __syncthreads();
    }

    long Mbase = (long)p*96*NT;
    #pragma unroll
    for (int mt=0;mt<3;mt++){
        int r0 = mOff + mt*16 + lq;
        #pragma unroll
        for (int nt=0;nt<4;nt++){
            int c = nBlk + nOff + nt*8 + 2*lr;
            *reinterpret_cast<float2*>(&Mo[Mbase + (long)r0*NT + c]) =
                make_float2(acc[mt][nt][0], acc[mt][nt][1]);
            *reinterpret_cast<float2*>(&Mo[Mbase + (long)(r0+8)*NT + c]) =
                make_float2(acc[mt][nt][2], acc[mt][nt][3]);
        }
    }
}

// ---------------- split-bf16 TC GEMM for 1x1 convs (double buffered) ----------------
__global__ __launch_bounds__(256)
void gemm1x1_tc(const __nv_bfloat16* __restrict__ Wh, const __nv_bfloat16* __restrict__ Wl,
                const __nv_bfloat16* __restrict__ Xh, const __nv_bfloat16* __restrict__ Xl,
                const float* __restrict__ bias, float* __restrict__ out,
                int IC, int OC, int npix, long outBz) {
    const int z    = blockIdx.z;
    const int nBlk = blockIdx.x * 128;
    const int mBlk = blockIdx.y * 96;
    const int tid  = threadIdx.x;
    const int warp = tid >> 5, lane = tid & 31;
    const int mOff = (warp >> 2) * 48;
    const int nOff = (warp & 3) * 32;
    const int lq   = lane >> 2;
    const int lr   = lane & 3;

    __shared__ uint32_t Ah[2][96*9], Al[2][96*9];
    __shared__ uint32_t Bh[2][128*9], Bl[2][128*9];

    float acc[3][4][4];
    #pragma unroll
    for (int mt=0;mt<3;mt++)
        #pragma unroll
        for (int nt=0;nt<4;nt++)
            #pragma unroll
            for (int q=0;q<4;q++) acc[mt][nt][q]=0.f;

    const long Xplane = (long)z*IC*npix;
    const int nIter = IC/16;

    #pragma unroll
    for (int s=0;s<3;s++){
        int e = tid + s*256;
        int m = e >> 3, kp = e & 7;
        int gm = mBlk + m;
        uint32_t vh = 0, vl = 0;
        if (gm < OC){
            long off = (long)gm*IC + kp*2;
            vh = *reinterpret_cast<const uint32_t*>(Wh + off);
            vl = *reinterpret_cast<const uint32_t*>(Wl + off);
        }
        Ah[0][m*9+kp] = vh; Al[0][m*9+kp] = vl;
    }
    #pragma unroll
    for (int s=0;s<2;s++){
        int e = tid + s*256;
        int kp = e >> 6, j = e & 63;
        long off = Xplane + (long)(2*kp)*npix + nBlk + 2*j;
        uint32_t h0 = *reinterpret_cast<const uint32_t*>(Xh + off);
        uint32_t h1 = *reinterpret_cast<const uint32_t*>(Xh + off + npix);
        Bh[0][(2*j  )*9 + kp] = __byte_perm(h0, h1, 0x5410);
        Bh[0][(2*j+1)*9 + kp] = __byte_perm(h0, h1, 0x7632);
        uint32_t l0 = *reinterpret_cast<const uint32_t*>(Xl + off);
        uint32_t l1 = *reinterpret_cast<const uint32_t*>(Xl + off + npix);
        Bl[0][(2*j  )*9 + kp] = __byte_perm(l0, l1, 0x5410);
        Bl[0][(2*j+1)*9 + kp] = __byte_perm(l0, l1, 0x7632);
    }
    __syncthreads();

    for (int it=0; it<nIter; it++){
        const int cur = it & 1, nxt = cur ^ 1;
        const bool more = (it+1 < nIter);

        uint32_t sa[6], sb[8];
        if (more){
            int icb = (it+1)*16;
            #pragma unroll
            for (int s=0;s<3;s++){
                int e = tid + s*256;
                int m = e >> 3, kp = e & 7;
                int gm = mBlk + m;
                uint32_t vh = 0, vl = 0;
                if (gm < OC){
                    long off = (long)gm*IC + icb + kp*2;
                    vh = *reinterpret_cast<const uint32_t*>(Wh + off);
                    vl = *reinterpret_cast<const uint32_t*>(Wl + off);
                }
                sa[2*s] = vh; sa[2*s+1] = vl;
            }
            #pragma unroll
            for (int s=0;s<2;s++){
                int e = tid + s*256;
                int kp = e >> 6, j = e & 63;
                long off = Xplane + (long)(icb + 2*kp)*npix + nBlk + 2*j;
                sb[4*s  ] = *reinterpret_cast<const uint32_t*>(Xh + off);
                sb[4*s+1] = *reinterpret_cast<const uint32_t*>(Xh + off + npix);
                sb[4*s+2] = *reinterpret_cast<const uint32_t*>(Xl + off);
                sb[4*s+3] = *reinterpret_cast<const uint32_t*>(Xl + off + npix);
            }
        }

        #pragma unroll
        for (int ph=0; ph<3; ph++){
            const uint32_t* As = (ph < 2) ? Ah[cur] : Al[cur];
            const uint32_t* Bs = (ph == 1) ? Bl[cur] : Bh[cur];
            uint32_t a[3][4], b[4][2];
            #pragma unroll
            for (int mt=0;mt<3;mt++){
                int m0 = mOff + mt*16;
                a[mt][0] = As[(m0     + lq)*9 +     lr];
                a[mt][1] = As[(m0 + 8 + lq)*9 +     lr];
                a[mt][2] = As[(m0     + lq)*9 + 4 + lr];
                a[mt][3] = As[(m0 + 8 + lq)*9 + 4 + lr];
            }
            #pragma unroll
            for (int nt=0;nt<4;nt++){
                int n0 = nOff + nt*8;
                b[nt][0] = Bs[(n0 + lq)*9 +     lr];
                b[nt][1] = Bs[(n0 + lq)*9 + 4 + lr];
            }
            #pragma unroll
            for (int mt=0;mt<3;mt++)
                #pragma unroll
                for (int nt=0;nt<4;nt++){
                    asm volatile(
                        "mma.sync.aligned.m16n8k16.row.col.f32.bf16.bf16.f32 "
                        "{%0,%1,%2,%3}, {%4,%5,%6,%7}, {%8,%9}, {%0,%1,%2,%3};"
                        : "+f"(acc[mt][nt][0]), "+f"(acc[mt][nt][1]),
                          "+f"(acc[mt][nt][2]), "+f"(acc[mt][nt][3])
                        : "r"(a[mt][0]), "r"(a[mt][1]), "r"(a[mt][2]), "r"(a[mt][3]),
                          "r"(b[nt][0]), "r"(b[nt][1]));
                }
        }

        if (more){
            #pragma unroll
            for (int s=0;s<3;s++){
                int e = tid + s*256;
                int m = e >> 3, kp = e & 7;
                Ah[nxt][m*9+kp] = sa[2*s];
                Al[nxt][m*9+kp] = sa[2*s+1];
            }
            #pragma unroll
            for (int s=0;s<2;s++){
                int e = tid + s*256;
                int kp = e >> 6, j = e & 63;
                Bh[nxt][(2*j  )*9 + kp] = __byte_perm(sb[4*s], sb[4*s+1], 0x5410);
                Bh[nxt][(2*j+1)*9 + kp] = __byte_perm(sb[4*s], sb[4*s+1], 0x7632);
                Bl[nxt][(2*j  )*9 + kp] = __byte_perm(sb[4*s+2], sb[4*s+3], 0x5410);
                Bl[nxt][(2*j+1)*9 + kp] = __byte_perm(sb[4*s+2], sb[4*s+3], 0x7632);
            }
        }
        __syncthreads();
    }

    #pragma unroll
    for (int mt=0;mt<3;mt++){
        int r0 = mOff + mt*16 + lq;
        int g0 = mBlk + r0, g1 = g0 + 8;
        float bv0 = (bias && g0 < OC) ? bias[g0] : 0.f;
        float bv1 = (bias && g1 < OC) ? bias[g1] : 0.f;
        #pragma unroll
        for (int nt=0;nt<4;nt++){
            int c = nBlk + nOff + nt*8 + 2*lr;
            if (g0 < OC)
                *reinterpret_cast<float2*>(&out[(long)z*outBz + (long)g0*npix + c]) =
                    make_float2(acc[mt][nt][0] + bv0, acc[mt][nt][1] + bv0);
            if (g1 < OC)
                *reinterpret_cast<float2*>(&out[(long)z*outBz + (long)g1*npix + c]) =
                    make_float2(acc[mt][nt][2] + bv1, acc[mt][nt][3] + bv1);
        }
    }
}

// ---------------- Winograd F(4,3) output transform; fp32 out and split emit optional
__global__ void wino_otrans(const float* __restrict__ Mm, const float* __restrict__ bias,
                            float* __restrict__ out, long outB,
                            __nv_bfloat16* __restrict__ Xh, __nv_bfloat16* __restrict__ Xl) {
    int idx = blockIdx.x*blockDim.x + threadIdx.x;
    if (idx >= D96*NT_) return;
    int n  = idx % NT_;
    int oc = idx / NT_;
    float m[6][6];
    #pragma unroll
    for (int p=0;p<36;p++)
        m[p/6][p%6] = Mm[((long)p*D96 + oc)*NT_ + n];
    float t[4][6];
    #pragma unroll
    for (int c=0;c<6;c++){
        float m0=m[0][c], m1=m[1][c], m2=m[2][c], m3=m[3][c], m4=m[4][c], m5=m[5][c];
        t[0][c] = m0 + m1 + m2 + m3 + m4;
        t[1][c] = m1 - m2 + 2.f*m3 - 2.f*m4;
        t[2][c] = m1 + m2 + 4.f*m3 + 4.f*m4;
        t[3][c] = m1 - m2 + 8.f*m3 - 8.f*m4 + m5;
    }
    float bv = bias[oc];
    int b   = n / (NT_/B_);
    int loc = n % (NT_/B_);
    int ty = loc / TPD_, tx = loc % TPD_;
    long pixBase = (long)(b*D96 + oc)*HW_ + (long)(4*ty)*W_ + 4*tx;
    float* dst = out ? (out + (long)b*outB + (long)oc*HW_ + (long)(4*ty)*W_ + 4*tx) : nullptr;
    #pragma unroll
    for (int r=0;r<4;r++){
        float t0=t[r][0], t1=t[r][1], t2=t[r][2], t3=t[r][3], t4=t[r][4], t5=t[r][5];
        float y[4];
        y[0] = t0 + t1 + t2 + t3 + t4 + bv;
        y[1] = t1 - t2 + 2.f*t3 - 2.f*t4 + bv;
        y[2] = t1 + t2 + 4.f*t3 + 4.f*t4 + bv;
        y[3] = t1 - t2 + 8.f*t3 - 8.f*t4 + t5 + bv;
        if (dst){
            float* row = dst + (long)r*W_;
            row[0]=y[0]; row[1]=y[1]; row[2]=y[2]; row[3]=y[3];
        }
        if (Xh){
            long pb = pixBase + (long)r*W_;
            #pragma unroll
            for (int c=0;c<4;c++){
                __nv_bfloat16 h,l; split_bf16(y[c], h, l);
                Xh[pb+c] = h; Xl[pb+c] = l;
            }
        }
    }
}

// ---------------- GEMM / 1x1 conv (fp32, low-res use) ----------------
__global__ __launch_bounds__(256, 2)
void conv1x1_kernel(const float* __restrict__ in, long inB, int IC,
                    const float* __restrict__ w, const float* __restrict__ bias,
                    float* __restrict__ out, long outB, int OC, int npix, long wB) {
    const int tid  = threadIdx.x;
    const int lane = tid & 31;
    const int wy   = tid >> 5;
    const int p0   = blockIdx.x * 512;
    const int oc0  = blockIdx.y * 32;
    const int z    = blockIdx.z;

    __shared__ float xs[16][512];
    __shared__ float ws[16][32];

    float4 acc[4][4];
    #pragma unroll
    for (int j=0;j<4;j++)
        #pragma unroll
        for (int q=0;q<4;q++) acc[j][q] = make_float4(0.f,0.f,0.f,0.f);

    const float* inb = in + (long)z*inB;
    const float* wz  = w  + (long)z*wB;

    for (int c0=0; c0<IC; c0+=16) {
        #pragma unroll
        for (int s=0;s<8;s++){
            int li  = tid + s*256;
            int icl = li >> 7, pq = li & 127;
            int p = p0 + pq*4;
            float4 v = make_float4(0.f,0.f,0.f,0.f);
            if (p < npix)
                v = *reinterpret_cast<const float4*>(&inb[(long)(c0+icl)*npix + p]);
            *reinterpret_cast<float4*>(&xs[icl][pq*4]) = v;
        }
        #pragma unroll
        for (int s=0;s<2;s++){
            int li  = tid + s*256;
            int icl = li >> 5, ocl = li & 31;
            float v = 0.f;
            if (oc0+ocl < OC) v = wz[(long)(oc0+ocl)*IC + (c0+icl)];
            ws[icl][ocl] = v;
        }
        __syncthreads();
        #pragma unroll
        for (int ic=0; ic<16; ic++) {
            float4 xv[4];
            #pragma unroll
            for (int q=0;q<4;q++) xv[q] = *reinterpret_cast<const float4*>(&xs[ic][(q*32+lane)*4]);
            float4 wv = *reinterpret_cast<const float4*>(&ws[ic][wy*4]);
            #pragma unroll
            for (int q=0;q<4;q++){
                acc[0][q].x += xv[q].x*wv.x; acc[0][q].y += xv[q].y*wv.x; acc[0][q].z += xv[q].z*wv.x; acc[0][q].w += xv[q].w*wv.x;
                acc[1][q].x += xv[q].x*wv.y; acc[1][q].y += xv[q].y*wv.y; acc[1][q].z += xv[q].z*wv.y; acc[1][q].w += xv[q].w*wv.y;
                acc[2][q].x += xv[q].x*wv.z; acc[2][q].y += xv[q].y*wv.z; acc[2][q].z += xv[q].z*wv.z; acc[2][q].w += xv[q].w*wv.z;
                acc[3][q].x += xv[q].x*wv.w; acc[3][q].y += xv[q].y*wv.w; acc[3][q].z += xv[q].z*wv.w; acc[3][q].w += xv[q].w*wv.w;
            }
        }
        __syncthreads();
    }

    #pragma unroll
    for (int j=0;j<4;j++){
        int oc = oc0 + wy*4 + j;
        if (oc >= OC) continue;
        float bv = bias ? bias[oc] : 0.f;
        #pragma unroll
        for (int q=0;q<4;q++){
            int p = p0 + (q*32+lane)*4;
            if (p < npix){
                float4 r = acc[j][q];
                r.x += bv; r.y += bv; r.z += bv; r.w += bv;
                *reinterpret_cast<float4*>(&out[(long)z*outB + (long)oc*npix + p]) = r;
            }
        }
    }
}

// ---------------- fused 8x8 max pool + depthwise 3x3 (24x24) ----------------
__global__ __launch_bounds__(576)
void pool_dw(const float* __restrict__ in, const float* __restrict__ w,
             const float* __restrict__ bias, float* __restrict__ out) {
    int bc = blockIdx.x;
    int c  = bc % QC_;
    int b  = bc / QC_;
    int t  = threadIdx.x;
    int oh = t / WL_, ow = t % WL_;
    __shared__ float sp[PL_];
    const float* p = in + ((long)b*QC_ + c)*HW_ + (long)oh*8*W_ + ow*8;
    float m = -INFINITY;
    #pragma unroll
    for (int r=0;r<8;r++)
        #pragma unroll
        for (int cc=0;cc<8;cc++)
            m = fmaxf(m, p[r*W_ + cc]);
    sp[t] = m;
    __syncthreads();
    const float* wc = w + (long)c*9;
    float s = bias[c];
    #pragma unroll
    for (int dr=-1;dr<=1;dr++){
        int hh = oh+dr; if (hh<0||hh>=HL_) continue;
        #pragma unroll
        for (int dc=-1;dc<=1;dc++){
            int ww = ow+dc; if (ww<0||ww>=WL_) continue;
            s += wc[(dr+1)*3 + (dc+1)] * sp[hh*WL_ + ww];
        }
    }
    out[((long)b*QC_ + c)*PL_ + t] = s;
}

// ---------------- normalize q / k rows in place ----------------
__global__ void rownorm(float* dw) {
    int rid = blockIdx.x;
    int sel = rid / (B_*HEADS*C48);
    int rem = rid % (B_*HEADS*C48);
    int b   = rem / (HEADS*C48);
    int ch  = rem % (HEADS*C48);
    float* row = dw + ((long)b*QC_ + sel*D96 + ch)*PL_;
    __shared__ float sh[256];
    float s = 0.f;
    for (int i=threadIdx.x;i<PL_;i+=256){ float v=row[i]; s += v*v; }
    sh[threadIdx.x]=s; __syncthreads();
    for (int st=128;st>0;st>>=1){ if (threadIdx.x<st) sh[threadIdx.x]+=sh[threadIdx.x+st]; __syncthreads(); }
    float scale = 1.f / fmaxf(sqrtf(sh[0]), 1e-12f);
    for (int i=threadIdx.x;i<PL_;i+=256) row[i]*=scale;
}

// ---------------- attn = qn @ kn^T * temp ----------------
__global__ void attn_kernel(const float* __restrict__ dw, const float* __restrict__ temp,
                            float* __restrict__ attn) {
    int idx = blockIdx.x*blockDim.x + threadIdx.x;
    if (idx >= B_*HEADS*C48*C48) return;
    int j = idx % C48;
    int i = (idx / C48) % C48;
    int h = (idx / (C48*C48)) % HEADS;
    int b =  idx / (C48*C48*HEADS);
    const float* q = dw + ((long)b*QC_ +      h*C48 + i)*PL_;
    const float* k = dw + ((long)b*QC_ + D96 + h*C48 + j)*PL_;
    float s = 0.f;
    for (int n=0;n<PL_;n++) s += q[n]*k[n];
    attn[idx] = s * temp[h];
}

// ---------------- top-k threshold softmaxes, combined ----------------
__global__ void topk_combine(const float* __restrict__ attn, const float* __restrict__ aw,
                             float* __restrict__ acomb) {
    int r = threadIdx.x;
    if (r >= B_*HEADS*C48) return;
    const float* row = attn + (long)r*C48;
    float a[C48], srt[C48];
    for (int j=0;j<C48;j++){ a[j]=row[j]; srt[j]=a[j]; }
    for (int x=1;x<C48;x++){
        float key = srt[x]; int j = x-1;
        while (j>=0 && srt[j]<key){ srt[j+1]=srt[j]; j--; }
        srt[j+1]=key;
    }
    const int kks[4] = {24,32,36,38};
    float m = srt[0];
    float th[4], sm[4];
    #pragma unroll
    for (int l=0;l<4;l++){
        th[l] = srt[kks[l]-1];
        float s = 0.f;
        for (int j=0;j<C48;j++) if (a[j] >= th[l]) s += expf(a[j]-m);
        sm[l] = s;
    }
    float w0=aw[0], w1=aw[1], w2=aw[2], w3=aw[3];
    for (int j=0;j<C48;j++){
        float e = expf(a[j]-m);
        float o = 0.f;
        if (a[j] >= th[0]) o += w0*e/sm[0];
        if (a[j] >= th[1]) o += w1*e/sm[1];
        if (a[j] >= th[2]) o += w2*e/sm[2];
        if (a[j] >= th[3]) o += w3*e/sm[3];
        acomb[(long)r*C48 + j] = o;
    }
}

// ---------------- out = gelu(Acomb @ v) ----------------
__global__ void av_gelu(const float* __restrict__ acomb, const float* __restrict__ dw,
                        float* __restrict__ outlow) {
    int idx = blockIdx.x*blockDim.x + threadIdx.x;
    if (idx >= B_*HEADS*C48*PL_) return;
    int n = idx % PL_;
    int c = (idx / PL_) % C48;
    int h = (idx / (PL_*C48)) % HEADS;
    int b =  idx / (PL_*C48*HEADS);
    const float* arow = acomb + (((long)(b*HEADS+h))*C48 + c)*C48;
    const float* v = dw + ((long)b*QC_ + 2*D96 + h*C48)*PL_;
    float s = 0.f;
    #pragma unroll 4
    for (int d=0;d<C48;d++) s += arow[d] * v[(long)d*PL_ + n];
    float g = 0.5f * s * (1.f + erff(s * 0.70710678118654752440f));
    outlow[((long)b*D96 + h*C48 + c)*PL_ + n] = g;
}

// ---------------- BN partials / finals ----------------
__global__ void bn_partial1(const float* __restrict__ src, float (*part)[16][2]) {
    int c = blockIdx.x;
    int chunk = blockIdx.y;
    const float* base = src + ((long)(chunk>>3)*C48 + c)*HW_ + (long)(chunk & 7)*(HW_/8);
    float s = 0.f, s2 = 0.f;
    for (int i = threadIdx.x; i < HW_/8; i += 256){
        float v = base[i]; s += v; s2 += v*v;
    }
    __shared__ float sh[512];
    sh[threadIdx.x] = s; sh[256+threadIdx.x] = s2; __syncthreads();
    for (int st=128; st>0; st>>=1){
        if (threadIdx.x < st){ sh[threadIdx.x]+=sh[threadIdx.x+st]; sh[256+threadIdx.x]+=sh[256+threadIdx.x+st]; }
        __syncthreads();
    }
    if (threadIdx.x == 0){ part[c][chunk][0] = sh[0]; part[c][chunk][1] = sh[256]; }
}

__global__ void bn_final1(const float (*part)[16][2], float* dst) {
    int c = threadIdx.x;
    if (c >= C48) return;
    float s = 0.f, s2 = 0.f;
    #pragma unroll
    for (int k=0;k<16;k++){ s += part[c][k][0]; s2 += part[c][k][1]; }
    float N = (float)(B_*HW_);
    float m = s/N;
    float var = s2/N - m*m;
    dst[c]       = m;
    dst[C48+c]   = rsqrtf(fmaxf(var,0.f) + 1e-5f);
}

__global__ void bn_partial2(const float* __restrict__ xk, const float* __restrict__ yq,
                            float (*part)[16][2]) {
    int c = blockIdx.x;           // 0..95 : <48 -> xk, >=48 -> yq
    int chunk = blockIdx.y;
    const float* src = (c < C48) ? xk : yq;
    int cc = c % C48;
    const float* base = src + ((long)(chunk>>3)*C48 + cc)*HW_ + (long)(chunk & 7)*(HW_/8);
    float s = 0.f, s2 = 0.f;
    for (int i = threadIdx.x; i < HW_/8; i += 256){
        float v = base[i]; s += v; s2 += v*v;
    }
    __shared__ float sh[512];
    sh[threadIdx.x] = s; sh[256+threadIdx.x] = s2; __syncthreads();
    for (int st=128; st>0; st>>=1){
        if (threadIdx.x < st){ sh[threadIdx.x]+=sh[threadIdx.x+st]; sh[256+threadIdx.x]+=sh[256+threadIdx.x+st]; }
        __syncthreads();
    }
    if (threadIdx.x == 0){ part[c][chunk][0] = sh[0]; part[c][chunk][1] = sh[256]; }
}

__global__ void bn_final2(const float (*part)[16][2], float* bnx, float* bny) {
    int c = threadIdx.x;
    if (c >= 96) return;
    float s = 0.f, s2 = 0.f;
    #pragma unroll
    for (int k=0;k<16;k++){ s += part[c][k][0]; s2 += part[c][k][1]; }
    float N = (float)(B_*HW_);
    float m = s/N;
    float var = s2/N - m*m;
    float* dst = (c < C48) ? bnx : bny;
    int cc = c % C48;
    dst[cc]     = m;
    dst[C48+cc] = rsqrtf(fmaxf(var,0.f) + 1e-5f);
}

__global__ void bn_low(const float* __restrict__ src, float* __restrict__ dst) {
    int c = blockIdx.x;
    float s = 0.f, s2 = 0.f;
    for (int i = threadIdx.x; i < B_*PL_; i += 256){
        int b = i / PL_, j = i % PL_;
        float v = src[((long)b*C48 + c)*PL_ + j];
        s += v; s2 += v*v;
    }
    __shared__ float sh[512];
    sh[threadIdx.x]=s; sh[256+threadIdx.x]=s2; __syncthreads();
    for (int st=128; st>0; st>>=1){
        if (threadIdx.x < st){ sh[threadIdx.x]+=sh[threadIdx.x+st]; sh[256+threadIdx.x]+=sh[256+threadIdx.x+st]; }
        __syncthreads();
    }
    if (threadIdx.x == 0){
        float N = (float)(B_*PL_);
        float m = sh[0]/N;
        float var = sh[256]/N - m*m;
        dst[c]     = m;
        dst[C48+c] = rsqrtf(fmaxf(var,0.f) + 1e-5f);
    }
}

// ---------------- EAF blend (both full-res) ----------------
__global__ void eaf_blend(const float* __restrict__ x, long xB,
                          const float* __restrict__ y, long yB,
                          const float* __restrict__ xk, const float* __restrict__ yq,
                          const float* __restrict__ bnx, const float* __restrict__ bny,
                          float* __restrict__ out, long outB) {
    int p = blockIdx.x*blockDim.x + threadIdx.x;
    int b = blockIdx.y;
    if (p >= HW_) return;
    long base = (long)b*C48*HW_ + p;
    float s = 0.f;
    for (int c=0;c<C48;c++){
        float a  = (xk[base + (long)c*HW_] - bnx[c]) * bnx[C48+c];
        float bb = (yq[base + (long)c*HW_] - bny[c]) * bny[C48+c];
        s += a*bb;
    }
    float sim = 1.f/(1.f + expf(-s));
    for (int c=0;c<D96;c++){
        float xv = x[(long)b*xB + (long)c*HW_ + p];
        float yv = y[(long)b*yB + (long)c*HW_ + p];
        out[(long)b*outB + (long)c*HW_ + p] = sim*xv + (1.f-sim)*yv;
    }
}

// ---------------- EAF blend HF variant: x/xk low res; emits split copy -------------
__global__ void eaf_blend_hf(const float* __restrict__ xlow,
                             const float* __restrict__ y, long yB,
                             const float* __restrict__ xklow,
                             const float* __restrict__ yq,
                             const float* __restrict__ bnx, const float* __restrict__ bny,
                             float* __restrict__ out, long outB,
                             __nv_bfloat16* __restrict__ Xh, __nv_bfloat16* __restrict__ Xl) {
    int p = blockIdx.x*blockDim.x + threadIdx.x;
    int b = blockIdx.y;
    if (p >= HW_) return;
    int h = p / W_, w = p % W_;
    int lp = (h>>3)*WL_ + (w>>3);
    long basey = (long)b*C48*HW_ + p;
    float s = 0.f;
    for (int c=0;c<C48;c++){
        float a  = (xklow[((long)b*C48 + c)*PL_ + lp] - bnx[c]) * bnx[C48+c];
        float bb = (yq[basey + (long)c*HW_] - bny[c]) * bny[C48+c];
        s += a*bb;
    }
    float sim = 1.f/(1.f + expf(-s));
    for (int c=0;c<D96;c++){
        float xv = xlow[((long)b*D96 + c)*PL_ + lp];
        float yv = y[(long)b*yB + (long)c*HW_ + p];
        float o  = sim*xv + (1.f-sim)*yv;
        out[(long)b*outB + (long)c*HW_ + p] = o;
        __nv_bfloat16 hh,ll; split_bf16(o, hh, ll);
        long xi = ((long)b*D96 + c)*HW_ + p;
        Xh[xi] = hh; Xl[xi] = ll;
    }
}

// ---------------- convert fp32 activations -> split bf16 ----------------
__global__ void convert_x(const float* __restrict__ in, long inB,
                          __nv_bfloat16* __restrict__ Xh, __nv_bfloat16* __restrict__ Xl) {
    long idx = (long)blockIdx.x*blockDim.x + threadIdx.x;
    if (idx >= (long)B_*D96*HW_) return;
    long per = (long)D96*HW_;
    int z = (int)(idx / per);
    long r = idx - (long)z*per;
    float v = in[(long)z*inB + r];
    __nv_bfloat16 h,l; split_bf16(v, h, l);
    Xh[idx] = h; Xl[idx] = l;
}

// ---------------- orchestration (single stream) ----------------
extern "C" void kernel_launch(void* const* d_in, const int* in_sizes, int n_in,
                              void* d_out, int out_size) {
    const float* x_in   = (const float*)d_in[0];
    const float* hf     = (const float*)d_in[1];
    const float* lf     = (const float*)d_in[2];
    const float* mkw_w  = (const float*)d_in[3];
    const float* mkw_b  = (const float*)d_in[4];
    const float* mkw_wc = (const float*)d_in[5];
    const float* mkw_bc = (const float*)d_in[6];
    const float* mkw_wh = (const float*)d_in[7];
    const float* mkw_bh = (const float*)d_in[8];
    const float* mkw_wv = (const float*)d_in[9];
    const float* mkw_bv = (const float*)d_in[10];
    const float* mkw_wa = (const float*)d_in[11];
    const float* mkw_ba = (const float*)d_in[12];
    const float* mkw_s  = (const float*)d_in[13];
    const float* dt_temp= (const float*)d_in[14];
    const float* dt_wqkv= (const float*)d_in[15];
    const float* dt_bqkv= (const float*)d_in[16];
    const float* dt_wdw = (const float*)d_in[17];
    const float* dt_bdw = (const float*)d_in[18];
    const float* dt_wprj= (const float*)d_in[19];
    const float* dt_bprj= (const float*)d_in[20];
    const float* dt_aw  = (const float*)d_in[21];
    const float* eh_wx  = (const float*)d_in[22];
    const float* eh_wy  = (const float*)d_in[23];
    const float* el_wx  = (const float*)d_in[24];
    const float* el_wy  = (const float*)d_in[25];
    const float* cab_w  = (const float*)d_in[26];
    const float* cab_b  = (const float*)d_in[27];
    float* out = (float*)d_out;

    float *feats, *qkvfull, *weff, *beff, *dw, *attn, *acomb,
          *low1, *low2, *xk, *yq, *bnx, *bny, *M;
    __nv_bfloat16 *Uh, *Ul, *UCh, *UCl, *Vh, *Vl, *Xh, *Xl, *HFh, *HFl, *LFh, *LFl, *WBh, *WBl;
    float (*bnpart2)[16][2];
    cudaGetSymbolAddress((void**)&feats,   g_feats);
    cudaGetSymbolAddress((void**)&qkvfull, g_qkvfull);
    cudaGetSymbolAddress((void**)&weff,    g_weff);
    cudaGetSymbolAddress((void**)&beff,    g_beff);
    cudaGetSymbolAddress((void**)&dw,      g_dw);
    cudaGetSymbolAddress((void**)&attn,    g_attn);
    cudaGetSymbolAddress((void**)&acomb,   g_acomb);
    cudaGetSymbolAddress((void**)&low1,    g_low1);
    cudaGetSymbolAddress((void**)&low2,    g_low2);
    cudaGetSymbolAddress((void**)&xk,      g_xk);
    cudaGetSymbolAddress((void**)&yq,      g_yq);
    cudaGetSymbolAddress((void**)&bnx,     g_bnx);
    cudaGetSymbolAddress((void**)&bny,     g_bny);
    cudaGetSymbolAddress((void**)&bnpart2, g_bnpart2);
    cudaGetSymbolAddress((void**)&Uh,      g_Uh);
    cudaGetSymbolAddress((void**)&Ul,      g_Ul);
    cudaGetSymbolAddress((void**)&UCh,     g_UCh);
    cudaGetSymbolAddress((void**)&UCl,     g_UCl);
    cudaGetSymbolAddress((void**)&Vh,      g_Vh);
    cudaGetSymbolAddress((void**)&Vl,      g_Vl);
    cudaGetSymbolAddress((void**)&M,       g_M);
    cudaGetSymbolAddress((void**)&Xh,      g_Xh);
    cudaGetSymbolAddress((void**)&Xl,      g_Xl);
    cudaGetSymbolAddress((void**)&HFh,     g_HFh);
    cudaGetSymbolAddress((void**)&HFl,     g_HFl);
    cudaGetSymbolAddress((void**)&LFh,     g_LFh);
    cudaGetSymbolAddress((void**)&LFl,     g_LFl);
    cudaGetSymbolAddress((void**)&WBh,     g_WBh);
    cudaGetSymbolAddress((void**)&WBl,     g_WBl);

    const long fB   = (long)QC_*HW_;
    const long dB   = (long)D96*HW_;
    const long cB   = (long)C48*HW_;
    const long lowB = (long)D96*PL_;
    const long lowC = (long)C48*PL_;
    const long nConv = (long)B_*D96*HW_;
    const unsigned convGrid = (unsigned)((nConv+255)/256);

    // prologue: hoisted conversions / transforms (no copy_slot0 — slot0 unused)
    convert_x<<<convGrid, 256>>>(hf, dB, HFh, HFl);
    convert_x<<<convGrid, 256>>>(lf, dB, LFh, LFl);
    convert_all_w<<<(WB_TOT+255)/256, 256>>>(dt_wqkv, eh_wy, el_wx, el_wy, WBh, WBl);
    wino_wtrans<<<(D96*QC_+255)/256, 256>>>(cab_w, D96, QC_, UCh, UCl);

    for (int i=0;i<2;i++){
        const float* s4 = mkw_s + i*4;
        build_weight<<<(D96*D96+255)/256, 256>>>(mkw_w + (size_t)i*D96*D96*9,
                                                 mkw_wc + (size_t)i*D96*D96*9,
                                                 mkw_wh + (size_t)i*D96*D96*3,
                                                 mkw_wv + (size_t)i*D96*D96*3,
                                                 mkw_wa + (size_t)i*D96*D96*9,
                                                 s4, weff,
                                                 mkw_b + i*D96, mkw_bc + i*D96,
                                                 mkw_bh + i*D96, mkw_bv + i*D96,
                                                 mkw_ba + i*D96, beff);

        // ---- MKW conv3x3: Winograd F(4,3) + TC GEMM; itrans writes shared V bank ----
        // layer0 input = x_in (stride dB); layer1 input = feats slot1 (stride fB)
        const float* xsrc = (i == 0) ? x_in : (feats + (size_t)D96*HW_);
        const long   srcB = (i == 0) ? dB : fB;
        wino_wtrans<<<(D96*D96+255)/256, 256>>>(weff, D96, D96, Uh, Ul);
        wino_itrans<<<dim3(NT_/256, D96), 256>>>(xsrc, srcB, QC_, i*D96, Vh, Vl);
        wino_gemm<<<dim3(NT_/128, 1, 36), 256>>>(Uh, Ul,
            Vh + (long)(i*D96)*NT_, Vl + (long)(i*D96)*NT_, M, D96, QC_, NT_);
        wino_otrans<<<(D96*NT_+255)/256, 256>>>(M, beff, nullptr, 0L, Xh, Xl);

        // ---- qkv 1x1 (full res) via TC GEMM (X split from otrans) ----
        gemm1x1_tc<<<dim3(HW_/128, 3, B_), 256>>>(WBh + WB_QKV + (size_t)i*QC_*D96,
            WBl + WB_QKV + (size_t)i*QC_*D96, Xh, Xl,
            dt_bqkv + i*QC_, qkvfull, D96, QC_, HW_, fB);

        pool_dw<<<B_*QC_, 576>>>(qkvfull, dt_wdw + (size_t)i*QC_*9, dt_bdw + i*QC_, dw);
        rownorm<<<2*B_*HEADS*C48, 256>>>(dw);
        attn_kernel<<<(B_*HEADS*C48*C48+255)/256, 256>>>(dw, dt_temp + i*HEADS, attn);
        topk_combine<<<1, 192>>>(attn, dt_aw + i*4, acomb);
        av_gelu<<<(B_*HEADS*C48*PL_+255)/256, 256>>>(acomb, dw, low1);

        // proj 1x1 at low res (fp32)
        conv1x1_kernel<<<dim3((PL_+511)/512, D96/32, B_), 256>>>(
            low1, lowB, D96, dt_wprj + (size_t)i*D96*D96, dt_bprj + i*D96,
            low2, lowB, D96, PL_, 0L);

        float* slot_out = feats + (size_t)(i+1)*D96*HW_;

        // ---- EAF_HF (xk at low res fp32; yq full res TC); blend emits split ----
        conv1x1_kernel<<<dim3((PL_+511)/512, (C48+31)/32, B_), 256>>>(
            low2, lowB, D96, eh_wx + (size_t)i*C48*D96, nullptr, xk, lowC, C48, PL_, 0L);
        gemm1x1_tc<<<dim3(HW_/128, 1, B_), 256>>>(WBh + WB_EHY + (size_t)i*C48*D96,
            WBl + WB_EHY + (size_t)i*C48*D96, HFh, HFl,
            nullptr, yq, D96, C48, HW_, cB);
        bn_low<<<C48, 256>>>(xk, bnx);
        bn_partial1<<<dim3(C48,16), 256>>>(yq, bnpart2);
        bn_final1<<<1, C48>>>(bnpart2, bny);
        eaf_blend_hf<<<dim3(HW_/256, B_), 256>>>(low2, hf, dB, xk, yq, bnx, bny,
                                                 slot_out, fB, Xh, Xl);

        // ---- EAF_LF (both full res, TC; X split from blend_hf) ----
        gemm1x1_tc<<<dim3(HW_/128, 1, B_), 256>>>(WBh + WB_ELX + (size_t)i*C48*D96,
            WBl + WB_ELX + (size_t)i*C48*D96, Xh, Xl,
            nullptr, xk, D96, C48, HW_, cB);
        gemm1x1_tc<<<dim3(HW_/128, 1, B_), 256>>>(WBh + WB_ELY + (size_t)i*C48*D96,
            WBl + WB_ELY + (size_t)i*C48*D96, LFh, LFl,
            nullptr, yq, D96, C48, HW_, cB);
        bn_partial2<<<dim3(96,16), 256>>>(xk, yq, bnpart2);
        bn_final2<<<1, 96>>>(bnpart2, bnx, bny);
        eaf_blend<<<dim3(HW_/256, B_), 256>>>(slot_out, fB, lf, dB, xk, yq, bnx, bny,
                                              slot_out, fB);
    }

    // ---- CAB conv3x3 (IC=288): V ch 0-191 already in bank; transform only slot2 ----
    wino_itrans<<<dim3(NT_/256, D96), 256>>>(feats + (size_t)2*D96*HW_, fB, QC_, 2*D96, Vh, Vl);
    wino_gemm<<<dim3(NT_/128, 1, 36), 256>>>(UCh, UCl, Vh, Vl, M, QC_, QC_, NT_);
    wino_otrans<<<(D96*NT_+255)/256, 256>>>(M, cab_b, out, dB, nullptr, nullptr);
}